// round 6
// baseline (speedup 1.0000x reference)
#include <cuda_runtime.h>
#include <math.h>
#include <float.h>

#define NN 8192
#define NE 65536
#define VPLANE ((size_t)NN * 576)

#define INV_SQRT128 0.08838834764831843f
#define INV_SQRT512 0.04419417382415922f
#define INV_SQRT3   0.5773502691896258f
#define INV_SQRT160 0.07905694150420949f
#define INV_SQRT32  0.17677669529663687f

#define SC_S   (0.125f * INV_SQRT128 * INV_SQRT160)
#define SC_V   (INV_SQRT32 * 0.125f * INV_SQRT160)
#define SC_P_S (INV_SQRT128)
#define SC_P_V (0.125f)
#define SC_C_S (0.125f * INV_SQRT512)
#define SC_C_V (0.125f * 0.0625f)

typedef unsigned long long u64;

__device__ __forceinline__ void fma2(u64& d, u64 a, u64 b) {
    asm("fma.rn.f32x2 %0, %1, %2, %0;" : "+l"(d) : "l"(a), "l"(b));
}
__device__ __forceinline__ u64 dupf(float x) {
    u64 r; asm("mov.b64 %0, {%1, %1};" : "=l"(r) : "r"(__float_as_uint(x))); return r;
}

// ---------------- scratch ------------------------------------------------------
__device__ float g_xT[160 * NN];
__device__ float g_S[NN * 1088];          // tk_s 512 | tself_s 512 | PA_s 32 | PB_s 32
__device__ float g_V[3 * NN * 576];       // plane c: tk_v 256 | tself_v 256 | PAv 32 | PBv 32
__device__ float g_QKself[NN * 8];
__device__ float g_feat[NE * 160];        // c0 64 | vec c*32+d (96)
__device__ float g_logit[NE * 8];         // fallback (deg > 64)
__device__ float g_agg[NN * 1280];
__device__ float g_ms[NN * 64];
__device__ float g_mv[3 * NN * 32];
__device__ int   g_cnt[NN];
__device__ int   g_offs[NN + 1];
__device__ int   g_cursor[NN];
__device__ int   g_elist[NE];
__device__ float g_Wts[64 * 1088];
__device__ float g_Wtv[32 * 576];
__device__ float g_Wcs[512 * 64];
__device__ float g_Wcv[256 * 32];

// ---------------- weight packing / grams / hist -----------------------------------
__global__ void __launch_bounds__(256) k_pack2(
        const float* __restrict__ Wq_s, const float* __restrict__ Wq_v,
        const float* __restrict__ Wk_s, const float* __restrict__ Wk_v,
        const float* __restrict__ Wp_s, const float* __restrict__ Wp_v,
        const float* __restrict__ Wv_s, const float* __restrict__ Wv_v,
        const float* __restrict__ Wm_s, const float* __restrict__ Wm_v,
        const int* __restrict__ ei) {
    __shared__ float sm[8192];
    int b = blockIdx.x, tid = threadIdx.x;
    if (b >= 49) {                          // histogram over dst
        int e = (b - 49) * 256 + tid;
        if (e < NE) atomicAdd(&g_cnt[ei[NE + e]], 1);
        return;
    }
    if (b < 16) {
        int h = b & 7, self = b >> 3;
        float* Q = sm; float* Kx = sm + 4096;
        for (int i = tid; i < 4096; i += 256) {
            int a = i >> 6, j = i & 63;
            Q[i]  = Wq_s[a * 512 + h * 64 + j];
            int kr = self ? a : (64 + a);
            Kx[i] = Wk_s[kr * 512 + h * 64 + j];
        }
        __syncthreads();
        for (int i = tid; i < 4096; i += 256) {
            int a = i & 63, bb = i >> 6;
            float s = 0.f;
            for (int j = 0; j < 64; j++) s += Q[a * 64 + j] * Kx[bb * 64 + j];
            g_Wts[bb * 1088 + self * 512 + h * 64 + a] = s * SC_S;
        }
    } else if (b < 32) {
        int h = (b - 16) & 7, self = (b - 16) >> 3;
        float* Q = sm; float* Kx = sm + 1024;
        for (int i = tid; i < 1024; i += 256) {
            int a = i >> 5, j = i & 31;
            Q[i]  = Wq_v[a * 256 + h * 32 + j];
            int kr = self ? a : (32 + a);
            Kx[i] = Wk_v[kr * 256 + h * 32 + j];
        }
        __syncthreads();
        for (int i = tid; i < 1024; i += 256) {
            int a = i & 31, bb = i >> 5;
            float s = 0.f;
            for (int j = 0; j < 32; j++) s += Q[a * 32 + j] * Kx[bb * 32 + j];
            g_Wtv[bb * 576 + self * 256 + h * 32 + a] = s * SC_V;
        }
    } else if (b < 40) {
        int h = b - 32;
        float* V = sm; float* M = sm + 4096;
        for (int i = tid; i < 4096; i += 256) {
            int k = i >> 6, j = i & 63;
            V[i] = Wv_s[k * 512 + h * 64 + j];
            M[i] = Wm_s[(h * 64 + k) * 64 + j];
        }
        __syncthreads();
        for (int i = tid; i < 4096; i += 256) {
            int d = i & 63, k = i >> 6;
            float s = 0.f;
            for (int j = 0; j < 64; j++) s += V[k * 64 + j] * M[j * 64 + d];
            g_Wcs[(h * 64 + k) * 64 + d] = s * SC_C_S;
        }
    } else if (b < 48) {
        int h = b - 40;
        float* V = sm; float* M = sm + 1024;
        for (int i = tid; i < 1024; i += 256) {
            int k = i >> 5, j = i & 31;
            V[i] = Wv_v[k * 256 + h * 32 + j] + Wv_v[(32 + k) * 256 + h * 32 + j];
            M[i] = Wm_v[(h * 32 + k) * 32 + j];
        }
        __syncthreads();
        for (int i = tid; i < 1024; i += 256) {
            int d = i & 31, k = i >> 5;
            float s = 0.f;
            for (int j = 0; j < 32; j++) s += V[k * 32 + j] * M[j * 32 + d];
            g_Wcv[(h * 32 + k) * 32 + d] = s * SC_C_V;
        }
    } else {   // b == 48: Wp copies
        for (int i = tid; i < 4096; i += 256) {
            int bb = i >> 6, c = i & 63;
            float w = (c < 32) ? Wp_s[bb * 32 + c] : Wp_s[(64 + bb) * 32 + (c - 32)];
            g_Wts[bb * 1088 + 1024 + c] = w * SC_P_S;
        }
        for (int i = tid; i < 2048; i += 256) {
            int bb = i >> 6, c = i & 63;
            float w = (c < 32) ? Wp_v[bb * 32 + c] : Wp_v[(32 + bb) * 32 + (c - 32)];
            g_Wtv[bb * 576 + 512 + c] = w * SC_P_V;
        }
    }
}

// ---------------- transpose x -> xT [160][8192] ----------------------------------
__global__ void k_xT(const float* __restrict__ x, float* __restrict__ xT) {
    __shared__ float t[32][33];
    int tx = threadIdx.x, ty = threadIdx.y;
    int n0 = blockIdx.x * 32, t0 = blockIdx.y * 32;
#pragma unroll
    for (int i = 0; i < 32; i += 8)
        t[ty + i][tx] = x[(size_t)(n0 + ty + i) * 160 + t0 + tx];
    __syncthreads();
#pragma unroll
    for (int i = 0; i < 32; i += 8)
        xT[(size_t)(t0 + ty + i) * 8192 + n0 + tx] = t[tx][ty + i];
}

// ---------------- full-K resident GEMM with f32x2 (round-4 config: BM=128) -------
template<int K>
__global__ void __launch_bounds__(256) k_gemmT(
        const float* __restrict__ AT, int baseRow, int rowStride,
        const float* __restrict__ W, int N,
        float* __restrict__ C, int cRow, size_t planeStride) {
    __shared__ __align__(16) float As[K * 128];
    __shared__ __align__(16) float Ws[K * 64];
    int tid = threadIdx.x;
    int n0 = blockIdx.x * 64, m0 = blockIdx.y * 128;
    int z = blockIdx.z;
#pragma unroll
    for (int r = 0; r < (K * 128) / 1024; r++) {
        int idx = tid + r * 256;
        int k = idx >> 5, mp = idx & 31;
        *(float4*)&As[k * 128 + mp * 4] =
            *(const float4*)&AT[(size_t)(baseRow + z + k * rowStride) * 8192 + m0 + mp * 4];
    }
#pragma unroll
    for (int r = 0; r < (K * 64) / 1024; r++) {
        int idx = tid + r * 256;
        int k = idx >> 4, j = idx & 15;
        *(float4*)&Ws[k * 64 + j * 4] = *(const float4*)&W[(size_t)k * N + n0 + j * 4];
    }
    __syncthreads();
    int ty = tid >> 4, tx = tid & 15;
    u64 acc[4][4] = {};
#pragma unroll 8
    for (int k = 0; k < K; k++) {
        ulonglong2 a01 = *(const ulonglong2*)&As[k * 128 + ty * 8];
        ulonglong2 a23 = *(const ulonglong2*)&As[k * 128 + ty * 8 + 4];
        float4 b4 = *(const float4*)&Ws[k * 64 + tx * 4];
        u64 bb0 = dupf(b4.x), bb1 = dupf(b4.y), bb2 = dupf(b4.z), bb3 = dupf(b4.w);
        u64 ap[4] = {a01.x, a01.y, a23.x, a23.y};
#pragma unroll
        for (int q = 0; q < 4; q++) {
            fma2(acc[q][0], ap[q], bb0);
            fma2(acc[q][1], ap[q], bb1);
            fma2(acc[q][2], ap[q], bb2);
            fma2(acc[q][3], ap[q], bb3);
        }
    }
    float* Cb = C + (size_t)z * planeStride;
#pragma unroll
    for (int q = 0; q < 4; q++) {
        float2 c0 = *(float2*)&acc[q][0];
        float2 c1 = *(float2*)&acc[q][1];
        float2 c2 = *(float2*)&acc[q][2];
        float2 c3 = *(float2*)&acc[q][3];
        int r0 = m0 + ty * 8 + 2 * q;
        *(float4*)&Cb[(size_t)r0 * cRow + n0 + tx * 4]       = make_float4(c0.x, c1.x, c2.x, c3.x);
        *(float4*)&Cb[(size_t)(r0 + 1) * cRow + n0 + tx * 4] = make_float4(c0.y, c1.y, c2.y, c3.y);
    }
}

// ---------------- final projection: agg @ Wc -> g_ms / g_mv -------------------------
__global__ void __launch_bounds__(256) k_proj() {
    __shared__ __align__(16) char smraw[16384 + 16384];
    float* As = (float*)smraw;                 // [32][128]
    u64* Ws2 = (u64*)(smraw + 16384);          // [32][<=64]
    int tid = threadIdx.x;
    int b = blockIdx.x;
    if (b < 64) {       // scalar: [8192,512] @ [512,64]
        int m0 = b * 128;
        int ty = tid >> 4, tx = tid & 15;
        u64 acc[4][4] = {};
        for (int k0 = 0; k0 < 512; k0 += 32) {
            __syncthreads();
#pragma unroll
            for (int r = 0; r < 4; r++) {
                int idx = tid + r * 256;
                int m = idx & 127, kq = idx >> 7;
                float4 v = *(const float4*)&g_agg[(size_t)(m0 + m) * 1280 + k0 + kq * 4];
                As[(kq * 4 + 0) * 128 + m] = v.x;
                As[(kq * 4 + 1) * 128 + m] = v.y;
                As[(kq * 4 + 2) * 128 + m] = v.z;
                As[(kq * 4 + 3) * 128 + m] = v.w;
            }
#pragma unroll
            for (int r = 0; r < 2; r++) {
                int idx = tid + r * 256;
                int k = idx >> 4, j = idx & 15;
                float4 w = *(const float4*)&g_Wcs[(size_t)(k0 + k) * 64 + j * 4];
                Ws2[k * 64 + j * 4 + 0] = dupf(w.x);
                Ws2[k * 64 + j * 4 + 1] = dupf(w.y);
                Ws2[k * 64 + j * 4 + 2] = dupf(w.z);
                Ws2[k * 64 + j * 4 + 3] = dupf(w.w);
            }
            __syncthreads();
#pragma unroll 4
            for (int k = 0; k < 32; k++) {
                ulonglong2 a01 = *(const ulonglong2*)&As[k * 128 + ty * 8];
                ulonglong2 a23 = *(const ulonglong2*)&As[k * 128 + ty * 8 + 4];
                ulonglong2 b01 = *(const ulonglong2*)&Ws2[k * 64 + tx * 4];
                ulonglong2 b23 = *(const ulonglong2*)&Ws2[k * 64 + tx * 4 + 2];
                u64 ap[4] = {a01.x, a01.y, a23.x, a23.y};
                u64 bb[4] = {b01.x, b01.y, b23.x, b23.y};
#pragma unroll
                for (int q = 0; q < 4; q++)
#pragma unroll
                    for (int j = 0; j < 4; j++)
                        fma2(acc[q][j], ap[q], bb[j]);
            }
        }
#pragma unroll
        for (int q = 0; q < 4; q++) {
            float2 c0 = *(float2*)&acc[q][0];
            float2 c1 = *(float2*)&acc[q][1];
            float2 c2 = *(float2*)&acc[q][2];
            float2 c3 = *(float2*)&acc[q][3];
            int r0 = m0 + ty * 8 + 2 * q;
            *(float4*)&g_ms[(size_t)r0 * 64 + tx * 4]       = make_float4(c0.x, c1.x, c2.x, c3.x);
            *(float4*)&g_ms[(size_t)(r0 + 1) * 64 + tx * 4] = make_float4(c0.y, c1.y, c2.y, c3.y);
        }
    } else {            // vector: 3 x [8192,256] @ [256,32]
        int idx2 = b - 64;
        int c = idx2 / 64, mt = idx2 % 64;
        int m0 = mt * 128;
        int ty = tid >> 3, tx = tid & 7;
        u64 acc[2][4] = {};
        for (int k0 = 0; k0 < 256; k0 += 32) {
            __syncthreads();
#pragma unroll
            for (int r = 0; r < 4; r++) {
                int idx = tid + r * 256;
                int m = idx & 127, kq = idx >> 7;
                float4 v = *(const float4*)&g_agg[(size_t)(m0 + m) * 1280 + 512 + c * 256 + k0 + kq * 4];
                As[(kq * 4 + 0) * 128 + m] = v.x;
                As[(kq * 4 + 1) * 128 + m] = v.y;
                As[(kq * 4 + 2) * 128 + m] = v.z;
                As[(kq * 4 + 3) * 128 + m] = v.w;
            }
            {
                int k = tid >> 3, j = tid & 7;
                float4 w = *(const float4*)&g_Wcv[(size_t)(k0 + k) * 32 + j * 4];
                Ws2[k * 32 + j * 4 + 0] = dupf(w.x);
                Ws2[k * 32 + j * 4 + 1] = dupf(w.y);
                Ws2[k * 32 + j * 4 + 2] = dupf(w.z);
                Ws2[k * 32 + j * 4 + 3] = dupf(w.w);
            }
            __syncthreads();
#pragma unroll 4
            for (int k = 0; k < 32; k++) {
                ulonglong2 a = *(const ulonglong2*)&As[k * 128 + ty * 4];
                ulonglong2 b01 = *(const ulonglong2*)&Ws2[k * 32 + tx * 4];
                ulonglong2 b23 = *(const ulonglong2*)&Ws2[k * 32 + tx * 4 + 2];
                u64 bb[4] = {b01.x, b01.y, b23.x, b23.y};
#pragma unroll
                for (int j = 0; j < 4; j++) {
                    fma2(acc[0][j], a.x, bb[j]);
                    fma2(acc[1][j], a.y, bb[j]);
                }
            }
        }
        float* Cb = g_mv + (size_t)c * NN * 32;
#pragma unroll
        for (int q = 0; q < 2; q++) {
            float2 c0 = *(float2*)&acc[q][0];
            float2 c1 = *(float2*)&acc[q][1];
            float2 c2 = *(float2*)&acc[q][2];
            float2 c3 = *(float2*)&acc[q][3];
            int r0 = m0 + ty * 4 + 2 * q;
            *(float4*)&Cb[(size_t)r0 * 32 + tx * 4]       = make_float4(c0.x, c1.x, c2.x, c3.x);
            *(float4*)&Cb[(size_t)(r0 + 1) * 32 + tx * 4] = make_float4(c0.y, c1.y, c2.y, c3.y);
        }
    }
}

// ---------------- self term: warp per node ----------------------------------------
__global__ void __launch_bounds__(256) k_qkself2(const float* __restrict__ x) {
    __shared__ float s_x[8][160];
    int tid = threadIdx.x;
    int wid = tid >> 5, lane = tid & 31;
    int n = blockIdx.x * 8 + wid;
    const float4* xs = (const float4*)(x + (size_t)n * 160);
    ((float4*)s_x[wid])[lane] = xs[lane];
    if (lane < 8) ((float4*)s_x[wid])[32 + lane] = xs[32 + lane];
    __syncwarp();
    const float* xr = s_x[wid];
    const float* Sb = g_S + (size_t)n * 1088 + 512;
#pragma unroll
    for (int h = 0; h < 8; h++) {
        float a = Sb[h * 64 + lane] * xr[lane]
                + Sb[h * 64 + 32 + lane] * xr[32 + lane];
#pragma unroll
        for (int c = 0; c < 3; c++)
            a += g_V[c * VPLANE + (size_t)n * 576 + 256 + h * 32 + lane]
                 * xr[64 + lane * 3 + c];
#pragma unroll
        for (int o = 16; o; o >>= 1) a += __shfl_xor_sync(0xffffffffu, a, o);
        if (lane == 0) g_QKself[n * 8 + h] = a;
    }
}

// ---------------- CSR --------------------------------------------------------------
__global__ void __launch_bounds__(1024) k_scan() {
    __shared__ int wsum[32];
    int tid = threadIdx.x;
    int base = tid * 8;
    int loc[8]; int tot = 0;
#pragma unroll
    for (int i = 0; i < 8; i++) { loc[i] = tot; tot += g_cnt[base + i]; }
    int lane = tid & 31, w = tid >> 5;
    int incl = tot;
#pragma unroll
    for (int o = 1; o < 32; o <<= 1) {
        int y = __shfl_up_sync(0xffffffffu, incl, o);
        if (lane >= o) incl += y;
    }
    if (lane == 31) wsum[w] = incl;
    int excl = incl - tot;
    __syncthreads();
    if (w == 0) {
        int t = wsum[lane];
        int i2 = t;
#pragma unroll
        for (int o = 1; o < 32; o <<= 1) {
            int y = __shfl_up_sync(0xffffffffu, i2, o);
            if (lane >= o) i2 += y;
        }
        wsum[lane] = i2 - t;
    }
    __syncthreads();
    int off = wsum[w] + excl;
#pragma unroll
    for (int i = 0; i < 8; i++) {
        int o2 = off + loc[i];
        g_offs[base + i] = o2;
        g_cursor[base + i] = o2;
    }
    if (tid == 1023) g_offs[NN] = NE;
}

__global__ void k_scatter(const int* __restrict__ ei) {
    int e = blockIdx.x * 256 + threadIdx.x;
    if (e < NE) {
        int pos = atomicAdd(&g_cursor[ei[NE + e]], 1);
        g_elist[pos] = e;
    }
}

// ---------------- per-edge sph -> feat ----------------------------------------------
__global__ void __launch_bounds__(256) k_edgeprep(const float* __restrict__ rbf,
                                                  const float* __restrict__ rsh,
                                                  const int* __restrict__ ei,
                                                  const float* __restrict__ Wrbf) {
    __shared__ float sW[1024];
    int tid = threadIdx.x;
    for (int l = tid; l < 1024; l += 256) sW[l] = Wrbf[l];
    __syncthreads();
    int e = blockIdx.x * 8 + (tid >> 5);
    int lane = tid & 31;
    int src = ei[e], dst = ei[NE + e];
    int d = lane;
    float ps = g_S[(size_t)src * 1088 + 1024 + d] + g_S[(size_t)dst * 1088 + 1056 + d];
    float pv[3];
#pragma unroll
    for (int c = 0; c < 3; c++)
        pv[c] = g_V[c * VPLANE + (size_t)src * 576 + 512 + d]
              + g_V[c * VPLANE + (size_t)dst * 576 + 544 + d];
    float rval = (lane < 16) ? rbf[e * 16 + lane] : 0.f;
    float scal_s = 0.f, scal_v = 0.f;
#pragma unroll
    for (int b = 0; b < 16; b++) {
        float rb = __shfl_sync(0xffffffffu, rval, b);
        scal_s += rb * sW[b * 64 + d];
        scal_v += rb * sW[b * 64 + 32 + d];
    }
    float rs = rsh[e * 128 + d];
    float sph_s = rs * scal_s * ps;
    float sv[3];
#pragma unroll
    for (int c = 0; c < 3; c++)
        sv[c] = rsh[e * 128 + 32 + d * 3 + c] * scal_v * pv[c];
    float* f = g_feat + (size_t)e * 160;
    f[d]      = sph_s * sph_s;
    f[32 + d] = (sv[0] * sv[0] + sv[1] * sv[1] + sv[2] * sv[2]) * INV_SQRT3;
#pragma unroll
    for (int c = 0; c < 3; c++)
        f[64 + c * 32 + d] = sph_s * sv[c];
}

// ---------------- fused attention + aggregation: warp per node ----------------------
__global__ void __launch_bounds__(256) k_attn_agg2(const float* __restrict__ x,
                                                   const int* __restrict__ ei) {
    __shared__ float s_x[8][160];
    __shared__ float s_lg[8][512];
    const unsigned F = 0xffffffffu;
    int tid = threadIdx.x;
    int wid = tid >> 5, lane = tid & 31;
    int n = blockIdx.x * 8 + wid;
    int h = lane >> 2, p = lane & 3;

    int s0 = g_offs[n], deg = g_offs[n + 1] - s0;
    float* lg = (deg <= 64) ? &s_lg[wid][0] : (g_logit + (size_t)s0 * 8);

    int e0 = 0, e1 = 0, src0 = 0, src1 = 0;
    if (lane < deg) e0 = g_elist[s0 + lane];
    if (lane + 32 < deg) e1 = g_elist[s0 + 32 + lane];
    if (lane < deg) src0 = ei[e0];
    if (lane + 32 < deg) src1 = ei[e1];

    float mymax = -FLT_MAX;
    {
        float tk[40];
#pragma unroll
        for (int tt = 0; tt < 40; tt++) {
            int t = p * 40 + tt;
            if (t < 64)
                tk[tt] = g_S[(size_t)n * 1088 + h * 64 + t];
            else {
                int j = t - 64;
                tk[tt] = g_V[(j % 3) * VPLANE + (size_t)n * 576 + h * 32 + (j / 3)];
            }
        }
        for (int i = 0; i < deg; i++) {
            int e, src;
            if (i < 64) {
                e   = __shfl_sync(F, (i < 32) ? e0 : e1, i & 31);
                src = __shfl_sync(F, (i < 32) ? src0 : src1, i & 31);
            } else {
                int ee = 0, ss = 0;
                if (lane == 0) { ee = g_elist[s0 + i]; ss = ei[ee]; }
                e = __shfl_sync(F, ee, 0);
                src = __shfl_sync(F, ss, 0);
            }
            const float4* xs = (const float4*)(x + (size_t)src * 160);
            ((float4*)s_x[wid])[lane] = xs[lane];
            if (lane < 8) ((float4*)s_x[wid])[32 + lane] = xs[32 + lane];
            __syncwarp();
            const float* xr = s_x[wid] + p * 40;
            float a = 0.f;
#pragma unroll
            for (int tt = 0; tt < 40; tt++) a += tk[tt] * xr[tt];
            a += __shfl_xor_sync(F, a, 1);
            a += __shfl_xor_sync(F, a, 2);
            if (p == 0) {
                a += g_QKself[src * 8 + h];
                lg[i * 8 + h] = a;
                mymax = fmaxf(mymax, a);
            }
            __syncwarp();
        }
    }

    if (p == 0 && deg > 0) {
        float den = 0.f;
        for (int i = 0; i < deg; i++) {
            float ex = expf(lg[i * 8 + h] - mymax);
            lg[i * 8 + h] = ex;
            den += ex;
        }
        float inv = 1.f / den;
        for (int i = 0; i < deg; i++) lg[i * 8 + h] *= inv;
    }
    __syncwarp();

    float acc[40];
#pragma unroll
    for (int tt = 0; tt < 40; tt++) acc[tt] = 0.f;

    for (int i = 0; i < deg; i++) {
        int e;
        if (i < 64) e = __shfl_sync(F, (i < 32) ? e0 : e1, i & 31);
        else {
            int ee = 0;
            if (lane == 0) ee = g_elist[s0 + i];
            e = __shfl_sync(F, ee, 0);
        }
        const float* fr = g_feat + (size_t)e * 160;
        float f0  = fr[lane];
        float f1  = fr[32 + lane];
        float fv0 = fr[64 + lane];
        float fv1 = fr[96 + lane];
        float fv2 = fr[128 + lane];
        float at[8];
#pragma unroll
        for (int hh = 0; hh < 8; hh++) at[hh] = lg[i * 8 + hh];
#pragma unroll
        for (int tt = 0; tt < 40; tt++) {
            int hT = (tt < 16) ? (tt >> 1) : ((tt - 16) & 7);
            float fval;
            if (tt < 16) fval = (tt & 1) ? f1 : f0;
            else {
                int c = (tt - 16) >> 3;
                fval = (c == 0) ? fv0 : ((c == 1) ? fv1 : fv2);
            }
            acc[tt] += at[hT] * fval;
        }
    }
#pragma unroll
    for (int tt = 0; tt < 40; tt++)
        g_agg[(size_t)n * 1280 + tt * 32 + lane] = acc[tt];
}

// ---------------- NormGate + output --------------------------------------------------
__global__ void __launch_bounds__(256) k_normgate(const float* __restrict__ ln_g,
                                                  const float* __restrict__ ln_b,
                                                  const float* __restrict__ W1,
                                                  const float* __restrict__ b1,
                                                  const float* __restrict__ W2,
                                                  const float* __restrict__ b2,
                                                  float* __restrict__ out) {
    __shared__ float sW1[96 * 96];
    __shared__ float sX[8][96];
    __shared__ float sH[8][96];
    int tid = threadIdx.x;
    int w = tid >> 5, lane = tid & 31;
    for (int i = tid; i < 9216; i += 256) sW1[i] = W1[i];
    __syncthreads();

    for (int sub = 0; sub < 4; sub++) {
        int n = blockIdx.x * 32 + w * 4 + sub;
        float ms0 = g_ms[(size_t)n * 64 + lane];
        float ms1 = g_ms[(size_t)n * 64 + 32 + lane];
        float v0 = g_mv[(size_t)0 * NN * 32 + n * 32 + lane];
        float v1 = g_mv[(size_t)1 * NN * 32 + n * 32 + lane];
        float v2 = g_mv[(size_t)2 * NN * 32 + n * 32 + lane];
        float n00 = fabsf(ms0), n01 = fabsf(ms1);
        float n02 = sqrtf(v0 * v0 + v1 * v1 + v2 * v2);
        float s = n00 + n01 + n02;
        float s2 = n00 * n00 + n01 * n01 + n02 * n02;
#pragma unroll
        for (int o = 16; o; o >>= 1) {
            s  += __shfl_xor_sync(0xffffffffu, s, o);
            s2 += __shfl_xor_sync(0xffffffffu, s2, o);
        }
        float mu = s * (1.f / 96.f);
        float var = s2 * (1.f / 96.f) - mu * mu;
        float rstd = rsqrtf(var + 1e-5f);
        sX[w][lane]      = (n00 - mu) * rstd * ln_g[lane]      + ln_b[lane];
        sX[w][lane + 32] = (n01 - mu) * rstd * ln_g[lane + 32] + ln_b[lane + 32];
        sX[w][lane + 64] = (n02 - mu) * rstd * ln_g[lane + 64] + ln_b[lane + 64];
        __syncwarp();
#pragma unroll
        for (int t = 0; t < 3; t++) {
            int jp = lane + t * 32;
            float hs = b1[jp];
            for (int j = 0; j < 96; j++) hs += sX[w][j] * sW1[j * 96 + jp];
            sH[w][jp] = hs / (1.f + expf(-hs));
        }
        __syncwarp();
        float n0arr[3] = {n00, n01, n02};
        float f[3];
#pragma unroll
        for (int t = 0; t < 3; t++) {
            int jp = lane + t * 32;
            float gs = b2[jp];
            for (int j = 0; j < 96; j++) gs += sH[w][j] * W2[j * 96 + jp];
            float gg = gs / (1.f + expf(-gs));
            f[t] = gg / (n0arr[t] + 1e-6f);
        }
        out[n * 160 + lane]      = ms0 * f[0];
        out[n * 160 + 32 + lane] = ms1 * f[1];
        out[n * 160 + 64 + lane * 3 + 0] = v0 * f[2];
        out[n * 160 + 64 + lane * 3 + 1] = v1 * f[2];
        out[n * 160 + 64 + lane * 3 + 2] = v2 * f[2];
        __syncwarp();
    }
}

// ---------------- launch ----------------------------------------------------------------
extern "C" void kernel_launch(void* const* d_in, const int* in_sizes, int n_in,
                              void* d_out, int out_size) {
    const float* pseduo_x = (const float*)d_in[0];
    const float* rbf   = (const float*)d_in[1];
    const float* rsh   = (const float*)d_in[2];
    const int*   ei    = (const int*)d_in[3];
    const float* Wq_s  = (const float*)d_in[4];
    const float* Wq_v  = (const float*)d_in[5];
    const float* Wk_s  = (const float*)d_in[6];
    const float* Wk_v  = (const float*)d_in[7];
    const float* Wp_s  = (const float*)d_in[8];
    const float* Wp_v  = (const float*)d_in[9];
    const float* Wrbf  = (const float*)d_in[10];
    const float* Wv_s  = (const float*)d_in[11];
    const float* Wv_v  = (const float*)d_in[12];
    const float* Wm_s  = (const float*)d_in[13];
    const float* Wm_v  = (const float*)d_in[14];
    const float* ln_g  = (const float*)d_in[15];
    const float* ln_b  = (const float*)d_in[16];
    const float* W1    = (const float*)d_in[17];
    const float* b1    = (const float*)d_in[18];
    const float* W2    = (const float*)d_in[19];
    const float* b2    = (const float*)d_in[20];
    float* out = (float*)d_out;

    void* p;
    cudaGetSymbolAddress(&p, g_xT);  float* XT  = (float*)p;
    cudaGetSymbolAddress(&p, g_S);   float* S   = (float*)p;
    cudaGetSymbolAddress(&p, g_V);   float* V   = (float*)p;
    cudaGetSymbolAddress(&p, g_cnt); int*   CNT = (int*)p;
    cudaGetSymbolAddress(&p, g_Wts); float* Wts = (float*)p;
    cudaGetSymbolAddress(&p, g_Wtv); float* Wtv = (float*)p;

    cudaMemsetAsync(CNT, 0, NN * sizeof(int));
    k_pack2<<<305, 256>>>(Wq_s, Wq_v, Wk_s, Wk_v, Wp_s, Wp_v, Wv_s, Wv_v, Wm_s, Wm_v, ei);
    k_xT<<<dim3(256, 5), dim3(32, 8)>>>(pseduo_x, XT);

    k_gemmT<64><<<dim3(17, 64, 1), 256>>>(XT, 0, 1, Wts, 1088, S, 1088, 0);
    k_gemmT<32><<<dim3(9, 64, 3), 256>>>(XT, 64, 3, Wtv, 576, V, 576, VPLANE);
    k_qkself2<<<1024, 256>>>(pseduo_x);

    k_scan<<<1, 1024>>>();
    k_scatter<<<256, 256>>>(ei);

    k_edgeprep<<<8192, 256>>>(rbf, rsh, ei, Wrbf);
    k_attn_agg2<<<1024, 256>>>(pseduo_x, ei);

    k_proj<<<256, 256>>>();
    k_normgate<<<256, 256>>>(ln_g, ln_b, W1, b1, W2, b2, out);
}

// round 7
// speedup vs baseline: 1.5230x; 1.5230x over previous
#include <cuda_runtime.h>
#include <math.h>
#include <float.h>

#define NN 8192
#define NE 65536
#define VPLANE ((size_t)NN * 576)

#define INV_SQRT128 0.08838834764831843f
#define INV_SQRT512 0.04419417382415922f
#define INV_SQRT3   0.5773502691896258f
#define INV_SQRT160 0.07905694150420949f
#define INV_SQRT32  0.17677669529663687f

#define SC_S   (0.125f * INV_SQRT128 * INV_SQRT160)
#define SC_V   (INV_SQRT32 * 0.125f * INV_SQRT160)
#define SC_P_S (INV_SQRT128)
#define SC_P_V (0.125f)
#define SC_C_S (0.125f * INV_SQRT512)
#define SC_C_V (0.125f * 0.0625f)

typedef unsigned long long u64;

__device__ __forceinline__ void fma2(u64& d, u64 a, u64 b) {
    asm("fma.rn.f32x2 %0, %1, %2, %0;" : "+l"(d) : "l"(a), "l"(b));
}
__device__ __forceinline__ u64 dupf(float x) {
    u64 r; asm("mov.b64 %0, {%1, %1};" : "=l"(r) : "r"(__float_as_uint(x))); return r;
}

// ---------------- scratch ------------------------------------------------------
__device__ float g_xT[160 * NN];
__device__ float g_S[NN * 1088];          // tk_s 512 | tself_s 512 | PA_s 32 | PB_s 32
__device__ float g_V[3 * NN * 576];       // plane c: tk_v 256 | tself_v 256 | PAv 32 | PBv 32
__device__ float g_QKself[NN * 8];
__device__ float g_feat[NE * 160];        // c0 64 | vec c*32+d (96)
__device__ float g_logit[NE * 8];         // fallback (deg > 64)
__device__ float g_agg[NN * 1280];
__device__ float g_ms[NN * 64];
__device__ float g_mv[3 * NN * 32];
__device__ int   g_cnt[NN];
__device__ int   g_offs[NN + 1];
__device__ int   g_cursor[NN];
__device__ int   g_elist[NE];
__device__ float g_Wts[64 * 1088];
__device__ float g_Wtv[32 * 576];
__device__ float g_Wcs[512 * 64];
__device__ float g_Wcv[256 * 32];

// ---------------- weight packing / grams (smem staged) --------------------------
__global__ void __launch_bounds__(256) k_pack2(
        const float* __restrict__ Wq_s, const float* __restrict__ Wq_v,
        const float* __restrict__ Wk_s, const float* __restrict__ Wk_v,
        const float* __restrict__ Wp_s, const float* __restrict__ Wp_v,
        const float* __restrict__ Wv_s, const float* __restrict__ Wv_v,
        const float* __restrict__ Wm_s, const float* __restrict__ Wm_v) {
    __shared__ float sm[8192];
    int b = blockIdx.x, tid = threadIdx.x;
    if (b < 16) {
        int h = b & 7, self = b >> 3;
        float* Q = sm; float* Kx = sm + 4096;
        for (int i = tid; i < 4096; i += 256) {
            int a = i >> 6, j = i & 63;
            Q[i]  = Wq_s[a * 512 + h * 64 + j];
            int kr = self ? a : (64 + a);
            Kx[i] = Wk_s[kr * 512 + h * 64 + j];
        }
        __syncthreads();
        for (int i = tid; i < 4096; i += 256) {
            int a = i & 63, bb = i >> 6;
            float s = 0.f;
            for (int j = 0; j < 64; j++) s += Q[a * 64 + j] * Kx[bb * 64 + j];
            g_Wts[bb * 1088 + self * 512 + h * 64 + a] = s * SC_S;
        }
    } else if (b < 32) {
        int h = (b - 16) & 7, self = (b - 16) >> 3;
        float* Q = sm; float* Kx = sm + 1024;
        for (int i = tid; i < 1024; i += 256) {
            int a = i >> 5, j = i & 31;
            Q[i]  = Wq_v[a * 256 + h * 32 + j];
            int kr = self ? a : (32 + a);
            Kx[i] = Wk_v[kr * 256 + h * 32 + j];
        }
        __syncthreads();
        for (int i = tid; i < 1024; i += 256) {
            int a = i & 31, bb = i >> 5;
            float s = 0.f;
            for (int j = 0; j < 32; j++) s += Q[a * 32 + j] * Kx[bb * 32 + j];
            g_Wtv[bb * 576 + self * 256 + h * 32 + a] = s * SC_V;
        }
    } else if (b < 40) {
        int h = b - 32;
        float* V = sm; float* M = sm + 4096;
        for (int i = tid; i < 4096; i += 256) {
            int k = i >> 6, j = i & 63;
            V[i] = Wv_s[k * 512 + h * 64 + j];
            M[i] = Wm_s[(h * 64 + k) * 64 + j];
        }
        __syncthreads();
        for (int i = tid; i < 4096; i += 256) {
            int d = i & 63, k = i >> 6;
            float s = 0.f;
            for (int j = 0; j < 64; j++) s += V[k * 64 + j] * M[j * 64 + d];
            g_Wcs[(h * 64 + k) * 64 + d] = s * SC_C_S;
        }
    } else if (b < 48) {
        int h = b - 40;
        float* V = sm; float* M = sm + 1024;
        for (int i = tid; i < 1024; i += 256) {
            int k = i >> 5, j = i & 31;
            V[i] = Wv_v[k * 256 + h * 32 + j] + Wv_v[(32 + k) * 256 + h * 32 + j];
            M[i] = Wm_v[(h * 32 + k) * 32 + j];
        }
        __syncthreads();
        for (int i = tid; i < 1024; i += 256) {
            int d = i & 31, k = i >> 5;
            float s = 0.f;
            for (int j = 0; j < 32; j++) s += V[k * 32 + j] * M[j * 32 + d];
            g_Wcv[(h * 32 + k) * 32 + d] = s * SC_C_V;
        }
    } else if (b == 48) {
        for (int i = tid; i < 4096; i += 256) {
            int bb = i >> 6, c = i & 63;
            float w = (c < 32) ? Wp_s[bb * 32 + c] : Wp_s[(64 + bb) * 32 + (c - 32)];
            g_Wts[bb * 1088 + 1024 + c] = w * SC_P_S;
        }
        for (int i = tid; i < 2048; i += 256) {
            int bb = i >> 6, c = i & 63;
            float w = (c < 32) ? Wp_v[bb * 32 + c] : Wp_v[(32 + bb) * 32 + (c - 32)];
            g_Wtv[bb * 576 + 512 + c] = w * SC_P_V;
        }
    } else {   // b == 49: zero histogram
        for (int i = tid; i < NN; i += 256) g_cnt[i] = 0;
    }
}

// ---------------- transpose x -> xT [160][8192] ----------------------------------
__global__ void k_xT(const float* __restrict__ x, float* __restrict__ xT) {
    __shared__ float t[32][33];
    int tx = threadIdx.x, ty = threadIdx.y;
    int n0 = blockIdx.x * 32, t0 = blockIdx.y * 32;
#pragma unroll
    for (int i = 0; i < 32; i += 8)
        t[ty + i][tx] = x[(size_t)(n0 + ty + i) * 160 + t0 + tx];
    __syncthreads();
#pragma unroll
    for (int i = 0; i < 32; i += 8)
        xT[(size_t)(t0 + ty + i) * 8192 + n0 + tx] = t[tx][ty + i];
}

// ---------------- full-K resident GEMM with f32x2 (BM=128, BN=64) -----------------
template<int K>
__global__ void __launch_bounds__(256) k_gemmT(
        const float* __restrict__ AT, int baseRow, int rowStride,
        const float* __restrict__ W, int N,
        float* __restrict__ C, int cRow, size_t planeStride) {
    __shared__ __align__(16) float As[K * 128];
    __shared__ __align__(16) float Ws[K * 64];
    int tid = threadIdx.x;
    int n0 = blockIdx.x * 64, m0 = blockIdx.y * 128;
    int z = blockIdx.z;
#pragma unroll
    for (int r = 0; r < (K * 128) / 1024; r++) {
        int idx = tid + r * 256;
        int k = idx >> 5, mp = idx & 31;
        *(float4*)&As[k * 128 + mp * 4] =
            *(const float4*)&AT[(size_t)(baseRow + z + k * rowStride) * 8192 + m0 + mp * 4];
    }
#pragma unroll
    for (int r = 0; r < (K * 64) / 1024; r++) {
        int idx = tid + r * 256;
        int k = idx >> 4, j = idx & 15;
        *(float4*)&Ws[k * 64 + j * 4] = *(const float4*)&W[(size_t)k * N + n0 + j * 4];
    }
    __syncthreads();
    int ty = tid >> 4, tx = tid & 15;
    u64 acc[4][4] = {};
#pragma unroll 8
    for (int k = 0; k < K; k++) {
        ulonglong2 a01 = *(const ulonglong2*)&As[k * 128 + ty * 8];
        ulonglong2 a23 = *(const ulonglong2*)&As[k * 128 + ty * 8 + 4];
        float4 b4 = *(const float4*)&Ws[k * 64 + tx * 4];
        u64 bb0 = dupf(b4.x), bb1 = dupf(b4.y), bb2 = dupf(b4.z), bb3 = dupf(b4.w);
        u64 ap[4] = {a01.x, a01.y, a23.x, a23.y};
#pragma unroll
        for (int q = 0; q < 4; q++) {
            fma2(acc[q][0], ap[q], bb0);
            fma2(acc[q][1], ap[q], bb1);
            fma2(acc[q][2], ap[q], bb2);
            fma2(acc[q][3], ap[q], bb3);
        }
    }
    float* Cb = C + (size_t)z * planeStride;
#pragma unroll
    for (int q = 0; q < 4; q++) {
        float2 c0 = *(float2*)&acc[q][0];
        float2 c1 = *(float2*)&acc[q][1];
        float2 c2 = *(float2*)&acc[q][2];
        float2 c3 = *(float2*)&acc[q][3];
        int r0 = m0 + ty * 8 + 2 * q;
        *(float4*)&Cb[(size_t)r0 * cRow + n0 + tx * 4]       = make_float4(c0.x, c1.x, c2.x, c3.x);
        *(float4*)&Cb[(size_t)(r0 + 1) * cRow + n0 + tx * 4] = make_float4(c0.y, c1.y, c2.y, c3.y);
    }
}

// ---------------- final projection: agg @ Wc -> g_ms / g_mv ------------------------
// Coalesced A loads (threads sweep k within a row), smem stride 132.
#define ASTRIDE 132
__global__ void __launch_bounds__(256) k_proj() {
    __shared__ __align__(16) float As[32 * ASTRIDE];
    __shared__ __align__(16) u64 Ws2[32 * 64];
    int tid = threadIdx.x;
    int b = blockIdx.x;
    if (b < 64) {       // scalar: [8192,512] @ [512,64]
        int m0 = b * 128;
        int ty = tid >> 4, tx = tid & 15;
        u64 acc[4][4] = {};
        for (int k0 = 0; k0 < 512; k0 += 32) {
            __syncthreads();
#pragma unroll
            for (int r = 0; r < 4; r++) {
                int idx = tid + r * 256;
                int m = idx >> 3, kq = idx & 7;
                float4 v = *(const float4*)&g_agg[(size_t)(m0 + m) * 1280 + k0 + kq * 4];
                As[(kq * 4 + 0) * ASTRIDE + m] = v.x;
                As[(kq * 4 + 1) * ASTRIDE + m] = v.y;
                As[(kq * 4 + 2) * ASTRIDE + m] = v.z;
                As[(kq * 4 + 3) * ASTRIDE + m] = v.w;
            }
#pragma unroll
            for (int r = 0; r < 2; r++) {
                int idx = tid + r * 256;
                int k = idx >> 4, j = idx & 15;
                float4 w = *(const float4*)&g_Wcs[(size_t)(k0 + k) * 64 + j * 4];
                Ws2[k * 64 + j * 4 + 0] = dupf(w.x);
                Ws2[k * 64 + j * 4 + 1] = dupf(w.y);
                Ws2[k * 64 + j * 4 + 2] = dupf(w.z);
                Ws2[k * 64 + j * 4 + 3] = dupf(w.w);
            }
            __syncthreads();
#pragma unroll 4
            for (int k = 0; k < 32; k++) {
                ulonglong2 a01 = *(const ulonglong2*)&As[k * ASTRIDE + ty * 8];
                ulonglong2 a23 = *(const ulonglong2*)&As[k * ASTRIDE + ty * 8 + 4];
                ulonglong2 b01 = *(const ulonglong2*)&Ws2[k * 64 + tx * 4];
                ulonglong2 b23 = *(const ulonglong2*)&Ws2[k * 64 + tx * 4 + 2];
                u64 ap[4] = {a01.x, a01.y, a23.x, a23.y};
                u64 bb[4] = {b01.x, b01.y, b23.x, b23.y};
#pragma unroll
                for (int q = 0; q < 4; q++)
#pragma unroll
                    for (int j = 0; j < 4; j++)
                        fma2(acc[q][j], ap[q], bb[j]);
            }
        }
#pragma unroll
        for (int q = 0; q < 4; q++) {
            float2 c0 = *(float2*)&acc[q][0];
            float2 c1 = *(float2*)&acc[q][1];
            float2 c2 = *(float2*)&acc[q][2];
            float2 c3 = *(float2*)&acc[q][3];
            int r0 = m0 + ty * 8 + 2 * q;
            *(float4*)&g_ms[(size_t)r0 * 64 + tx * 4]       = make_float4(c0.x, c1.x, c2.x, c3.x);
            *(float4*)&g_ms[(size_t)(r0 + 1) * 64 + tx * 4] = make_float4(c0.y, c1.y, c2.y, c3.y);
        }
    } else {            // vector: 3 x [8192,256] @ [256,32]
        int idx2 = b - 64;
        int c = idx2 / 64, mt = idx2 % 64;
        int m0 = mt * 128;
        int ty = tid >> 3, tx = tid & 7;
        u64 acc[2][4] = {};
        for (int k0 = 0; k0 < 256; k0 += 32) {
            __syncthreads();
#pragma unroll
            for (int r = 0; r < 4; r++) {
                int idx = tid + r * 256;
                int m = idx >> 3, kq = idx & 7;
                float4 v = *(const float4*)&g_agg[(size_t)(m0 + m) * 1280 + 512 + c * 256 + k0 + kq * 4];
                As[(kq * 4 + 0) * ASTRIDE + m] = v.x;
                As[(kq * 4 + 1) * ASTRIDE + m] = v.y;
                As[(kq * 4 + 2) * ASTRIDE + m] = v.z;
                As[(kq * 4 + 3) * ASTRIDE + m] = v.w;
            }
            {
                int k = tid >> 3, j = tid & 7;
                float4 w = *(const float4*)&g_Wcv[(size_t)(k0 + k) * 32 + j * 4];
                Ws2[k * 32 + j * 4 + 0] = dupf(w.x);
                Ws2[k * 32 + j * 4 + 1] = dupf(w.y);
                Ws2[k * 32 + j * 4 + 2] = dupf(w.z);
                Ws2[k * 32 + j * 4 + 3] = dupf(w.w);
            }
            __syncthreads();
#pragma unroll 4
            for (int k = 0; k < 32; k++) {
                ulonglong2 a = *(const ulonglong2*)&As[k * ASTRIDE + ty * 4];
                ulonglong2 b01 = *(const ulonglong2*)&Ws2[k * 32 + tx * 4];
                ulonglong2 b23 = *(const ulonglong2*)&Ws2[k * 32 + tx * 4 + 2];
                u64 bb[4] = {b01.x, b01.y, b23.x, b23.y};
#pragma unroll
                for (int j = 0; j < 4; j++) {
                    fma2(acc[0][j], a.x, bb[j]);
                    fma2(acc[1][j], a.y, bb[j]);
                }
            }
        }
        float* Cb = g_mv + (size_t)c * NN * 32;
#pragma unroll
        for (int q = 0; q < 2; q++) {
            float2 c0 = *(float2*)&acc[q][0];
            float2 c1 = *(float2*)&acc[q][1];
            float2 c2 = *(float2*)&acc[q][2];
            float2 c3 = *(float2*)&acc[q][3];
            int r0 = m0 + ty * 4 + 2 * q;
            *(float4*)&Cb[(size_t)r0 * 32 + tx * 4]       = make_float4(c0.x, c1.x, c2.x, c3.x);
            *(float4*)&Cb[(size_t)(r0 + 1) * 32 + tx * 4] = make_float4(c0.y, c1.y, c2.y, c3.y);
        }
    }
}

// ---------------- self term: warp per node ----------------------------------------
__global__ void __launch_bounds__(256) k_qkself2(const float* __restrict__ x) {
    __shared__ float s_x[8][160];
    int tid = threadIdx.x;
    int wid = tid >> 5, lane = tid & 31;
    int n = blockIdx.x * 8 + wid;
    const float4* xs = (const float4*)(x + (size_t)n * 160);
    ((float4*)s_x[wid])[lane] = xs[lane];
    if (lane < 8) ((float4*)s_x[wid])[32 + lane] = xs[32 + lane];
    __syncwarp();
    const float* xr = s_x[wid];
    const float* Sb = g_S + (size_t)n * 1088 + 512;
#pragma unroll
    for (int h = 0; h < 8; h++) {
        float a = Sb[h * 64 + lane] * xr[lane]
                + Sb[h * 64 + 32 + lane] * xr[32 + lane];
#pragma unroll
        for (int c = 0; c < 3; c++)
            a += g_V[c * VPLANE + (size_t)n * 576 + 256 + h * 32 + lane]
                 * xr[64 + lane * 3 + c];
#pragma unroll
        for (int o = 16; o; o >>= 1) a += __shfl_xor_sync(0xffffffffu, a, o);
        if (lane == 0) g_QKself[n * 8 + h] = a;
    }
}

// ---------------- CSR --------------------------------------------------------------
__global__ void k_hist(const int* __restrict__ ei) {
    int e = blockIdx.x * 256 + threadIdx.x;
    if (e < NE) atomicAdd(&g_cnt[ei[NE + e]], 1);
}

__global__ void __launch_bounds__(1024) k_scan() {
    __shared__ int wsum[32];
    int tid = threadIdx.x;
    int base = tid * 8;
    int loc[8]; int tot = 0;
#pragma unroll
    for (int i = 0; i < 8; i++) { loc[i] = tot; tot += g_cnt[base + i]; }
    int lane = tid & 31, w = tid >> 5;
    int incl = tot;
#pragma unroll
    for (int o = 1; o < 32; o <<= 1) {
        int y = __shfl_up_sync(0xffffffffu, incl, o);
        if (lane >= o) incl += y;
    }
    if (lane == 31) wsum[w] = incl;
    int excl = incl - tot;
    __syncthreads();
    if (w == 0) {
        int t = wsum[lane];
        int i2 = t;
#pragma unroll
        for (int o = 1; o < 32; o <<= 1) {
            int y = __shfl_up_sync(0xffffffffu, i2, o);
            if (lane >= o) i2 += y;
        }
        wsum[lane] = i2 - t;
    }
    __syncthreads();
    int off = wsum[w] + excl;
#pragma unroll
    for (int i = 0; i < 8; i++) {
        int o2 = off + loc[i];
        g_offs[base + i] = o2;
        g_cursor[base + i] = o2;
    }
    if (tid == 1023) g_offs[NN] = NE;
}

__global__ void k_scatter(const int* __restrict__ ei) {
    int e = blockIdx.x * 256 + threadIdx.x;
    if (e < NE) {
        int pos = atomicAdd(&g_cursor[ei[NE + e]], 1);
        g_elist[pos] = e;
    }
}

// ---------------- per-edge sph -> feat ----------------------------------------------
__global__ void __launch_bounds__(256) k_edgeprep(const float* __restrict__ rbf,
                                                  const float* __restrict__ rsh,
                                                  const int* __restrict__ ei,
                                                  const float* __restrict__ Wrbf) {
    __shared__ float sW[1024];
    int tid = threadIdx.x;
    for (int l = tid; l < 1024; l += 256) sW[l] = Wrbf[l];
    __syncthreads();
    int e = blockIdx.x * 8 + (tid >> 5);
    int lane = tid & 31;
    int src = ei[e], dst = ei[NE + e];
    int d = lane;
    float ps = g_S[(size_t)src * 1088 + 1024 + d] + g_S[(size_t)dst * 1088 + 1056 + d];
    float pv[3];
#pragma unroll
    for (int c = 0; c < 3; c++)
        pv[c] = g_V[c * VPLANE + (size_t)src * 576 + 512 + d]
              + g_V[c * VPLANE + (size_t)dst * 576 + 544 + d];
    float rval = (lane < 16) ? rbf[e * 16 + lane] : 0.f;
    float scal_s = 0.f, scal_v = 0.f;
#pragma unroll
    for (int b = 0; b < 16; b++) {
        float rb = __shfl_sync(0xffffffffu, rval, b);
        scal_s += rb * sW[b * 64 + d];
        scal_v += rb * sW[b * 64 + 32 + d];
    }
    float rs = rsh[e * 128 + d];
    float sph_s = rs * scal_s * ps;
    float sv[3];
#pragma unroll
    for (int c = 0; c < 3; c++)
        sv[c] = rsh[e * 128 + 32 + d * 3 + c] * scal_v * pv[c];
    float* f = g_feat + (size_t)e * 160;
    f[d]      = sph_s * sph_s;
    f[32 + d] = (sv[0] * sv[0] + sv[1] * sv[1] + sv[2] * sv[2]) * INV_SQRT3;
#pragma unroll
    for (int c = 0; c < 3; c++)
        f[64 + c * 32 + d] = sph_s * sv[c];
}

// ---------------- fused attention + aggregation: warp per node ----------------------
__global__ void __launch_bounds__(256) k_attn_agg2(const float* __restrict__ x,
                                                   const int* __restrict__ ei) {
    __shared__ float s_x[8][160];
    __shared__ float s_lg[8][512];
    const unsigned F = 0xffffffffu;
    int tid = threadIdx.x;
    int wid = tid >> 5, lane = tid & 31;
    int n = blockIdx.x * 8 + wid;
    int h = lane >> 2, p = lane & 3;

    int s0 = g_offs[n], deg = g_offs[n + 1] - s0;
    float* lg = (deg <= 64) ? &s_lg[wid][0] : (g_logit + (size_t)s0 * 8);

    int e0 = 0, e1 = 0, src0 = 0, src1 = 0;
    if (lane < deg) e0 = g_elist[s0 + lane];
    if (lane + 32 < deg) e1 = g_elist[s0 + 32 + lane];
    if (lane < deg) src0 = ei[e0];
    if (lane + 32 < deg) src1 = ei[e1];

    float mymax = -FLT_MAX;
    {
        float tk[40];
#pragma unroll
        for (int tt = 0; tt < 40; tt++) {
            int t = p * 40 + tt;
            if (t < 64)
                tk[tt] = g_S[(size_t)n * 1088 + h * 64 + t];
            else {
                int j = t - 64;
                tk[tt] = g_V[(j % 3) * VPLANE + (size_t)n * 576 + h * 32 + (j / 3)];
            }
        }
        for (int i = 0; i < deg; i++) {
            int e, src;
            if (i < 64) {
                e   = __shfl_sync(F, (i < 32) ? e0 : e1, i & 31);
                src = __shfl_sync(F, (i < 32) ? src0 : src1, i & 31);
            } else {
                int ee = 0, ss = 0;
                if (lane == 0) { ee = g_elist[s0 + i]; ss = ei[ee]; }
                e = __shfl_sync(F, ee, 0);
                src = __shfl_sync(F, ss, 0);
            }
            const float4* xs = (const float4*)(x + (size_t)src * 160);
            ((float4*)s_x[wid])[lane] = xs[lane];
            if (lane < 8) ((float4*)s_x[wid])[32 + lane] = xs[32 + lane];
            __syncwarp();
            const float* xr = s_x[wid] + p * 40;
            float a = 0.f;
#pragma unroll
            for (int tt = 0; tt < 40; tt++) a += tk[tt] * xr[tt];
            a += __shfl_xor_sync(F, a, 1);
            a += __shfl_xor_sync(F, a, 2);
            if (p == 0) {
                a += g_QKself[src * 8 + h];
                lg[i * 8 + h] = a;
                mymax = fmaxf(mymax, a);
            }
            __syncwarp();
        }
    }

    if (p == 0 && deg > 0) {
        float den = 0.f;
        for (int i = 0; i < deg; i++) {
            float ex = expf(lg[i * 8 + h] - mymax);
            lg[i * 8 + h] = ex;
            den += ex;
        }
        float inv = 1.f / den;
        for (int i = 0; i < deg; i++) lg[i * 8 + h] *= inv;
    }
    __syncwarp();

    float acc[40];
#pragma unroll
    for (int tt = 0; tt < 40; tt++) acc[tt] = 0.f;

    for (int i = 0; i < deg; i++) {
        int e;
        if (i < 64) e = __shfl_sync(F, (i < 32) ? e0 : e1, i & 31);
        else {
            int ee = 0;
            if (lane == 0) ee = g_elist[s0 + i];
            e = __shfl_sync(F, ee, 0);
        }
        const float* fr = g_feat + (size_t)e * 160;
        float f0  = fr[lane];
        float f1  = fr[32 + lane];
        float fv0 = fr[64 + lane];
        float fv1 = fr[96 + lane];
        float fv2 = fr[128 + lane];
        float at[8];
#pragma unroll
        for (int hh = 0; hh < 8; hh++) at[hh] = lg[i * 8 + hh];
#pragma unroll
        for (int tt = 0; tt < 40; tt++) {
            int hT = (tt < 16) ? (tt >> 1) : ((tt - 16) & 7);
            float fval;
            if (tt < 16) fval = (tt & 1) ? f1 : f0;
            else {
                int c = (tt - 16) >> 3;
                fval = (c == 0) ? fv0 : ((c == 1) ? fv1 : fv2);
            }
            acc[tt] += at[hT] * fval;
        }
    }
#pragma unroll
    for (int tt = 0; tt < 40; tt++)
        g_agg[(size_t)n * 1280 + tt * 32 + lane] = acc[tt];
}

// ---------------- NormGate + output --------------------------------------------------
__global__ void __launch_bounds__(256) k_normgate(const float* __restrict__ ln_g,
                                                  const float* __restrict__ ln_b,
                                                  const float* __restrict__ W1,
                                                  const float* __restrict__ b1,
                                                  const float* __restrict__ W2,
                                                  const float* __restrict__ b2,
                                                  float* __restrict__ out) {
    __shared__ float sW1[96 * 96];
    __shared__ float sX[8][96];
    __shared__ float sH[8][96];
    int tid = threadIdx.x;
    int w = tid >> 5, lane = tid & 31;
    for (int i = tid; i < 9216; i += 256) sW1[i] = W1[i];
    __syncthreads();

    for (int sub = 0; sub < 4; sub++) {
        int n = blockIdx.x * 32 + w * 4 + sub;
        float ms0 = g_ms[(size_t)n * 64 + lane];
        float ms1 = g_ms[(size_t)n * 64 + 32 + lane];
        float v0 = g_mv[(size_t)0 * NN * 32 + n * 32 + lane];
        float v1 = g_mv[(size_t)1 * NN * 32 + n * 32 + lane];
        float v2 = g_mv[(size_t)2 * NN * 32 + n * 32 + lane];
        float n00 = fabsf(ms0), n01 = fabsf(ms1);
        float n02 = sqrtf(v0 * v0 + v1 * v1 + v2 * v2);
        float s = n00 + n01 + n02;
        float s2 = n00 * n00 + n01 * n01 + n02 * n02;
#pragma unroll
        for (int o = 16; o; o >>= 1) {
            s  += __shfl_xor_sync(0xffffffffu, s, o);
            s2 += __shfl_xor_sync(0xffffffffu, s2, o);
        }
        float mu = s * (1.f / 96.f);
        float var = s2 * (1.f / 96.f) - mu * mu;
        float rstd = rsqrtf(var + 1e-5f);
        sX[w][lane]      = (n00 - mu) * rstd * ln_g[lane]      + ln_b[lane];
        sX[w][lane + 32] = (n01 - mu) * rstd * ln_g[lane + 32] + ln_b[lane + 32];
        sX[w][lane + 64] = (n02 - mu) * rstd * ln_g[lane + 64] + ln_b[lane + 64];
        __syncwarp();
#pragma unroll
        for (int t = 0; t < 3; t++) {
            int jp = lane + t * 32;
            float hs = b1[jp];
            for (int j = 0; j < 96; j++) hs += sX[w][j] * sW1[j * 96 + jp];
            sH[w][jp] = hs / (1.f + expf(-hs));
        }
        __syncwarp();
        float n0arr[3] = {n00, n01, n02};
        float f[3];
#pragma unroll
        for (int t = 0; t < 3; t++) {
            int jp = lane + t * 32;
            float gs = b2[jp];
            for (int j = 0; j < 96; j++) gs += sH[w][j] * W2[j * 96 + jp];
            float gg = gs / (1.f + expf(-gs));
            f[t] = gg / (n0arr[t] + 1e-6f);
        }
        out[n * 160 + lane]      = ms0 * f[0];
        out[n * 160 + 32 + lane] = ms1 * f[1];
        out[n * 160 + 64 + lane * 3 + 0] = v0 * f[2];
        out[n * 160 + 64 + lane * 3 + 1] = v1 * f[2];
        out[n * 160 + 64 + lane * 3 + 2] = v2 * f[2];
        __syncwarp();
    }
}

// ---------------- launch ----------------------------------------------------------------
extern "C" void kernel_launch(void* const* d_in, const int* in_sizes, int n_in,
                              void* d_out, int out_size) {
    const float* pseduo_x = (const float*)d_in[0];
    const float* rbf   = (const float*)d_in[1];
    const float* rsh   = (const float*)d_in[2];
    const int*   ei    = (const int*)d_in[3];
    const float* Wq_s  = (const float*)d_in[4];
    const float* Wq_v  = (const float*)d_in[5];
    const float* Wk_s  = (const float*)d_in[6];
    const float* Wk_v  = (const float*)d_in[7];
    const float* Wp_s  = (const float*)d_in[8];
    const float* Wp_v  = (const float*)d_in[9];
    const float* Wrbf  = (const float*)d_in[10];
    const float* Wv_s  = (const float*)d_in[11];
    const float* Wv_v  = (const float*)d_in[12];
    const float* Wm_s  = (const float*)d_in[13];
    const float* Wm_v  = (const float*)d_in[14];
    const float* ln_g  = (const float*)d_in[15];
    const float* ln_b  = (const float*)d_in[16];
    const float* W1    = (const float*)d_in[17];
    const float* b1    = (const float*)d_in[18];
    const float* W2    = (const float*)d_in[19];
    const float* b2    = (const float*)d_in[20];
    float* out = (float*)d_out;

    void* p;
    cudaGetSymbolAddress(&p, g_xT);  float* XT  = (float*)p;
    cudaGetSymbolAddress(&p, g_S);   float* S   = (float*)p;
    cudaGetSymbolAddress(&p, g_V);   float* V   = (float*)p;
    cudaGetSymbolAddress(&p, g_Wts); float* Wts = (float*)p;
    cudaGetSymbolAddress(&p, g_Wtv); float* Wtv = (float*)p;

    k_pack2<<<50, 256>>>(Wq_s, Wq_v, Wk_s, Wk_v, Wp_s, Wp_v, Wv_s, Wv_v, Wm_s, Wm_v);
    k_xT<<<dim3(256, 5), dim3(32, 8)>>>(pseduo_x, XT);

    k_gemmT<64><<<dim3(17, 64, 1), 256>>>(XT, 0, 1, Wts, 1088, S, 1088, 0);
    k_gemmT<32><<<dim3(9, 64, 3), 256>>>(XT, 64, 3, Wtv, 576, V, 576, VPLANE);
    k_qkself2<<<1024, 256>>>(pseduo_x);

    k_hist<<<256, 256>>>(ei);
    k_scan<<<1, 1024>>>();
    k_scatter<<<256, 256>>>(ei);

    k_edgeprep<<<8192, 256>>>(rbf, rsh, ei, Wrbf);
    k_attn_agg2<<<1024, 256>>>(pseduo_x, ei);

    k_proj<<<256, 256>>>();
    k_normgate<<<256, 256>>>(ln_g, ln_b, W1, b1, W2, b2, out);
}

// round 8
// speedup vs baseline: 1.6235x; 1.0660x over previous
#include <cuda_runtime.h>
#include <math.h>
#include <float.h>

#define NN 8192
#define NE 65536
#define VPLANE ((size_t)NN * 576)

#define INV_SQRT128 0.08838834764831843f
#define INV_SQRT512 0.04419417382415922f
#define INV_SQRT3   0.5773502691896258f
#define INV_SQRT160 0.07905694150420949f
#define INV_SQRT32  0.17677669529663687f

#define SC_S   (0.125f * INV_SQRT128 * INV_SQRT160)
#define SC_V   (INV_SQRT32 * 0.125f * INV_SQRT160)
#define SC_P_S (INV_SQRT128)
#define SC_P_V (0.125f)
#define SC_C_S (0.125f * INV_SQRT512)
#define SC_C_V (0.125f * 0.0625f)

typedef unsigned long long u64;

__device__ __forceinline__ void fma2(u64& d, u64 a, u64 b) {
    asm("fma.rn.f32x2 %0, %1, %2, %0;" : "+l"(d) : "l"(a), "l"(b));
}
__device__ __forceinline__ u64 dupf(float x) {
    u64 r; asm("mov.b64 %0, {%1, %1};" : "=l"(r) : "r"(__float_as_uint(x))); return r;
}
__device__ __forceinline__ u64 pk2(float lo, float hi) {
    u64 r; asm("mov.b64 %0, {%1, %2};" : "=l"(r) : "r"(__float_as_uint(lo)), "r"(__float_as_uint(hi)));
    return r;
}

// ---------------- scratch ------------------------------------------------------
__device__ float g_xT[160 * NN];
__device__ float g_S[NN * 1088];          // tk_s 512 | tself_s 512 | PA_s 32 | PB_s 32
__device__ float g_V[3 * NN * 576];       // plane c: tk_v 256 | tself_v 256 | PAv 32 | PBv 32
__device__ float g_QKself[NN * 8];
__device__ float g_feat[NE * 160];        // c0 64 | vec c*32+d (96)
__device__ float g_logit[NE * 8];         // fallback (deg > 64)
__device__ float g_agg[NN * 1280];
__device__ float g_m[NN * 160];
__device__ int   g_cnt[NN];
__device__ int   g_offs[NN + 1];
__device__ int   g_cursor[NN];
__device__ int   g_elist[NE];
__device__ float g_Wts[64 * 1088];
__device__ float g_Wtv[32 * 576];
__device__ float g_Wcs[512 * 64];
__device__ float g_Wcv[256 * 32];

// ---------------- weight packing / grams (smem staged) --------------------------
__global__ void __launch_bounds__(256) k_pack2(
        const float* __restrict__ Wq_s, const float* __restrict__ Wq_v,
        const float* __restrict__ Wk_s, const float* __restrict__ Wk_v,
        const float* __restrict__ Wp_s, const float* __restrict__ Wp_v,
        const float* __restrict__ Wv_s, const float* __restrict__ Wv_v,
        const float* __restrict__ Wm_s, const float* __restrict__ Wm_v) {
    __shared__ float sm[8192];
    int b = blockIdx.x, tid = threadIdx.x;
    if (b < 16) {
        int h = b & 7, self = b >> 3;
        float* Q = sm; float* Kx = sm + 4096;
        for (int i = tid; i < 4096; i += 256) {
            int a = i >> 6, j = i & 63;
            Q[i]  = Wq_s[a * 512 + h * 64 + j];
            int kr = self ? a : (64 + a);
            Kx[i] = Wk_s[kr * 512 + h * 64 + j];
        }
        __syncthreads();
        for (int i = tid; i < 4096; i += 256) {
            int a = i & 63, bb = i >> 6;
            float s = 0.f;
            for (int j = 0; j < 64; j++) s += Q[a * 64 + j] * Kx[bb * 64 + j];
            g_Wts[bb * 1088 + self * 512 + h * 64 + a] = s * SC_S;
        }
    } else if (b < 32) {
        int h = (b - 16) & 7, self = (b - 16) >> 3;
        float* Q = sm; float* Kx = sm + 1024;
        for (int i = tid; i < 1024; i += 256) {
            int a = i >> 5, j = i & 31;
            Q[i]  = Wq_v[a * 256 + h * 32 + j];
            int kr = self ? a : (32 + a);
            Kx[i] = Wk_v[kr * 256 + h * 32 + j];
        }
        __syncthreads();
        for (int i = tid; i < 1024; i += 256) {
            int a = i & 31, bb = i >> 5;
            float s = 0.f;
            for (int j = 0; j < 32; j++) s += Q[a * 32 + j] * Kx[bb * 32 + j];
            g_Wtv[bb * 576 + self * 256 + h * 32 + a] = s * SC_V;
        }
    } else if (b < 40) {
        int h = b - 32;
        float* V = sm; float* M = sm + 4096;
        for (int i = tid; i < 4096; i += 256) {
            int k = i >> 6, j = i & 63;
            V[i] = Wv_s[k * 512 + h * 64 + j];
            M[i] = Wm_s[(h * 64 + k) * 64 + j];
        }
        __syncthreads();
        for (int i = tid; i < 4096; i += 256) {
            int d = i & 63, k = i >> 6;
            float s = 0.f;
            for (int j = 0; j < 64; j++) s += V[k * 64 + j] * M[j * 64 + d];
            g_Wcs[(h * 64 + k) * 64 + d] = s * SC_C_S;
        }
    } else if (b < 48) {
        int h = b - 40;
        float* V = sm; float* M = sm + 1024;
        for (int i = tid; i < 1024; i += 256) {
            int k = i >> 5, j = i & 31;
            V[i] = Wv_v[k * 256 + h * 32 + j] + Wv_v[(32 + k) * 256 + h * 32 + j];
            M[i] = Wm_v[(h * 32 + k) * 32 + j];
        }
        __syncthreads();
        for (int i = tid; i < 1024; i += 256) {
            int d = i & 31, k = i >> 5;
            float s = 0.f;
            for (int j = 0; j < 32; j++) s += V[k * 32 + j] * M[j * 32 + d];
            g_Wcv[(h * 32 + k) * 32 + d] = s * SC_C_V;
        }
    } else if (b == 48) {
        for (int i = tid; i < 4096; i += 256) {
            int bb = i >> 6, c = i & 63;
            float w = (c < 32) ? Wp_s[bb * 32 + c] : Wp_s[(64 + bb) * 32 + (c - 32)];
            g_Wts[bb * 1088 + 1024 + c] = w * SC_P_S;
        }
        for (int i = tid; i < 2048; i += 256) {
            int bb = i >> 6, c = i & 63;
            float w = (c < 32) ? Wp_v[bb * 32 + c] : Wp_v[(32 + bb) * 32 + (c - 32)];
            g_Wtv[bb * 576 + 512 + c] = w * SC_P_V;
        }
    } else {   // b == 49: zero histogram
        for (int i = tid; i < NN; i += 256) g_cnt[i] = 0;
    }
}

// ---------------- transpose x -> xT [160][8192] ----------------------------------
__global__ void k_xT(const float* __restrict__ x, float* __restrict__ xT) {
    __shared__ float t[32][33];
    int tx = threadIdx.x, ty = threadIdx.y;
    int n0 = blockIdx.x * 32, t0 = blockIdx.y * 32;
#pragma unroll
    for (int i = 0; i < 32; i += 8)
        t[ty + i][tx] = x[(size_t)(n0 + ty + i) * 160 + t0 + tx];
    __syncthreads();
#pragma unroll
    for (int i = 0; i < 32; i += 8)
        xT[(size_t)(t0 + ty + i) * 8192 + n0 + tx] = t[tx][ty + i];
}

// ---------------- full-K resident GEMM with f32x2 (BM=128, BN=64) -----------------
template<int K>
__global__ void __launch_bounds__(256) k_gemmT(
        const float* __restrict__ AT, int baseRow, int rowStride,
        const float* __restrict__ W, int N,
        float* __restrict__ C, int cRow, size_t planeStride) {
    __shared__ __align__(16) float As[K * 128];
    __shared__ __align__(16) float Ws[K * 64];
    int tid = threadIdx.x;
    int n0 = blockIdx.x * 64, m0 = blockIdx.y * 128;
    int z = blockIdx.z;
#pragma unroll
    for (int r = 0; r < (K * 128) / 1024; r++) {
        int idx = tid + r * 256;
        int k = idx >> 5, mp = idx & 31;
        *(float4*)&As[k * 128 + mp * 4] =
            *(const float4*)&AT[(size_t)(baseRow + z + k * rowStride) * 8192 + m0 + mp * 4];
    }
#pragma unroll
    for (int r = 0; r < (K * 64) / 1024; r++) {
        int idx = tid + r * 256;
        int k = idx >> 4, j = idx & 15;
        *(float4*)&Ws[k * 64 + j * 4] = *(const float4*)&W[(size_t)k * N + n0 + j * 4];
    }
    __syncthreads();
    int ty = tid >> 4, tx = tid & 15;
    u64 acc[4][4] = {};
#pragma unroll 8
    for (int k = 0; k < K; k++) {
        ulonglong2 a01 = *(const ulonglong2*)&As[k * 128 + ty * 8];
        ulonglong2 a23 = *(const ulonglong2*)&As[k * 128 + ty * 8 + 4];
        float4 b4 = *(const float4*)&Ws[k * 64 + tx * 4];
        u64 bb0 = dupf(b4.x), bb1 = dupf(b4.y), bb2 = dupf(b4.z), bb3 = dupf(b4.w);
        u64 ap[4] = {a01.x, a01.y, a23.x, a23.y};
#pragma unroll
        for (int q = 0; q < 4; q++) {
            fma2(acc[q][0], ap[q], bb0);
            fma2(acc[q][1], ap[q], bb1);
            fma2(acc[q][2], ap[q], bb2);
            fma2(acc[q][3], ap[q], bb3);
        }
    }
    float* Cb = C + (size_t)z * planeStride;
#pragma unroll
    for (int q = 0; q < 4; q++) {
        float2 c0 = *(float2*)&acc[q][0];
        float2 c1 = *(float2*)&acc[q][1];
        float2 c2 = *(float2*)&acc[q][2];
        float2 c3 = *(float2*)&acc[q][3];
        int r0 = m0 + ty * 8 + 2 * q;
        *(float4*)&Cb[(size_t)r0 * cRow + n0 + tx * 4]       = make_float4(c0.x, c1.x, c2.x, c3.x);
        *(float4*)&Cb[(size_t)(r0 + 1) * cRow + n0 + tx * 4] = make_float4(c0.y, c1.y, c2.y, c3.y);
    }
}

// ---------------- generic tiled fp32 GEMM (final projections) --------------------
__global__ void __launch_bounds__(256) k_gemm(
    const float* __restrict__ A, int aRow, int aCol, int aComp,
    const float* __restrict__ W, int WO,
    float* __restrict__ C, int cRow, int cCol, int cComp, int ccol0,
    int K, int NC) {
    __shared__ __align__(16) float As[32 * 68];
    __shared__ __align__(16) float Ws[32 * 68];
    int tid = threadIdx.x;
    int m0 = blockIdx.y * 64;
    int n0 = blockIdx.x * 64;
    int comp = blockIdx.z;
    const float* Ab = A + (size_t)comp * aComp;
    float acc[4][4] = {};
    int ty = tid >> 4, tx = tid & 15;

    for (int k0 = 0; k0 < K; k0 += 32) {
#pragma unroll
        for (int r = 0; r < 8; r++) {
            int l = tid + r * 256;
            int kk = l & 31, mm = l >> 5;
            As[kk * 68 + mm] = Ab[(size_t)(m0 + mm) * aRow + (size_t)(k0 + kk) * aCol];
        }
#pragma unroll
        for (int r = 0; r < 8; r++) {
            int l = tid + r * 256;
            int kk = l >> 6, jj = l & 63;
            int col = n0 + jj;
            Ws[kk * 68 + jj] = (col < NC) ? W[(size_t)(k0 + kk) * WO + col] : 0.f;
        }
        __syncthreads();
#pragma unroll
        for (int k = 0; k < 32; k++) {
            float4 a4 = *(const float4*)&As[k * 68 + ty * 4];
            float4 b4 = *(const float4*)&Ws[k * 68 + tx * 4];
            float av[4] = {a4.x, a4.y, a4.z, a4.w};
            float bv[4] = {b4.x, b4.y, b4.z, b4.w};
#pragma unroll
            for (int i = 0; i < 4; i++)
#pragma unroll
                for (int j = 0; j < 4; j++)
                    acc[i][j] += av[i] * bv[j];
        }
        __syncthreads();
    }
#pragma unroll
    for (int i = 0; i < 4; i++) {
        int m = m0 + ty * 4 + i;
#pragma unroll
        for (int j = 0; j < 4; j++) {
            int col = n0 + tx * 4 + j;
            if (col < NC)
                C[(size_t)m * cRow + (size_t)comp * cComp + ccol0 + (size_t)col * cCol] = acc[i][j];
        }
    }
}

// ---------------- self term: warp per node ----------------------------------------
__global__ void __launch_bounds__(256) k_qkself2(const float* __restrict__ x) {
    __shared__ float s_x[8][160];
    int tid = threadIdx.x;
    int wid = tid >> 5, lane = tid & 31;
    int n = blockIdx.x * 8 + wid;
    const float4* xs = (const float4*)(x + (size_t)n * 160);
    ((float4*)s_x[wid])[lane] = xs[lane];
    if (lane < 8) ((float4*)s_x[wid])[32 + lane] = xs[32 + lane];
    __syncwarp();
    const float* xr = s_x[wid];
    const float* Sb = g_S + (size_t)n * 1088 + 512;
#pragma unroll
    for (int h = 0; h < 8; h++) {
        float a = Sb[h * 64 + lane] * xr[lane]
                + Sb[h * 64 + 32 + lane] * xr[32 + lane];
#pragma unroll
        for (int c = 0; c < 3; c++)
            a += g_V[c * VPLANE + (size_t)n * 576 + 256 + h * 32 + lane]
                 * xr[64 + lane * 3 + c];
#pragma unroll
        for (int o = 16; o; o >>= 1) a += __shfl_xor_sync(0xffffffffu, a, o);
        if (lane == 0) g_QKself[n * 8 + h] = a;
    }
}

// ---------------- CSR --------------------------------------------------------------
__global__ void k_hist(const int* __restrict__ ei) {
    int e = blockIdx.x * 256 + threadIdx.x;
    if (e < NE) atomicAdd(&g_cnt[ei[NE + e]], 1);
}

__global__ void __launch_bounds__(1024) k_scan() {
    __shared__ int wsum[32];
    int tid = threadIdx.x;
    int base = tid * 8;
    int loc[8]; int tot = 0;
#pragma unroll
    for (int i = 0; i < 8; i++) { loc[i] = tot; tot += g_cnt[base + i]; }
    int lane = tid & 31, w = tid >> 5;
    int incl = tot;
#pragma unroll
    for (int o = 1; o < 32; o <<= 1) {
        int y = __shfl_up_sync(0xffffffffu, incl, o);
        if (lane >= o) incl += y;
    }
    if (lane == 31) wsum[w] = incl;
    int excl = incl - tot;
    __syncthreads();
    if (w == 0) {
        int t = wsum[lane];
        int i2 = t;
#pragma unroll
        for (int o = 1; o < 32; o <<= 1) {
            int y = __shfl_up_sync(0xffffffffu, i2, o);
            if (lane >= o) i2 += y;
        }
        wsum[lane] = i2 - t;
    }
    __syncthreads();
    int off = wsum[w] + excl;
#pragma unroll
    for (int i = 0; i < 8; i++) {
        int o2 = off + loc[i];
        g_offs[base + i] = o2;
        g_cursor[base + i] = o2;
    }
    if (tid == 1023) g_offs[NN] = NE;
}

__global__ void k_scatter(const int* __restrict__ ei) {
    int e = blockIdx.x * 256 + threadIdx.x;
    if (e < NE) {
        int pos = atomicAdd(&g_cursor[ei[NE + e]], 1);
        g_elist[pos] = e;
    }
}

// ---------------- per-edge sph -> feat ----------------------------------------------
__global__ void __launch_bounds__(256) k_edgeprep(const float* __restrict__ rbf,
                                                  const float* __restrict__ rsh,
                                                  const int* __restrict__ ei,
                                                  const float* __restrict__ Wrbf) {
    __shared__ float sW[1024];
    int tid = threadIdx.x;
    for (int l = tid; l < 1024; l += 256) sW[l] = Wrbf[l];
    __syncthreads();
    int e = blockIdx.x * 8 + (tid >> 5);
    int lane = tid & 31;
    int src = ei[e], dst = ei[NE + e];
    int d = lane;
    float ps = g_S[(size_t)src * 1088 + 1024 + d] + g_S[(size_t)dst * 1088 + 1056 + d];
    float pv[3];
#pragma unroll
    for (int c = 0; c < 3; c++)
        pv[c] = g_V[c * VPLANE + (size_t)src * 576 + 512 + d]
              + g_V[c * VPLANE + (size_t)dst * 576 + 544 + d];
    float rval = (lane < 16) ? rbf[e * 16 + lane] : 0.f;
    float scal_s = 0.f, scal_v = 0.f;
#pragma unroll
    for (int b = 0; b < 16; b++) {
        float rb = __shfl_sync(0xffffffffu, rval, b);
        scal_s += rb * sW[b * 64 + d];
        scal_v += rb * sW[b * 64 + 32 + d];
    }
    float rs = rsh[e * 128 + d];
    float sph_s = rs * scal_s * ps;
    float sv[3];
#pragma unroll
    for (int c = 0; c < 3; c++)
        sv[c] = rsh[e * 128 + 32 + d * 3 + c] * scal_v * pv[c];
    float* f = g_feat + (size_t)e * 160;
    f[d]      = sph_s * sph_s;
    f[32 + d] = (sv[0] * sv[0] + sv[1] * sv[1] + sv[2] * sv[2]) * INV_SQRT3;
#pragma unroll
    for (int c = 0; c < 3; c++)
        f[64 + c * 32 + d] = sph_s * sv[c];
}

// ---------------- fused attention + aggregation: warp per node, f32x2 ----------------
__global__ void __launch_bounds__(256) k_attn_agg2(const float* __restrict__ x,
                                                   const int* __restrict__ ei) {
    __shared__ __align__(16) float s_x[8][160];
    __shared__ float s_lg[8][512];
    const unsigned F = 0xffffffffu;
    int tid = threadIdx.x;
    int wid = tid >> 5, lane = tid & 31;
    int n = blockIdx.x * 8 + wid;
    int h = lane >> 2, p = lane & 3;

    int s0 = g_offs[n], deg = g_offs[n + 1] - s0;
    float* lg = (deg <= 64) ? &s_lg[wid][0] : (g_logit + (size_t)s0 * 8);

    int e0 = 0, e1 = 0, src0 = 0, src1 = 0;
    if (lane < deg) e0 = g_elist[s0 + lane];
    if (lane + 32 < deg) e1 = g_elist[s0 + 32 + lane];
    if (lane < deg) src0 = ei[e0];
    if (lane + 32 < deg) src1 = ei[e1];

    float mymax = -FLT_MAX;
    {
        // per-lane tk slice (head h, terms p*40..p*40+39), packed as f32x2 pairs
        float tkf[40];
#pragma unroll
        for (int tt = 0; tt < 40; tt++) {
            int t = p * 40 + tt;
            if (t < 64)
                tkf[tt] = g_S[(size_t)n * 1088 + h * 64 + t];
            else {
                int j = t - 64;
                tkf[tt] = g_V[(j % 3) * VPLANE + (size_t)n * 576 + h * 32 + (j / 3)];
            }
        }
        u64 tk2[20];
#pragma unroll
        for (int i = 0; i < 20; i++) tk2[i] = pk2(tkf[2 * i], tkf[2 * i + 1]);

        for (int i = 0; i < deg; i++) {
            int e, src;
            if (i < 64) {
                e   = __shfl_sync(F, (i < 32) ? e0 : e1, i & 31);
                src = __shfl_sync(F, (i < 32) ? src0 : src1, i & 31);
            } else {
                int ee = 0, ss = 0;
                if (lane == 0) { ee = g_elist[s0 + i]; ss = ei[ee]; }
                e = __shfl_sync(F, ee, 0);
                src = __shfl_sync(F, ss, 0);
            }
            const float4* xs = (const float4*)(x + (size_t)src * 160);
            ((float4*)s_x[wid])[lane] = xs[lane];
            if (lane < 8) ((float4*)s_x[wid])[32 + lane] = xs[32 + lane];
            __syncwarp();
            const u64* xr2 = (const u64*)(s_x[wid] + p * 40);
            u64 ac0 = 0, ac1 = 0, ac2 = 0, ac3 = 0;
#pragma unroll
            for (int q = 0; q < 20; q += 4) {
                fma2(ac0, tk2[q + 0], xr2[q + 0]);
                fma2(ac1, tk2[q + 1], xr2[q + 1]);
                fma2(ac2, tk2[q + 2], xr2[q + 2]);
                fma2(ac3, tk2[q + 3], xr2[q + 3]);
            }
            float2 v0 = *(float2*)&ac0, v1 = *(float2*)&ac1;
            float2 v2 = *(float2*)&ac2, v3 = *(float2*)&ac3;
            float a = ((v0.x + v0.y) + (v1.x + v1.y)) + ((v2.x + v2.y) + (v3.x + v3.y));
            a += __shfl_xor_sync(F, a, 1);
            a += __shfl_xor_sync(F, a, 2);
            if (p == 0) {
                a += g_QKself[src * 8 + h];
                lg[i * 8 + h] = a;
                mymax = fmaxf(mymax, a);
            }
            __syncwarp();
        }
    }

    if (p == 0 && deg > 0) {
        float den = 0.f;
        for (int i = 0; i < deg; i++) {
            float ex = expf(lg[i * 8 + h] - mymax);
            lg[i * 8 + h] = ex;
            den += ex;
        }
        float inv = 1.f / den;
        for (int i = 0; i < deg; i++) lg[i * 8 + h] *= inv;
    }
    __syncwarp();

    // aggregation: paired accumulators
    // accS[h] = (agg[h*64+lane], agg[h*64+32+lane])
    // accV[h] = (agg_v c=0, c=1), accW[h] = agg_v c=2
    u64 accS[8] = {}, accV[8] = {};
    float accW[8] = {};

    for (int i = 0; i < deg; i++) {
        int e;
        if (i < 64) e = __shfl_sync(F, (i < 32) ? e0 : e1, i & 31);
        else {
            int ee = 0;
            if (lane == 0) ee = g_elist[s0 + i];
            e = __shfl_sync(F, ee, 0);
        }
        const float* fr = g_feat + (size_t)e * 160;
        float f0  = fr[lane];
        float f1  = fr[32 + lane];
        float fv0 = fr[64 + lane];
        float fv1 = fr[96 + lane];
        float fv2 = fr[128 + lane];
        u64 fS = pk2(f0, f1);
        u64 fV = pk2(fv0, fv1);
        const float* ar = lg + i * 8;
#pragma unroll
        for (int hh = 0; hh < 8; hh++) {
            float at = ar[hh];
            u64 at2 = dupf(at);
            fma2(accS[hh], fS, at2);
            fma2(accV[hh], fV, at2);
            accW[hh] += at * fv2;
        }
    }
    float* ao = g_agg + (size_t)n * 1280;
#pragma unroll
    for (int hh = 0; hh < 8; hh++) {
        float2 s = *(float2*)&accS[hh];
        ao[(2 * hh) * 32 + lane]      = s.x;
        ao[(2 * hh + 1) * 32 + lane]  = s.y;
        float2 v = *(float2*)&accV[hh];
        ao[(16 + hh) * 32 + lane]     = v.x;
        ao[(24 + hh) * 32 + lane]     = v.y;
        ao[(32 + hh) * 32 + lane]     = accW[hh];
    }
}

// ---------------- NormGate + output --------------------------------------------------
__global__ void __launch_bounds__(256) k_normgate(const float* __restrict__ ln_g,
                                                  const float* __restrict__ ln_b,
                                                  const float* __restrict__ W1,
                                                  const float* __restrict__ b1,
                                                  const float* __restrict__ W2,
                                                  const float* __restrict__ b2,
                                                  float* __restrict__ out) {
    __shared__ float sW1[96 * 96];
    __shared__ float sX[8][96];
    __shared__ float sH[8][96];
    int tid = threadIdx.x;
    int w = tid >> 5, lane = tid & 31;
    for (int i = tid; i < 9216; i += 256) sW1[i] = W1[i];
    __syncthreads();

    for (int sub = 0; sub < 4; sub++) {
        int n = blockIdx.x * 32 + w * 4 + sub;
        const float* mrow = g_m + (size_t)n * 160;
        float ms0 = mrow[lane], ms1 = mrow[32 + lane];
        float v0 = mrow[64 + lane * 3 + 0];
        float v1 = mrow[64 + lane * 3 + 1];
        float v2 = mrow[64 + lane * 3 + 2];
        float n00 = fabsf(ms0), n01 = fabsf(ms1);
        float n02 = sqrtf(v0 * v0 + v1 * v1 + v2 * v2);
        float s = n00 + n01 + n02;
        float s2 = n00 * n00 + n01 * n01 + n02 * n02;
#pragma unroll
        for (int o = 16; o; o >>= 1) {
            s  += __shfl_xor_sync(0xffffffffu, s, o);
            s2 += __shfl_xor_sync(0xffffffffu, s2, o);
        }
        float mu = s * (1.f / 96.f);
        float var = s2 * (1.f / 96.f) - mu * mu;
        float rstd = rsqrtf(var + 1e-5f);
        sX[w][lane]      = (n00 - mu) * rstd * ln_g[lane]      + ln_b[lane];
        sX[w][lane + 32] = (n01 - mu) * rstd * ln_g[lane + 32] + ln_b[lane + 32];
        sX[w][lane + 64] = (n02 - mu) * rstd * ln_g[lane + 64] + ln_b[lane + 64];
        __syncwarp();
#pragma unroll
        for (int t = 0; t < 3; t++) {
            int jp = lane + t * 32;
            float hs = b1[jp];
            for (int j = 0; j < 96; j++) hs += sX[w][j] * sW1[j * 96 + jp];
            sH[w][jp] = hs / (1.f + expf(-hs));
        }
        __syncwarp();
        float n0arr[3] = {n00, n01, n02};
        float f[3];
#pragma unroll
        for (int t = 0; t < 3; t++) {
            int jp = lane + t * 32;
            float gs = b2[jp];
            for (int j = 0; j < 96; j++) gs += sH[w][j] * W2[j * 96 + jp];
            float gg = gs / (1.f + expf(-gs));
            f[t] = gg / (n0arr[t] + 1e-6f);
        }
        out[n * 160 + lane]      = ms0 * f[0];
        out[n * 160 + 32 + lane] = ms1 * f[1];
        out[n * 160 + 64 + lane * 3 + 0] = v0 * f[2];
        out[n * 160 + 64 + lane * 3 + 1] = v1 * f[2];
        out[n * 160 + 64 + lane * 3 + 2] = v2 * f[2];
        __syncwarp();
    }
}

// ---------------- launch ----------------------------------------------------------------
extern "C" void kernel_launch(void* const* d_in, const int* in_sizes, int n_in,
                              void* d_out, int out_size) {
    const float* pseduo_x = (const float*)d_in[0];
    const float* rbf   = (const float*)d_in[1];
    const float* rsh   = (const float*)d_in[2];
    const int*   ei    = (const int*)d_in[3];
    const float* Wq_s  = (const float*)d_in[4];
    const float* Wq_v  = (const float*)d_in[5];
    const float* Wk_s  = (const float*)d_in[6];
    const float* Wk_v  = (const float*)d_in[7];
    const float* Wp_s  = (const float*)d_in[8];
    const float* Wp_v  = (const float*)d_in[9];
    const float* Wrbf  = (const float*)d_in[10];
    const float* Wv_s  = (const float*)d_in[11];
    const float* Wv_v  = (const float*)d_in[12];
    const float* Wm_s  = (const float*)d_in[13];
    const float* Wm_v  = (const float*)d_in[14];
    const float* ln_g  = (const float*)d_in[15];
    const float* ln_b  = (const float*)d_in[16];
    const float* W1    = (const float*)d_in[17];
    const float* b1    = (const float*)d_in[18];
    const float* W2    = (const float*)d_in[19];
    const float* b2    = (const float*)d_in[20];
    float* out = (float*)d_out;

    void* p;
    cudaGetSymbolAddress(&p, g_xT);  float* XT  = (float*)p;
    cudaGetSymbolAddress(&p, g_S);   float* S   = (float*)p;
    cudaGetSymbolAddress(&p, g_V);   float* V   = (float*)p;
    cudaGetSymbolAddress(&p, g_agg); float* AGG = (float*)p;
    cudaGetSymbolAddress(&p, g_m);   float* M   = (float*)p;
    cudaGetSymbolAddress(&p, g_Wts); float* Wts = (float*)p;
    cudaGetSymbolAddress(&p, g_Wtv); float* Wtv = (float*)p;
    cudaGetSymbolAddress(&p, g_Wcs); float* Wcs = (float*)p;
    cudaGetSymbolAddress(&p, g_Wcv); float* Wcv = (float*)p;

    k_pack2<<<50, 256>>>(Wq_s, Wq_v, Wk_s, Wk_v, Wp_s, Wp_v, Wv_s, Wv_v, Wm_s, Wm_v);
    k_xT<<<dim3(256, 5), dim3(32, 8)>>>(pseduo_x, XT);

    k_gemmT<64><<<dim3(17, 64, 1), 256>>>(XT, 0, 1, Wts, 1088, S, 1088, 0);
    k_gemmT<32><<<dim3(9, 64, 3), 256>>>(XT, 64, 3, Wtv, 576, V, 576, VPLANE);
    k_qkself2<<<1024, 256>>>(pseduo_x);

    k_hist<<<256, 256>>>(ei);
    k_scan<<<1, 1024>>>();
    k_scatter<<<256, 256>>>(ei);

    k_edgeprep<<<8192, 256>>>(rbf, rsh, ei, Wrbf);
    k_attn_agg2<<<1024, 256>>>(pseduo_x, ei);

    k_gemm<<<dim3(1, 128, 1), 256>>>(AGG, 1280, 1, 0, Wcs, 64,
                                     M, 160, 1, 0, 0, 512, 64);
    k_gemm<<<dim3(1, 128, 3), 256>>>(AGG + 512, 1280, 1, 256, Wcv, 32,
                                     M, 160, 3, 1, 64, 256, 32);

    k_normgate<<<256, 256>>>(ln_g, ln_b, W1, b1, W2, b2, out);
}

// round 9
// speedup vs baseline: 1.6547x; 1.0192x over previous
#include <cuda_runtime.h>
#include <math.h>
#include <float.h>

#define NN 8192
#define NE 65536
#define VPLANE ((size_t)NN * 576)

#define INV_SQRT128 0.08838834764831843f
#define INV_SQRT512 0.04419417382415922f
#define INV_SQRT3   0.5773502691896258f
#define INV_SQRT160 0.07905694150420949f
#define INV_SQRT32  0.17677669529663687f

#define SC_S   (0.125f * INV_SQRT128 * INV_SQRT160)
#define SC_V   (INV_SQRT32 * 0.125f * INV_SQRT160)
#define SC_P_S (INV_SQRT128)
#define SC_P_V (0.125f)
#define SC_C_S (0.125f * INV_SQRT512)
#define SC_C_V (0.125f * 0.0625f)

typedef unsigned long long u64;

__device__ __forceinline__ void fma2(u64& d, u64 a, u64 b) {
    asm("fma.rn.f32x2 %0, %1, %2, %0;" : "+l"(d) : "l"(a), "l"(b));
}
__device__ __forceinline__ u64 dupf(float x) {
    u64 r; asm("mov.b64 %0, {%1, %1};" : "=l"(r) : "r"(__float_as_uint(x))); return r;
}
__device__ __forceinline__ u64 pk2(float lo, float hi) {
    u64 r; asm("mov.b64 %0, {%1, %2};" : "=l"(r) : "r"(__float_as_uint(lo)), "r"(__float_as_uint(hi)));
    return r;
}

// ---------------- scratch ------------------------------------------------------
__device__ float g_xT[160 * NN];
__device__ float g_S[NN * 1088];          // tk_s 512 | tself_s 512 | PA_s 32 | PB_s 32
__device__ float g_V[3 * NN * 576];       // plane c: tk_v 256 | tself_v 256 | PAv 32 | PBv 32
__device__ float g_QKself[NN * 8];
__device__ float g_feat[NE * 160];        // c0 64 | vec c*32+d (96)
__device__ float g_logit[NE * 8];         // fallback (deg > 64)
__device__ float g_agg[NN * 1280];
__device__ float g_m[NN * 160];
__device__ int   g_cnt[NN];
__device__ int   g_offs[NN + 1];
__device__ int   g_cursor[NN];
__device__ int   g_elist[NE];
__device__ float g_Wts[64 * 1088];
__device__ float g_Wtv[32 * 576];
__device__ float g_Wcs[512 * 64];
__device__ float g_Wcv[256 * 32];

// ---------------- weight packing / grams (smem staged) --------------------------
__global__ void __launch_bounds__(256) k_pack2(
        const float* __restrict__ Wq_s, const float* __restrict__ Wq_v,
        const float* __restrict__ Wk_s, const float* __restrict__ Wk_v,
        const float* __restrict__ Wp_s, const float* __restrict__ Wp_v,
        const float* __restrict__ Wv_s, const float* __restrict__ Wv_v,
        const float* __restrict__ Wm_s, const float* __restrict__ Wm_v) {
    __shared__ float sm[8192];
    int b = blockIdx.x, tid = threadIdx.x;
    if (b < 16) {
        int h = b & 7, self = b >> 3;
        float* Q = sm; float* Kx = sm + 4096;
        for (int i = tid; i < 4096; i += 256) {
            int a = i >> 6, j = i & 63;
            Q[i]  = Wq_s[a * 512 + h * 64 + j];
            int kr = self ? a : (64 + a);
            Kx[i] = Wk_s[kr * 512 + h * 64 + j];
        }
        __syncthreads();
        for (int i = tid; i < 4096; i += 256) {
            int a = i & 63, bb = i >> 6;
            float s = 0.f;
            for (int j = 0; j < 64; j++) s += Q[a * 64 + j] * Kx[bb * 64 + j];
            g_Wts[bb * 1088 + self * 512 + h * 64 + a] = s * SC_S;
        }
    } else if (b < 32) {
        int h = (b - 16) & 7, self = (b - 16) >> 3;
        float* Q = sm; float* Kx = sm + 1024;
        for (int i = tid; i < 1024; i += 256) {
            int a = i >> 5, j = i & 31;
            Q[i]  = Wq_v[a * 256 + h * 32 + j];
            int kr = self ? a : (32 + a);
            Kx[i] = Wk_v[kr * 256 + h * 32 + j];
        }
        __syncthreads();
        for (int i = tid; i < 1024; i += 256) {
            int a = i & 31, bb = i >> 5;
            float s = 0.f;
            for (int j = 0; j < 32; j++) s += Q[a * 32 + j] * Kx[bb * 32 + j];
            g_Wtv[bb * 576 + self * 256 + h * 32 + a] = s * SC_V;
        }
    } else if (b < 40) {
        int h = b - 32;
        float* V = sm; float* M = sm + 4096;
        for (int i = tid; i < 4096; i += 256) {
            int k = i >> 6, j = i & 63;
            V[i] = Wv_s[k * 512 + h * 64 + j];
            M[i] = Wm_s[(h * 64 + k) * 64 + j];
        }
        __syncthreads();
        for (int i = tid; i < 4096; i += 256) {
            int d = i & 63, k = i >> 6;
            float s = 0.f;
            for (int j = 0; j < 64; j++) s += V[k * 64 + j] * M[j * 64 + d];
            g_Wcs[(h * 64 + k) * 64 + d] = s * SC_C_S;
        }
    } else if (b < 48) {
        int h = b - 40;
        float* V = sm; float* M = sm + 1024;
        for (int i = tid; i < 1024; i += 256) {
            int k = i >> 5, j = i & 31;
            V[i] = Wv_v[k * 256 + h * 32 + j] + Wv_v[(32 + k) * 256 + h * 32 + j];
            M[i] = Wm_v[(h * 32 + k) * 32 + j];
        }
        __syncthreads();
        for (int i = tid; i < 1024; i += 256) {
            int d = i & 31, k = i >> 5;
            float s = 0.f;
            for (int j = 0; j < 32; j++) s += V[k * 32 + j] * M[j * 32 + d];
            g_Wcv[(h * 32 + k) * 32 + d] = s * SC_C_V;
        }
    } else if (b == 48) {
        for (int i = tid; i < 4096; i += 256) {
            int bb = i >> 6, c = i & 63;
            float w = (c < 32) ? Wp_s[bb * 32 + c] : Wp_s[(64 + bb) * 32 + (c - 32)];
            g_Wts[bb * 1088 + 1024 + c] = w * SC_P_S;
        }
        for (int i = tid; i < 2048; i += 256) {
            int bb = i >> 6, c = i & 63;
            float w = (c < 32) ? Wp_v[bb * 32 + c] : Wp_v[(32 + bb) * 32 + (c - 32)];
            g_Wtv[bb * 576 + 512 + c] = w * SC_P_V;
        }
    } else {   // b == 49: zero histogram
        for (int i = tid; i < NN; i += 256) g_cnt[i] = 0;
    }
}

// ---------------- transpose x -> xT [160][8192] ----------------------------------
__global__ void k_xT(const float* __restrict__ x, float* __restrict__ xT) {
    __shared__ float t[32][33];
    int tx = threadIdx.x, ty = threadIdx.y;
    int n0 = blockIdx.x * 32, t0 = blockIdx.y * 32;
#pragma unroll
    for (int i = 0; i < 32; i += 8)
        t[ty + i][tx] = x[(size_t)(n0 + ty + i) * 160 + t0 + tx];
    __syncthreads();
#pragma unroll
    for (int i = 0; i < 32; i += 8)
        xT[(size_t)(t0 + ty + i) * 8192 + n0 + tx] = t[tx][ty + i];
}

// ---------------- full-K resident GEMM with f32x2 (BM=128, BN=64) -----------------
template<int K>
__global__ void __launch_bounds__(256) k_gemmT(
        const float* __restrict__ AT, int baseRow, int rowStride,
        const float* __restrict__ W, int N,
        float* __restrict__ C, int cRow, size_t planeStride) {
    __shared__ __align__(16) float As[K * 128];
    __shared__ __align__(16) float Ws[K * 64];
    int tid = threadIdx.x;
    int n0 = blockIdx.x * 64, m0 = blockIdx.y * 128;
    int z = blockIdx.z;
#pragma unroll
    for (int r = 0; r < (K * 128) / 1024; r++) {
        int idx = tid + r * 256;
        int k = idx >> 5, mp = idx & 31;
        *(float4*)&As[k * 128 + mp * 4] =
            *(const float4*)&AT[(size_t)(baseRow + z + k * rowStride) * 8192 + m0 + mp * 4];
    }
#pragma unroll
    for (int r = 0; r < (K * 64) / 1024; r++) {
        int idx = tid + r * 256;
        int k = idx >> 4, j = idx & 15;
        *(float4*)&Ws[k * 64 + j * 4] = *(const float4*)&W[(size_t)k * N + n0 + j * 4];
    }
    __syncthreads();
    int ty = tid >> 4, tx = tid & 15;
    u64 acc[4][4] = {};
#pragma unroll 8
    for (int k = 0; k < K; k++) {
        ulonglong2 a01 = *(const ulonglong2*)&As[k * 128 + ty * 8];
        ulonglong2 a23 = *(const ulonglong2*)&As[k * 128 + ty * 8 + 4];
        float4 b4 = *(const float4*)&Ws[k * 64 + tx * 4];
        u64 bb0 = dupf(b4.x), bb1 = dupf(b4.y), bb2 = dupf(b4.z), bb3 = dupf(b4.w);
        u64 ap[4] = {a01.x, a01.y, a23.x, a23.y};
#pragma unroll
        for (int q = 0; q < 4; q++) {
            fma2(acc[q][0], ap[q], bb0);
            fma2(acc[q][1], ap[q], bb1);
            fma2(acc[q][2], ap[q], bb2);
            fma2(acc[q][3], ap[q], bb3);
        }
    }
    float* Cb = C + (size_t)z * planeStride;
#pragma unroll
    for (int q = 0; q < 4; q++) {
        float2 c0 = *(float2*)&acc[q][0];
        float2 c1 = *(float2*)&acc[q][1];
        float2 c2 = *(float2*)&acc[q][2];
        float2 c3 = *(float2*)&acc[q][3];
        int r0 = m0 + ty * 8 + 2 * q;
        *(float4*)&Cb[(size_t)r0 * cRow + n0 + tx * 4]       = make_float4(c0.x, c1.x, c2.x, c3.x);
        *(float4*)&Cb[(size_t)(r0 + 1) * cRow + n0 + tx * 4] = make_float4(c0.y, c1.y, c2.y, c3.y);
    }
}

// ---------------- merged final projections (scalar + vector in one launch) --------
// blocks [0,128): scalar slice m-tile; blocks [128,512): vector comp c, m-tile
__global__ void __launch_bounds__(256) k_projm() {
    __shared__ __align__(16) float As[32 * 68];
    __shared__ __align__(16) float Ws[32 * 68];
    int tid = threadIdx.x;
    int b = blockIdx.x;
    const float* A; const float* W; float* C;
    int aRow, K, NC, cRow, cCol, ccol0, m0;
    if (b < 128) {
        A = g_agg; aRow = 1280; K = 512; NC = 64;
        W = g_Wcs; C = g_m; cRow = 160; cCol = 1; ccol0 = 0;
        m0 = b * 64;
    } else {
        int c = (b - 128) / 128, mt = (b - 128) % 128;
        A = g_agg + 512 + c * 256; aRow = 1280; K = 256; NC = 32;
        W = g_Wcv; C = g_m + 64 + c; cRow = 160; cCol = 3; ccol0 = 0;
        m0 = mt * 64;
    }
    float acc[4][4] = {};
    int ty = tid >> 4, tx = tid & 15;

    for (int k0 = 0; k0 < K; k0 += 32) {
#pragma unroll
        for (int r = 0; r < 8; r++) {
            int l = tid + r * 256;
            int kk = l & 31, mm = l >> 5;
            As[kk * 68 + mm] = A[(size_t)(m0 + mm) * aRow + (k0 + kk)];
        }
#pragma unroll
        for (int r = 0; r < 8; r++) {
            int l = tid + r * 256;
            int kk = l >> 6, jj = l & 63;
            Ws[kk * 68 + jj] = (jj < NC) ? W[(size_t)(k0 + kk) * NC + jj] : 0.f;
        }
        __syncthreads();
#pragma unroll
        for (int k = 0; k < 32; k++) {
            float4 a4 = *(const float4*)&As[k * 68 + ty * 4];
            float4 b4 = *(const float4*)&Ws[k * 68 + tx * 4];
            float av[4] = {a4.x, a4.y, a4.z, a4.w};
            float bv[4] = {b4.x, b4.y, b4.z, b4.w};
#pragma unroll
            for (int i = 0; i < 4; i++)
#pragma unroll
                for (int j = 0; j < 4; j++)
                    acc[i][j] += av[i] * bv[j];
        }
        __syncthreads();
    }
#pragma unroll
    for (int i = 0; i < 4; i++) {
        int m = m0 + ty * 4 + i;
#pragma unroll
        for (int j = 0; j < 4; j++) {
            int col = tx * 4 + j;
            if (col < NC)
                C[(size_t)m * cRow + ccol0 + col * cCol] = acc[i][j];
        }
    }
}

// ---------------- CSR --------------------------------------------------------------
__global__ void k_hist(const int* __restrict__ ei) {
    int e = blockIdx.x * 256 + threadIdx.x;
    if (e < NE) atomicAdd(&g_cnt[ei[NE + e]], 1);
}

__global__ void __launch_bounds__(1024) k_scan() {
    __shared__ int wsum[32];
    int tid = threadIdx.x;
    int base = tid * 8;
    int loc[8]; int tot = 0;
#pragma unroll
    for (int i = 0; i < 8; i++) { loc[i] = tot; tot += g_cnt[base + i]; }
    int lane = tid & 31, w = tid >> 5;
    int incl = tot;
#pragma unroll
    for (int o = 1; o < 32; o <<= 1) {
        int y = __shfl_up_sync(0xffffffffu, incl, o);
        if (lane >= o) incl += y;
    }
    if (lane == 31) wsum[w] = incl;
    int excl = incl - tot;
    __syncthreads();
    if (w == 0) {
        int t = wsum[lane];
        int i2 = t;
#pragma unroll
        for (int o = 1; o < 32; o <<= 1) {
            int y = __shfl_up_sync(0xffffffffu, i2, o);
            if (lane >= o) i2 += y;
        }
        wsum[lane] = i2 - t;
    }
    __syncthreads();
    int off = wsum[w] + excl;
#pragma unroll
    for (int i = 0; i < 8; i++) {
        int o2 = off + loc[i];
        g_offs[base + i] = o2;
        g_cursor[base + i] = o2;
    }
    if (tid == 1023) g_offs[NN] = NE;
}

__global__ void k_scatter(const int* __restrict__ ei) {
    int e = blockIdx.x * 256 + threadIdx.x;
    if (e < NE) {
        int pos = atomicAdd(&g_cursor[ei[NE + e]], 1);
        g_elist[pos] = e;
    }
}

// ---------------- edgeprep (64 edges/block) + qkself merged --------------------------
__global__ void __launch_bounds__(256) k_edge_qk(const float* __restrict__ rbf,
                                                 const float* __restrict__ rsh,
                                                 const int* __restrict__ ei,
                                                 const float* __restrict__ Wrbf,
                                                 const float* __restrict__ x) {
    int b = blockIdx.x, tid = threadIdx.x;
    if (b < 1024) {                       // edgeprep: 64 edges per block
        __shared__ float sW[1024];
        for (int l = tid; l < 1024; l += 256) sW[l] = Wrbf[l];
        __syncthreads();
        int wid = tid >> 5, lane = tid & 31;
        int d = lane;
#pragma unroll
        for (int it = 0; it < 8; it++) {
            int e = b * 64 + it * 8 + wid;
            int src = ei[e], dst = ei[NE + e];
            float ps = g_S[(size_t)src * 1088 + 1024 + d] + g_S[(size_t)dst * 1088 + 1056 + d];
            float pv[3];
#pragma unroll
            for (int c = 0; c < 3; c++)
                pv[c] = g_V[c * VPLANE + (size_t)src * 576 + 512 + d]
                      + g_V[c * VPLANE + (size_t)dst * 576 + 544 + d];
            float rval = (lane < 16) ? rbf[e * 16 + lane] : 0.f;
            float scal_s = 0.f, scal_v = 0.f;
#pragma unroll
            for (int bq = 0; bq < 16; bq++) {
                float rb = __shfl_sync(0xffffffffu, rval, bq);
                scal_s += rb * sW[bq * 64 + d];
                scal_v += rb * sW[bq * 64 + 32 + d];
            }
            float rs = rsh[e * 128 + d];
            float sph_s = rs * scal_s * ps;
            float sv[3];
#pragma unroll
            for (int c = 0; c < 3; c++)
                sv[c] = rsh[e * 128 + 32 + d * 3 + c] * scal_v * pv[c];
            float* f = g_feat + (size_t)e * 160;
            f[d]      = sph_s * sph_s;
            f[32 + d] = (sv[0] * sv[0] + sv[1] * sv[1] + sv[2] * sv[2]) * INV_SQRT3;
#pragma unroll
            for (int c = 0; c < 3; c++)
                f[64 + c * 32 + d] = sph_s * sv[c];
        }
    } else {                              // qkself: warp per node
        __shared__ float s_x[8][160];
        int wid = tid >> 5, lane = tid & 31;
        int n = (b - 1024) * 8 + wid;
        const float4* xs = (const float4*)(x + (size_t)n * 160);
        ((float4*)s_x[wid])[lane] = xs[lane];
        if (lane < 8) ((float4*)s_x[wid])[32 + lane] = xs[32 + lane];
        __syncwarp();
        const float* xr = s_x[wid];
        const float* Sb = g_S + (size_t)n * 1088 + 512;
#pragma unroll
        for (int h = 0; h < 8; h++) {
            float a = Sb[h * 64 + lane] * xr[lane]
                    + Sb[h * 64 + 32 + lane] * xr[32 + lane];
#pragma unroll
            for (int c = 0; c < 3; c++)
                a += g_V[c * VPLANE + (size_t)n * 576 + 256 + h * 32 + lane]
                     * xr[64 + lane * 3 + c];
#pragma unroll
            for (int o = 16; o; o >>= 1) a += __shfl_xor_sync(0xffffffffu, a, o);
            if (lane == 0) g_QKself[n * 8 + h] = a;
        }
    }
}

// ---------------- fused attention + aggregation: warp per node, f32x2 ----------------
__global__ void __launch_bounds__(256) k_attn_agg2(const float* __restrict__ x,
                                                   const int* __restrict__ ei) {
    __shared__ __align__(16) float s_x[8][160];
    __shared__ float s_lg[8][512];
    const unsigned F = 0xffffffffu;
    int tid = threadIdx.x;
    int wid = tid >> 5, lane = tid & 31;
    int n = blockIdx.x * 8 + wid;
    int h = lane >> 2, p = lane & 3;

    int s0 = g_offs[n], deg = g_offs[n + 1] - s0;
    float* lg = (deg <= 64) ? &s_lg[wid][0] : (g_logit + (size_t)s0 * 8);

    int e0 = 0, e1 = 0, src0 = 0, src1 = 0;
    if (lane < deg) e0 = g_elist[s0 + lane];
    if (lane + 32 < deg) e1 = g_elist[s0 + 32 + lane];
    if (lane < deg) src0 = ei[e0];
    if (lane + 32 < deg) src1 = ei[e1];

    float mymax = -FLT_MAX;
    {
        float tkf[40];
#pragma unroll
        for (int tt = 0; tt < 40; tt++) {
            int t = p * 40 + tt;
            if (t < 64)
                tkf[tt] = g_S[(size_t)n * 1088 + h * 64 + t];
            else {
                int j = t - 64;
                tkf[tt] = g_V[(j % 3) * VPLANE + (size_t)n * 576 + h * 32 + (j / 3)];
            }
        }
        u64 tk2[20];
#pragma unroll
        for (int i = 0; i < 20; i++) tk2[i] = pk2(tkf[2 * i], tkf[2 * i + 1]);

        for (int i = 0; i < deg; i++) {
            int e, src;
            if (i < 64) {
                e   = __shfl_sync(F, (i < 32) ? e0 : e1, i & 31);
                src = __shfl_sync(F, (i < 32) ? src0 : src1, i & 31);
            } else {
                int ee = 0, ss = 0;
                if (lane == 0) { ee = g_elist[s0 + i]; ss = ei[ee]; }
                e = __shfl_sync(F, ee, 0);
                src = __shfl_sync(F, ss, 0);
            }
            const float4* xs = (const float4*)(x + (size_t)src * 160);
            ((float4*)s_x[wid])[lane] = xs[lane];
            if (lane < 8) ((float4*)s_x[wid])[32 + lane] = xs[32 + lane];
            __syncwarp();
            const u64* xr2 = (const u64*)(s_x[wid] + p * 40);
            u64 ac0 = 0, ac1 = 0, ac2 = 0, ac3 = 0;
#pragma unroll
            for (int q = 0; q < 20; q += 4) {
                fma2(ac0, tk2[q + 0], xr2[q + 0]);
                fma2(ac1, tk2[q + 1], xr2[q + 1]);
                fma2(ac2, tk2[q + 2], xr2[q + 2]);
                fma2(ac3, tk2[q + 3], xr2[q + 3]);
            }
            float2 v0 = *(float2*)&ac0, v1 = *(float2*)&ac1;
            float2 v2 = *(float2*)&ac2, v3 = *(float2*)&ac3;
            float a = ((v0.x + v0.y) + (v1.x + v1.y)) + ((v2.x + v2.y) + (v3.x + v3.y));
            a += __shfl_xor_sync(F, a, 1);
            a += __shfl_xor_sync(F, a, 2);
            if (p == 0) {
                a += g_QKself[src * 8 + h];
                lg[i * 8 + h] = a;
                mymax = fmaxf(mymax, a);
            }
            __syncwarp();
        }
    }

    if (p == 0 && deg > 0) {
        float den = 0.f;
        for (int i = 0; i < deg; i++) {
            float ex = expf(lg[i * 8 + h] - mymax);
            lg[i * 8 + h] = ex;
            den += ex;
        }
        float inv = 1.f / den;
        for (int i = 0; i < deg; i++) lg[i * 8 + h] *= inv;
    }
    __syncwarp();

    u64 accS[8] = {}, accV[8] = {};
    float accW[8] = {};

    for (int i = 0; i < deg; i++) {
        int e;
        if (i < 64) e = __shfl_sync(F, (i < 32) ? e0 : e1, i & 31);
        else {
            int ee = 0;
            if (lane == 0) ee = g_elist[s0 + i];
            e = __shfl_sync(F, ee, 0);
        }
        const float* fr = g_feat + (size_t)e * 160;
        float f0  = fr[lane];
        float f1  = fr[32 + lane];
        float fv0 = fr[64 + lane];
        float fv1 = fr[96 + lane];
        float fv2 = fr[128 + lane];
        u64 fS = pk2(f0, f1);
        u64 fV = pk2(fv0, fv1);
        const float* ar = lg + i * 8;
#pragma unroll
        for (int hh = 0; hh < 8; hh++) {
            float at = ar[hh];
            u64 at2 = dupf(at);
            fma2(accS[hh], fS, at2);
            fma2(accV[hh], fV, at2);
            accW[hh] += at * fv2;
        }
    }
    float* ao = g_agg + (size_t)n * 1280;
#pragma unroll
    for (int hh = 0; hh < 8; hh++) {
        float2 s = *(float2*)&accS[hh];
        ao[(2 * hh) * 32 + lane]      = s.x;
        ao[(2 * hh + 1) * 32 + lane]  = s.y;
        float2 v = *(float2*)&accV[hh];
        ao[(16 + hh) * 32 + lane]     = v.x;
        ao[(24 + hh) * 32 + lane]     = v.y;
        ao[(32 + hh) * 32 + lane]     = accW[hh];
    }
}

// ---------------- NormGate + output --------------------------------------------------
__global__ void __launch_bounds__(256) k_normgate(const float* __restrict__ ln_g,
                                                  const float* __restrict__ ln_b,
                                                  const float* __restrict__ W1,
                                                  const float* __restrict__ b1,
                                                  const float* __restrict__ W2,
                                                  const float* __restrict__ b2,
                                                  float* __restrict__ out) {
    __shared__ float sW1[96 * 96];
    __shared__ float sX[8][96];
    __shared__ float sH[8][96];
    int tid = threadIdx.x;
    int w = tid >> 5, lane = tid & 31;
    for (int i = tid; i < 9216; i += 256) sW1[i] = W1[i];
    __syncthreads();

    for (int sub = 0; sub < 4; sub++) {
        int n = blockIdx.x * 32 + w * 4 + sub;
        const float* mrow = g_m + (size_t)n * 160;
        float ms0 = mrow[lane], ms1 = mrow[32 + lane];
        float v0 = mrow[64 + lane * 3 + 0];
        float v1 = mrow[64 + lane * 3 + 1];
        float v2 = mrow[64 + lane * 3 + 2];
        float n00 = fabsf(ms0), n01 = fabsf(ms1);
        float n02 = sqrtf(v0 * v0 + v1 * v1 + v2 * v2);
        float s = n00 + n01 + n02;
        float s2 = n00 * n00 + n01 * n01 + n02 * n02;
#pragma unroll
        for (int o = 16; o; o >>= 1) {
            s  += __shfl_xor_sync(0xffffffffu, s, o);
            s2 += __shfl_xor_sync(0xffffffffu, s2, o);
        }
        float mu = s * (1.f / 96.f);
        float var = s2 * (1.f / 96.f) - mu * mu;
        float rstd = rsqrtf(var + 1e-5f);
        sX[w][lane]      = (n00 - mu) * rstd * ln_g[lane]      + ln_b[lane];
        sX[w][lane + 32] = (n01 - mu) * rstd * ln_g[lane + 32] + ln_b[lane + 32];
        sX[w][lane + 64] = (n02 - mu) * rstd * ln_g[lane + 64] + ln_b[lane + 64];
        __syncwarp();
#pragma unroll
        for (int t = 0; t < 3; t++) {
            int jp = lane + t * 32;
            float hs = b1[jp];
            for (int j = 0; j < 96; j++) hs += sX[w][j] * sW1[j * 96 + jp];
            sH[w][jp] = hs / (1.f + expf(-hs));
        }
        __syncwarp();
        float n0arr[3] = {n00, n01, n02};
        float f[3];
#pragma unroll
        for (int t = 0; t < 3; t++) {
            int jp = lane + t * 32;
            float gs = b2[jp];
            for (int j = 0; j < 96; j++) gs += sH[w][j] * W2[j * 96 + jp];
            float gg = gs / (1.f + expf(-gs));
            f[t] = gg / (n0arr[t] + 1e-6f);
        }
        out[n * 160 + lane]      = ms0 * f[0];
        out[n * 160 + 32 + lane] = ms1 * f[1];
        out[n * 160 + 64 + lane * 3 + 0] = v0 * f[2];
        out[n * 160 + 64 + lane * 3 + 1] = v1 * f[2];
        out[n * 160 + 64 + lane * 3 + 2] = v2 * f[2];
        __syncwarp();
    }
}

// ---------------- launch ----------------------------------------------------------------
extern "C" void kernel_launch(void* const* d_in, const int* in_sizes, int n_in,
                              void* d_out, int out_size) {
    const float* pseduo_x = (const float*)d_in[0];
    const float* rbf   = (const float*)d_in[1];
    const float* rsh   = (const float*)d_in[2];
    const int*   ei    = (const int*)d_in[3];
    const float* Wq_s  = (const float*)d_in[4];
    const float* Wq_v  = (const float*)d_in[5];
    const float* Wk_s  = (const float*)d_in[6];
    const float* Wk_v  = (const float*)d_in[7];
    const float* Wp_s  = (const float*)d_in[8];
    const float* Wp_v  = (const float*)d_in[9];
    const float* Wrbf  = (const float*)d_in[10];
    const float* Wv_s  = (const float*)d_in[11];
    const float* Wv_v  = (const float*)d_in[12];
    const float* Wm_s  = (const float*)d_in[13];
    const float* Wm_v  = (const float*)d_in[14];
    const float* ln_g  = (const float*)d_in[15];
    const float* ln_b  = (const float*)d_in[16];
    const float* W1    = (const float*)d_in[17];
    const float* b1    = (const float*)d_in[18];
    const float* W2    = (const float*)d_in[19];
    const float* b2    = (const float*)d_in[20];
    float* out = (float*)d_out;

    void* p;
    cudaGetSymbolAddress(&p, g_xT);  float* XT  = (float*)p;
    cudaGetSymbolAddress(&p, g_S);   float* S   = (float*)p;
    cudaGetSymbolAddress(&p, g_V);   float* V   = (float*)p;
    cudaGetSymbolAddress(&p, g_Wts); float* Wts = (float*)p;
    cudaGetSymbolAddress(&p, g_Wtv); float* Wtv = (float*)p;

    k_pack2<<<50, 256>>>(Wq_s, Wq_v, Wk_s, Wk_v, Wp_s, Wp_v, Wv_s, Wv_v, Wm_s, Wm_v);
    k_xT<<<dim3(256, 5), dim3(32, 8)>>>(pseduo_x, XT);

    k_gemmT<64><<<dim3(17, 64, 1), 256>>>(XT, 0, 1, Wts, 1088, S, 1088, 0);
    k_gemmT<32><<<dim3(9, 64, 3), 256>>>(XT, 64, 3, Wtv, 576, V, 576, VPLANE);

    k_hist<<<256, 256>>>(ei);
    k_scan<<<1, 1024>>>();
    k_scatter<<<256, 256>>>(ei);

    // edgeprep (1024 blocks) + qkself (1024 blocks) in one launch
    k_edge_qk<<<2048, 256>>>(rbf, rsh, ei, Wrbf, pseduo_x);

    k_attn_agg2<<<1024, 256>>>(pseduo_x, ei);

    k_projm<<<512, 256>>>();
    k_normgate<<<256, 256>>>(ln_g, ln_b, W1, b1, W2, b2, out);
}

// round 10
// speedup vs baseline: 1.6937x; 1.0235x over previous
#include <cuda_runtime.h>
#include <math.h>
#include <float.h>

#define NN 8192
#define NE 65536
#define VPLANE ((size_t)NN * 576)

#define INV_SQRT128 0.08838834764831843f
#define INV_SQRT512 0.04419417382415922f
#define INV_SQRT3   0.5773502691896258f
#define INV_SQRT160 0.07905694150420949f
#define INV_SQRT32  0.17677669529663687f

#define SC_S   (0.125f * INV_SQRT128 * INV_SQRT160)
#define SC_V   (INV_SQRT32 * 0.125f * INV_SQRT160)
#define SC_P_S (INV_SQRT128)
#define SC_P_V (0.125f)
#define SC_C_S (0.125f * INV_SQRT512)
#define SC_C_V (0.125f * 0.0625f)

typedef unsigned long long u64;

__device__ __forceinline__ void fma2(u64& d, u64 a, u64 b) {
    asm("fma.rn.f32x2 %0, %1, %2, %0;" : "+l"(d) : "l"(a), "l"(b));
}
__device__ __forceinline__ u64 dupf(float x) {
    u64 r; asm("mov.b64 %0, {%1, %1};" : "=l"(r) : "r"(__float_as_uint(x))); return r;
}
__device__ __forceinline__ u64 pk2(float lo, float hi) {
    u64 r; asm("mov.b64 %0, {%1, %2};" : "=l"(r) : "r"(__float_as_uint(lo)), "r"(__float_as_uint(hi)));
    return r;
}

// ---------------- scratch ------------------------------------------------------
__device__ float g_xT[160 * NN];
__device__ float g_S[NN * 1088];          // tk_s 512 | tself_s 512 | PA_s 32 | PB_s 32
__device__ float g_V[3 * NN * 576];       // plane c: tk_v 256 | tself_v 256 | PAv 32 | PBv 32
__device__ float g_QKself[NN * 8];
__device__ float g_feat[NE * 160];        // c0 64 | vec c*32+d (96)
__device__ float g_logit[NE * 8];         // fallback (deg > 64)
__device__ float g_agg[NN * 1280];
__device__ float g_m[NN * 160];
__device__ int   g_cnt[NN];
__device__ int   g_offs[NN + 1];
__device__ int   g_cursor[NN];
__device__ int   g_elist[NE];
__device__ float g_Wts[64 * 1088];
__device__ float g_Wtv[32 * 576];
__device__ float g_Wcs[512 * 64];
__device__ float g_Wcv[256 * 32];

// ---------------- weight packing / grams (smem staged) --------------------------
__global__ void __launch_bounds__(256) k_pack2(
        const float* __restrict__ Wq_s, const float* __restrict__ Wq_v,
        const float* __restrict__ Wk_s, const float* __restrict__ Wk_v,
        const float* __restrict__ Wp_s, const float* __restrict__ Wp_v,
        const float* __restrict__ Wv_s, const float* __restrict__ Wv_v,
        const float* __restrict__ Wm_s, const float* __restrict__ Wm_v) {
    __shared__ float sm[8192];
    int b = blockIdx.x, tid = threadIdx.x;
    if (b < 16) {
        int h = b & 7, self = b >> 3;
        float* Q = sm; float* Kx = sm + 4096;
        for (int i = tid; i < 4096; i += 256) {
            int a = i >> 6, j = i & 63;
            Q[i]  = Wq_s[a * 512 + h * 64 + j];
            int kr = self ? a : (64 + a);
            Kx[i] = Wk_s[kr * 512 + h * 64 + j];
        }
        __syncthreads();
        for (int i = tid; i < 4096; i += 256) {
            int a = i & 63, bb = i >> 6;
            float s = 0.f;
            for (int j = 0; j < 64; j++) s += Q[a * 64 + j] * Kx[bb * 64 + j];
            g_Wts[bb * 1088 + self * 512 + h * 64 + a] = s * SC_S;
        }
    } else if (b < 32) {
        int h = (b - 16) & 7, self = (b - 16) >> 3;
        float* Q = sm; float* Kx = sm + 1024;
        for (int i = tid; i < 1024; i += 256) {
            int a = i >> 5, j = i & 31;
            Q[i]  = Wq_v[a * 256 + h * 32 + j];
            int kr = self ? a : (32 + a);
            Kx[i] = Wk_v[kr * 256 + h * 32 + j];
        }
        __syncthreads();
        for (int i = tid; i < 1024; i += 256) {
            int a = i & 31, bb = i >> 5;
            float s = 0.f;
            for (int j = 0; j < 32; j++) s += Q[a * 32 + j] * Kx[bb * 32 + j];
            g_Wtv[bb * 576 + self * 256 + h * 32 + a] = s * SC_V;
        }
    } else if (b < 40) {
        int h = b - 32;
        float* V = sm; float* M = sm + 4096;
        for (int i = tid; i < 4096; i += 256) {
            int k = i >> 6, j = i & 63;
            V[i] = Wv_s[k * 512 + h * 64 + j];
            M[i] = Wm_s[(h * 64 + k) * 64 + j];
        }
        __syncthreads();
        for (int i = tid; i < 4096; i += 256) {
            int d = i & 63, k = i >> 6;
            float s = 0.f;
            for (int j = 0; j < 64; j++) s += V[k * 64 + j] * M[j * 64 + d];
            g_Wcs[(h * 64 + k) * 64 + d] = s * SC_C_S;
        }
    } else if (b < 48) {
        int h = b - 40;
        float* V = sm; float* M = sm + 1024;
        for (int i = tid; i < 1024; i += 256) {
            int k = i >> 5, j = i & 31;
            V[i] = Wv_v[k * 256 + h * 32 + j] + Wv_v[(32 + k) * 256 + h * 32 + j];
            M[i] = Wm_v[(h * 32 + k) * 32 + j];
        }
        __syncthreads();
        for (int i = tid; i < 1024; i += 256) {
            int d = i & 31, k = i >> 5;
            float s = 0.f;
            for (int j = 0; j < 32; j++) s += V[k * 32 + j] * M[j * 32 + d];
            g_Wcv[(h * 32 + k) * 32 + d] = s * SC_C_V;
        }
    } else if (b == 48) {
        for (int i = tid; i < 4096; i += 256) {
            int bb = i >> 6, c = i & 63;
            float w = (c < 32) ? Wp_s[bb * 32 + c] : Wp_s[(64 + bb) * 32 + (c - 32)];
            g_Wts[bb * 1088 + 1024 + c] = w * SC_P_S;
        }
        for (int i = tid; i < 2048; i += 256) {
            int bb = i >> 6, c = i & 63;
            float w = (c < 32) ? Wp_v[bb * 32 + c] : Wp_v[(32 + bb) * 32 + (c - 32)];
            g_Wtv[bb * 576 + 512 + c] = w * SC_P_V;
        }
    } else {   // b == 49: zero histogram
        for (int i = tid; i < NN; i += 256) g_cnt[i] = 0;
    }
}

// ---------------- transpose x -> xT (+ histogram row) ------------------------------
__global__ void k_xT(const float* __restrict__ x, float* __restrict__ xT,
                     const int* __restrict__ ei) {
    int tx = threadIdx.x, ty = threadIdx.y;
    if (blockIdx.y == 5) {               // histogram over dst
        int e = blockIdx.x * 256 + ty * 32 + tx;
        atomicAdd(&g_cnt[ei[NE + e]], 1);
        return;
    }
    __shared__ float t[32][33];
    int n0 = blockIdx.x * 32, t0 = blockIdx.y * 32;
#pragma unroll
    for (int i = 0; i < 32; i += 8)
        t[ty + i][tx] = x[(size_t)(n0 + ty + i) * 160 + t0 + tx];
    __syncthreads();
#pragma unroll
    for (int i = 0; i < 32; i += 8)
        xT[(size_t)(t0 + ty + i) * 8192 + n0 + tx] = t[tx][ty + i];
}

// ---------------- full-K resident GEMM with f32x2 (BM=128, BN=64) -----------------
template<int K>
__global__ void __launch_bounds__(256) k_gemmT(
        const float* __restrict__ AT, int baseRow, int rowStride,
        const float* __restrict__ W, int N,
        float* __restrict__ C, int cRow, size_t planeStride) {
    __shared__ __align__(16) float As[K * 128];
    __shared__ __align__(16) float Ws[K * 64];
    int tid = threadIdx.x;
    int n0 = blockIdx.x * 64, m0 = blockIdx.y * 128;
    int z = blockIdx.z;
#pragma unroll
    for (int r = 0; r < (K * 128) / 1024; r++) {
        int idx = tid + r * 256;
        int k = idx >> 5, mp = idx & 31;
        *(float4*)&As[k * 128 + mp * 4] =
            *(const float4*)&AT[(size_t)(baseRow + z + k * rowStride) * 8192 + m0 + mp * 4];
    }
#pragma unroll
    for (int r = 0; r < (K * 64) / 1024; r++) {
        int idx = tid + r * 256;
        int k = idx >> 4, j = idx & 15;
        *(float4*)&Ws[k * 64 + j * 4] = *(const float4*)&W[(size_t)k * N + n0 + j * 4];
    }
    __syncthreads();
    int ty = tid >> 4, tx = tid & 15;
    u64 acc[4][4] = {};
#pragma unroll 8
    for (int k = 0; k < K; k++) {
        ulonglong2 a01 = *(const ulonglong2*)&As[k * 128 + ty * 8];
        ulonglong2 a23 = *(const ulonglong2*)&As[k * 128 + ty * 8 + 4];
        float4 b4 = *(const float4*)&Ws[k * 64 + tx * 4];
        u64 bb0 = dupf(b4.x), bb1 = dupf(b4.y), bb2 = dupf(b4.z), bb3 = dupf(b4.w);
        u64 ap[4] = {a01.x, a01.y, a23.x, a23.y};
#pragma unroll
        for (int q = 0; q < 4; q++) {
            fma2(acc[q][0], ap[q], bb0);
            fma2(acc[q][1], ap[q], bb1);
            fma2(acc[q][2], ap[q], bb2);
            fma2(acc[q][3], ap[q], bb3);
        }
    }
    float* Cb = C + (size_t)z * planeStride;
#pragma unroll
    for (int q = 0; q < 4; q++) {
        float2 c0 = *(float2*)&acc[q][0];
        float2 c1 = *(float2*)&acc[q][1];
        float2 c2 = *(float2*)&acc[q][2];
        float2 c3 = *(float2*)&acc[q][3];
        int r0 = m0 + ty * 8 + 2 * q;
        *(float4*)&Cb[(size_t)r0 * cRow + n0 + tx * 4]       = make_float4(c0.x, c1.x, c2.x, c3.x);
        *(float4*)&Cb[(size_t)(r0 + 1) * cRow + n0 + tx * 4] = make_float4(c0.y, c1.y, c2.y, c3.y);
    }
}

// ---------------- merged final projections (scalar + vector in one launch) --------
__global__ void __launch_bounds__(256) k_projm() {
    __shared__ __align__(16) float As[32 * 68];
    __shared__ __align__(16) float Ws[32 * 68];
    int tid = threadIdx.x;
    int b = blockIdx.x;
    const float* A; const float* W; float* C;
    int aRow, K, NC, cRow, cCol, m0;
    if (b < 128) {
        A = g_agg; aRow = 1280; K = 512; NC = 64;
        W = g_Wcs; C = g_m; cRow = 160; cCol = 1;
        m0 = b * 64;
    } else {
        int c = (b - 128) / 128, mt = (b - 128) % 128;
        A = g_agg + 512 + c * 256; aRow = 1280; K = 256; NC = 32;
        W = g_Wcv; C = g_m + 64 + c; cRow = 160; cCol = 3;
        m0 = mt * 64;
    }
    float acc[4][4] = {};
    int ty = tid >> 4, tx = tid & 15;

    for (int k0 = 0; k0 < K; k0 += 32) {
#pragma unroll
        for (int r = 0; r < 8; r++) {
            int l = tid + r * 256;
            int kk = l & 31, mm = l >> 5;
            As[kk * 68 + mm] = A[(size_t)(m0 + mm) * aRow + (k0 + kk)];
        }
#pragma unroll
        for (int r = 0; r < 8; r++) {
            int l = tid + r * 256;
            int kk = l >> 6, jj = l & 63;
            Ws[kk * 68 + jj] = (jj < NC) ? W[(size_t)(k0 + kk) * NC + jj] : 0.f;
        }
        __syncthreads();
#pragma unroll
        for (int k = 0; k < 32; k++) {
            float4 a4 = *(const float4*)&As[k * 68 + ty * 4];
            float4 b4 = *(const float4*)&Ws[k * 68 + tx * 4];
            float av[4] = {a4.x, a4.y, a4.z, a4.w};
            float bv[4] = {b4.x, b4.y, b4.z, b4.w};
#pragma unroll
            for (int i = 0; i < 4; i++)
#pragma unroll
                for (int j = 0; j < 4; j++)
                    acc[i][j] += av[i] * bv[j];
        }
        __syncthreads();
    }
#pragma unroll
    for (int i = 0; i < 4; i++) {
        int m = m0 + ty * 4 + i;
#pragma unroll
        for (int j = 0; j < 4; j++) {
            int col = tx * 4 + j;
            if (col < NC)
                C[(size_t)m * cRow + col * cCol] = acc[i][j];
        }
    }
}

// ---------------- CSR scan -----------------------------------------------------------
__global__ void __launch_bounds__(1024) k_scan() {
    __shared__ int wsum[32];
    int tid = threadIdx.x;
    int base = tid * 8;
    int loc[8]; int tot = 0;
#pragma unroll
    for (int i = 0; i < 8; i++) { loc[i] = tot; tot += g_cnt[base + i]; }
    int lane = tid & 31, w = tid >> 5;
    int incl = tot;
#pragma unroll
    for (int o = 1; o < 32; o <<= 1) {
        int y = __shfl_up_sync(0xffffffffu, incl, o);
        if (lane >= o) incl += y;
    }
    if (lane == 31) wsum[w] = incl;
    int excl = incl - tot;
    __syncthreads();
    if (w == 0) {
        int t = wsum[lane];
        int i2 = t;
#pragma unroll
        for (int o = 1; o < 32; o <<= 1) {
            int y = __shfl_up_sync(0xffffffffu, i2, o);
            if (lane >= o) i2 += y;
        }
        wsum[lane] = i2 - t;
    }
    __syncthreads();
    int off = wsum[w] + excl;
#pragma unroll
    for (int i = 0; i < 8; i++) {
        int o2 = off + loc[i];
        g_offs[base + i] = o2;
        g_cursor[base + i] = o2;
    }
    if (tid == 1023) g_offs[NN] = NE;
}

// ---------------- edgeprep + qkself + scatter merged ---------------------------------
__global__ void __launch_bounds__(256) k_edge_qk(const float* __restrict__ rbf,
                                                 const float* __restrict__ rsh,
                                                 const int* __restrict__ ei,
                                                 const float* __restrict__ Wrbf,
                                                 const float* __restrict__ x) {
    int b = blockIdx.x, tid = threadIdx.x;
    if (b < 1024) {                       // edgeprep: 64 edges per block
        __shared__ float sW[1024];
        for (int l = tid; l < 1024; l += 256) sW[l] = Wrbf[l];
        __syncthreads();
        int wid = tid >> 5, lane = tid & 31;
        int d = lane;
#pragma unroll
        for (int it = 0; it < 8; it++) {
            int e = b * 64 + it * 8 + wid;
            int src = ei[e], dst = ei[NE + e];
            float ps = g_S[(size_t)src * 1088 + 1024 + d] + g_S[(size_t)dst * 1088 + 1056 + d];
            float pv[3];
#pragma unroll
            for (int c = 0; c < 3; c++)
                pv[c] = g_V[c * VPLANE + (size_t)src * 576 + 512 + d]
                      + g_V[c * VPLANE + (size_t)dst * 576 + 544 + d];
            float rval = (lane < 16) ? rbf[e * 16 + lane] : 0.f;
            float scal_s = 0.f, scal_v = 0.f;
#pragma unroll
            for (int bq = 0; bq < 16; bq++) {
                float rb = __shfl_sync(0xffffffffu, rval, bq);
                scal_s += rb * sW[bq * 64 + d];
                scal_v += rb * sW[bq * 64 + 32 + d];
            }
            float rs = rsh[e * 128 + d];
            float sph_s = rs * scal_s * ps;
            float sv[3];
#pragma unroll
            for (int c = 0; c < 3; c++)
                sv[c] = rsh[e * 128 + 32 + d * 3 + c] * scal_v * pv[c];
            float* f = g_feat + (size_t)e * 160;
            f[d]      = sph_s * sph_s;
            f[32 + d] = (sv[0] * sv[0] + sv[1] * sv[1] + sv[2] * sv[2]) * INV_SQRT3;
#pragma unroll
            for (int c = 0; c < 3; c++)
                f[64 + c * 32 + d] = sph_s * sv[c];
        }
    } else if (b < 2048) {                // qkself: warp per node
        __shared__ float s_q[8][160];
        int wid = tid >> 5, lane = tid & 31;
        int n = (b - 1024) * 8 + wid;
        const float4* xs = (const float4*)(x + (size_t)n * 160);
        ((float4*)s_q[wid])[lane] = xs[lane];
        if (lane < 8) ((float4*)s_q[wid])[32 + lane] = xs[32 + lane];
        __syncwarp();
        const float* xr = s_q[wid];
        const float* Sb = g_S + (size_t)n * 1088 + 512;
#pragma unroll
        for (int h = 0; h < 8; h++) {
            float a = Sb[h * 64 + lane] * xr[lane]
                    + Sb[h * 64 + 32 + lane] * xr[32 + lane];
#pragma unroll
            for (int c = 0; c < 3; c++)
                a += g_V[c * VPLANE + (size_t)n * 576 + 256 + h * 32 + lane]
                     * xr[64 + lane * 3 + c];
#pragma unroll
            for (int o = 16; o; o >>= 1) a += __shfl_xor_sync(0xffffffffu, a, o);
            if (lane == 0) g_QKself[n * 8 + h] = a;
        }
    } else {                              // scatter: 256 blocks
        int e = (b - 2048) * 256 + tid;
        int pos = atomicAdd(&g_cursor[ei[NE + e]], 1);
        g_elist[pos] = e;
    }
}

// ---------------- fused attention + aggregation: warp/node, dbl-buffer + prefetch -----
__global__ void __launch_bounds__(256) k_attn_agg2(const float* __restrict__ x,
                                                   const int* __restrict__ ei) {
    __shared__ __align__(16) float s_x[8][2][160];
    __shared__ float s_lg[8][512];
    const unsigned F = 0xffffffffu;
    int tid = threadIdx.x;
    int wid = tid >> 5, lane = tid & 31;
    int n = blockIdx.x * 8 + wid;
    int h = lane >> 2, p = lane & 3;

    int s0 = g_offs[n], deg = g_offs[n + 1] - s0;
    float* lg = (deg <= 64) ? &s_lg[wid][0] : (g_logit + (size_t)s0 * 8);

    int e0 = 0, e1 = 0, src0 = 0, src1 = 0;
    if (lane < deg) e0 = g_elist[s0 + lane];
    if (lane + 32 < deg) e1 = g_elist[s0 + 32 + lane];
    if (lane < deg) src0 = ei[e0];
    if (lane + 32 < deg) src1 = ei[e1];

    float mymax = -FLT_MAX;
    {
        float tkf[40];
#pragma unroll
        for (int tt = 0; tt < 40; tt++) {
            int t = p * 40 + tt;
            if (t < 64)
                tkf[tt] = g_S[(size_t)n * 1088 + h * 64 + t];
            else {
                int j = t - 64;
                tkf[tt] = g_V[(j % 3) * VPLANE + (size_t)n * 576 + h * 32 + (j / 3)];
            }
        }
        u64 tk2[20];
#pragma unroll
        for (int i = 0; i < 20; i++) tk2[i] = pk2(tkf[2 * i], tkf[2 * i + 1]);

        // prime buffer 0 with edge 0's x
        if (deg > 0) {
            int src = __shfl_sync(F, src0, 0);
            const float4* xs = (const float4*)(x + (size_t)src * 160);
            ((float4*)s_x[wid][0])[lane] = xs[lane];
            if (lane < 8) ((float4*)s_x[wid][0])[32 + lane] = xs[32 + lane];
        }
        __syncwarp();

        for (int i = 0; i < deg; i++) {
            int src;
            if (i < 64) src = __shfl_sync(F, (i < 32) ? src0 : src1, i & 31);
            else {
                int ss = 0;
                if (lane == 0) ss = ei[g_elist[s0 + i]];
                src = __shfl_sync(F, ss, 0);
            }
            // issue next edge's loads before computing current
            float4 nf0, nf1;
            int havenext = (i + 1 < deg);
            if (havenext) {
                int nsrc;
                int j = i + 1;
                if (j < 64) nsrc = __shfl_sync(F, (j < 32) ? src0 : src1, j & 31);
                else {
                    int ss = 0;
                    if (lane == 0) ss = ei[g_elist[s0 + j]];
                    nsrc = __shfl_sync(F, ss, 0);
                }
                const float4* nxs = (const float4*)(x + (size_t)nsrc * 160);
                nf0 = nxs[lane];
                if (lane < 8) nf1 = nxs[32 + lane];
            }
            // compute current from buffer i&1
            const u64* xr2 = (const u64*)(s_x[wid][i & 1] + p * 40);
            u64 ac0 = 0, ac1 = 0, ac2 = 0, ac3 = 0;
#pragma unroll
            for (int q = 0; q < 20; q += 4) {
                fma2(ac0, tk2[q + 0], xr2[q + 0]);
                fma2(ac1, tk2[q + 1], xr2[q + 1]);
                fma2(ac2, tk2[q + 2], xr2[q + 2]);
                fma2(ac3, tk2[q + 3], xr2[q + 3]);
            }
            float2 v0 = *(float2*)&ac0, v1 = *(float2*)&ac1;
            float2 v2 = *(float2*)&ac2, v3 = *(float2*)&ac3;
            float a = ((v0.x + v0.y) + (v1.x + v1.y)) + ((v2.x + v2.y) + (v3.x + v3.y));
            a += __shfl_xor_sync(F, a, 1);
            a += __shfl_xor_sync(F, a, 2);
            if (p == 0) {
                a += g_QKself[src * 8 + h];
                lg[i * 8 + h] = a;
                mymax = fmaxf(mymax, a);
            }
            // store prefetched x into the other buffer
            if (havenext) {
                ((float4*)s_x[wid][(i + 1) & 1])[lane] = nf0;
                if (lane < 8) ((float4*)s_x[wid][(i + 1) & 1])[32 + lane] = nf1;
            }
            __syncwarp();
        }
    }

    if (p == 0 && deg > 0) {
        float den = 0.f;
        for (int i = 0; i < deg; i++) {
            float ex = expf(lg[i * 8 + h] - mymax);
            lg[i * 8 + h] = ex;
            den += ex;
        }
        float inv = 1.f / den;
        for (int i = 0; i < deg; i++) lg[i * 8 + h] *= inv;
    }
    __syncwarp();

    u64 accS[8] = {}, accV[8] = {};
    float accW[8] = {};

    // pass 2 with register prefetch of next edge's feat
    float f0, f1, fv0, fv1, fv2;
    if (deg > 0) {
        int e = __shfl_sync(F, e0, 0);
        const float* fr = g_feat + (size_t)e * 160;
        f0 = fr[lane]; f1 = fr[32 + lane];
        fv0 = fr[64 + lane]; fv1 = fr[96 + lane]; fv2 = fr[128 + lane];
    }
    for (int i = 0; i < deg; i++) {
        float nf0v, nf1v, nv0, nv1, nv2;
        int havenext = (i + 1 < deg);
        if (havenext) {
            int j = i + 1, e;
            if (j < 64) e = __shfl_sync(F, (j < 32) ? e0 : e1, j & 31);
            else {
                int ee = 0;
                if (lane == 0) ee = g_elist[s0 + j];
                e = __shfl_sync(F, ee, 0);
            }
            const float* fr = g_feat + (size_t)e * 160;
            nf0v = fr[lane]; nf1v = fr[32 + lane];
            nv0 = fr[64 + lane]; nv1 = fr[96 + lane]; nv2 = fr[128 + lane];
        }
        u64 fS = pk2(f0, f1);
        u64 fV = pk2(fv0, fv1);
        const float* ar = lg + i * 8;
#pragma unroll
        for (int hh = 0; hh < 8; hh++) {
            float at = ar[hh];
            u64 at2 = dupf(at);
            fma2(accS[hh], fS, at2);
            fma2(accV[hh], fV, at2);
            accW[hh] += at * fv2;
        }
        if (havenext) { f0 = nf0v; f1 = nf1v; fv0 = nv0; fv1 = nv1; fv2 = nv2; }
    }
    float* ao = g_agg + (size_t)n * 1280;
#pragma unroll
    for (int hh = 0; hh < 8; hh++) {
        float2 s = *(float2*)&accS[hh];
        ao[(2 * hh) * 32 + lane]      = s.x;
        ao[(2 * hh + 1) * 32 + lane]  = s.y;
        float2 v = *(float2*)&accV[hh];
        ao[(16 + hh) * 32 + lane]     = v.x;
        ao[(24 + hh) * 32 + lane]     = v.y;
        ao[(32 + hh) * 32 + lane]     = accW[hh];
    }
}

// ---------------- NormGate + output --------------------------------------------------
__global__ void __launch_bounds__(256) k_normgate(const float* __restrict__ ln_g,
                                                  const float* __restrict__ ln_b,
                                                  const float* __restrict__ W1,
                                                  const float* __restrict__ b1,
                                                  const float* __restrict__ W2,
                                                  const float* __restrict__ b2,
                                                  float* __restrict__ out) {
    __shared__ float sW1[96 * 96];
    __shared__ float sX[8][96];
    __shared__ float sH[8][96];
    int tid = threadIdx.x;
    int w = tid >> 5, lane = tid & 31;
    for (int i = tid; i < 9216; i += 256) sW1[i] = W1[i];
    __syncthreads();

    for (int sub = 0; sub < 4; sub++) {
        int n = blockIdx.x * 32 + w * 4 + sub;
        const float* mrow = g_m + (size_t)n * 160;
        float ms0 = mrow[lane], ms1 = mrow[32 + lane];
        float v0 = mrow[64 + lane * 3 + 0];
        float v1 = mrow[64 + lane * 3 + 1];
        float v2 = mrow[64 + lane * 3 + 2];
        float n00 = fabsf(ms0), n01 = fabsf(ms1);
        float n02 = sqrtf(v0 * v0 + v1 * v1 + v2 * v2);
        float s = n00 + n01 + n02;
        float s2 = n00 * n00 + n01 * n01 + n02 * n02;
#pragma unroll
        for (int o = 16; o; o >>= 1) {
            s  += __shfl_xor_sync(0xffffffffu, s, o);
            s2 += __shfl_xor_sync(0xffffffffu, s2, o);
        }
        float mu = s * (1.f / 96.f);
        float var = s2 * (1.f / 96.f) - mu * mu;
        float rstd = rsqrtf(var + 1e-5f);
        sX[w][lane]      = (n00 - mu) * rstd * ln_g[lane]      + ln_b[lane];
        sX[w][lane + 32] = (n01 - mu) * rstd * ln_g[lane + 32] + ln_b[lane + 32];
        sX[w][lane + 64] = (n02 - mu) * rstd * ln_g[lane + 64] + ln_b[lane + 64];
        __syncwarp();
#pragma unroll
        for (int t = 0; t < 3; t++) {
            int jp = lane + t * 32;
            float hs = b1[jp];
            for (int j = 0; j < 96; j++) hs += sX[w][j] * sW1[j * 96 + jp];
            sH[w][jp] = hs / (1.f + expf(-hs));
        }
        __syncwarp();
        float n0arr[3] = {n00, n01, n02};
        float f[3];
#pragma unroll
        for (int t = 0; t < 3; t++) {
            int jp = lane + t * 32;
            float gs = b2[jp];
            for (int j = 0; j < 96; j++) gs += sH[w][j] * W2[j * 96 + jp];
            float gg = gs / (1.f + expf(-gs));
            f[t] = gg / (n0arr[t] + 1e-6f);
        }
        out[n * 160 + lane]      = ms0 * f[0];
        out[n * 160 + 32 + lane] = ms1 * f[1];
        out[n * 160 + 64 + lane * 3 + 0] = v0 * f[2];
        out[n * 160 + 64 + lane * 3 + 1] = v1 * f[2];
        out[n * 160 + 64 + lane * 3 + 2] = v2 * f[2];
        __syncwarp();
    }
}

// ---------------- launch ----------------------------------------------------------------
extern "C" void kernel_launch(void* const* d_in, const int* in_sizes, int n_in,
                              void* d_out, int out_size) {
    const float* pseduo_x = (const float*)d_in[0];
    const float* rbf   = (const float*)d_in[1];
    const float* rsh   = (const float*)d_in[2];
    const int*   ei    = (const int*)d_in[3];
    const float* Wq_s  = (const float*)d_in[4];
    const float* Wq_v  = (const float*)d_in[5];
    const float* Wk_s  = (const float*)d_in[6];
    const float* Wk_v  = (const float*)d_in[7];
    const float* Wp_s  = (const float*)d_in[8];
    const float* Wp_v  = (const float*)d_in[9];
    const float* Wrbf  = (const float*)d_in[10];
    const float* Wv_s  = (const float*)d_in[11];
    const float* Wv_v  = (const float*)d_in[12];
    const float* Wm_s  = (const float*)d_in[13];
    const float* Wm_v  = (const float*)d_in[14];
    const float* ln_g  = (const float*)d_in[15];
    const float* ln_b  = (const float*)d_in[16];
    const float* W1    = (const float*)d_in[17];
    const float* b1    = (const float*)d_in[18];
    const float* W2    = (const float*)d_in[19];
    const float* b2    = (const float*)d_in[20];
    float* out = (float*)d_out;

    void* p;
    cudaGetSymbolAddress(&p, g_xT);  float* XT  = (float*)p;
    cudaGetSymbolAddress(&p, g_S);   float* S   = (float*)p;
    cudaGetSymbolAddress(&p, g_V);   float* V   = (float*)p;
    cudaGetSymbolAddress(&p, g_Wts); float* Wts = (float*)p;
    cudaGetSymbolAddress(&p, g_Wtv); float* Wtv = (float*)p;

    k_pack2<<<50, 256>>>(Wq_s, Wq_v, Wk_s, Wk_v, Wp_s, Wp_v, Wv_s, Wv_v, Wm_s, Wm_v);
    k_xT<<<dim3(256, 6), dim3(32, 8)>>>(pseduo_x, XT, ei);

    k_gemmT<64><<<dim3(17, 64, 1), 256>>>(XT, 0, 1, Wts, 1088, S, 1088, 0);
    k_gemmT<32><<<dim3(9, 64, 3), 256>>>(XT, 64, 3, Wtv, 576, V, 576, VPLANE);

    k_scan<<<1, 1024>>>();

    // edgeprep (1024) + qkself (1024) + scatter (256) in one launch
    k_edge_qk<<<2304, 256>>>(rbf, rsh, ei, Wrbf, pseduo_x);

    k_attn_agg2<<<1024, 256>>>(pseduo_x, ei);

    k_projm<<<512, 256>>>();
    k_normgate<<<256, 256>>>(ln_g, ln_b, W1, b1, W2, b2, out);
}

// round 11
// speedup vs baseline: 1.7155x; 1.0129x over previous
#include <cuda_runtime.h>
#include <math.h>
#include <float.h>

#define NN 8192
#define NE 65536
#define VPLANE ((size_t)NN * 576)

#define INV_SQRT128 0.08838834764831843f
#define INV_SQRT512 0.04419417382415922f
#define INV_SQRT3   0.5773502691896258f
#define INV_SQRT160 0.07905694150420949f
#define INV_SQRT32  0.17677669529663687f

#define SC_S   (0.125f * INV_SQRT128 * INV_SQRT160)
#define SC_V   (INV_SQRT32 * 0.125f * INV_SQRT160)
#define SC_P_S (INV_SQRT128)
#define SC_P_V (0.125f)
#define SC_C_S (0.125f * INV_SQRT512)
#define SC_C_V (0.125f * 0.0625f)

typedef unsigned long long u64;

__device__ __forceinline__ void fma2(u64& d, u64 a, u64 b) {
    asm("fma.rn.f32x2 %0, %1, %2, %0;" : "+l"(d) : "l"(a), "l"(b));
}
__device__ __forceinline__ u64 dupf(float x) {
    u64 r; asm("mov.b64 %0, {%1, %1};" : "=l"(r) : "r"(__float_as_uint(x))); return r;
}
__device__ __forceinline__ u64 pk2(float lo, float hi) {
    u64 r; asm("mov.b64 %0, {%1, %2};" : "=l"(r) : "r"(__float_as_uint(lo)), "r"(__float_as_uint(hi)));
    return r;
}

// ---------------- scratch ------------------------------------------------------
__device__ float g_xT[160 * NN];
__device__ float g_S[NN * 1088];
__device__ float g_V[3 * NN * 576];
__device__ float g_QKself[NN * 8];
__device__ float g_feat[NE * 160];
__device__ float g_logit[NE * 8];
__device__ float g_agg[NN * 1280];
__device__ float g_m[NN * 160];
__device__ int   g_cnt[NN];
__device__ int   g_offs[NN + 1];
__device__ int   g_cursor[NN];
__device__ int   g_elist[NE];
__device__ float g_Wts[64 * 1088];
__device__ float g_Wtv[32 * 576];
__device__ float g_Wcs[512 * 64];
__device__ float g_Wcv[256 * 32];

// ---------------- weight packing / grams (smem staged) --------------------------
__global__ void __launch_bounds__(256) k_pack2(
        const float* __restrict__ Wq_s, const float* __restrict__ Wq_v,
        const float* __restrict__ Wk_s, const float* __restrict__ Wk_v,
        const float* __restrict__ Wp_s, const float* __restrict__ Wp_v,
        const float* __restrict__ Wv_s, const float* __restrict__ Wv_v,
        const float* __restrict__ Wm_s, const float* __restrict__ Wm_v) {
    __shared__ float sm[8192];
    int b = blockIdx.x, tid = threadIdx.x;
    if (b < 16) {
        int h = b & 7, self = b >> 3;
        float* Q = sm; float* Kx = sm + 4096;
        for (int i = tid; i < 4096; i += 256) {
            int a = i >> 6, j = i & 63;
            Q[i]  = Wq_s[a * 512 + h * 64 + j];
            int kr = self ? a : (64 + a);
            Kx[i] = Wk_s[kr * 512 + h * 64 + j];
        }
        __syncthreads();
        for (int i = tid; i < 4096; i += 256) {
            int a = i & 63, bb = i >> 6;
            float s = 0.f;
            for (int j = 0; j < 64; j++) s += Q[a * 64 + j] * Kx[bb * 64 + j];
            g_Wts[bb * 1088 + self * 512 + h * 64 + a] = s * SC_S;
        }
    } else if (b < 32) {
        int h = (b - 16) & 7, self = (b - 16) >> 3;
        float* Q = sm; float* Kx = sm + 1024;
        for (int i = tid; i < 1024; i += 256) {
            int a = i >> 5, j = i & 31;
            Q[i]  = Wq_v[a * 256 + h * 32 + j];
            int kr = self ? a : (32 + a);
            Kx[i] = Wk_v[kr * 256 + h * 32 + j];
        }
        __syncthreads();
        for (int i = tid; i < 1024; i += 256) {
            int a = i & 31, bb = i >> 5;
            float s = 0.f;
            for (int j = 0; j < 32; j++) s += Q[a * 32 + j] * Kx[bb * 32 + j];
            g_Wtv[bb * 576 + self * 256 + h * 32 + a] = s * SC_V;
        }
    } else if (b < 40) {
        int h = b - 32;
        float* V = sm; float* M = sm + 4096;
        for (int i = tid; i < 4096; i += 256) {
            int k = i >> 6, j = i & 63;
            V[i] = Wv_s[k * 512 + h * 64 + j];
            M[i] = Wm_s[(h * 64 + k) * 64 + j];
        }
        __syncthreads();
        for (int i = tid; i < 4096; i += 256) {
            int d = i & 63, k = i >> 6;
            float s = 0.f;
            for (int j = 0; j < 64; j++) s += V[k * 64 + j] * M[j * 64 + d];
            g_Wcs[(h * 64 + k) * 64 + d] = s * SC_C_S;
        }
    } else if (b < 48) {
        int h = b - 40;
        float* V = sm; float* M = sm + 1024;
        for (int i = tid; i < 1024; i += 256) {
            int k = i >> 5, j = i & 31;
            V[i] = Wv_v[k * 256 + h * 32 + j] + Wv_v[(32 + k) * 256 + h * 32 + j];
            M[i] = Wm_v[(h * 32 + k) * 32 + j];
        }
        __syncthreads();
        for (int i = tid; i < 1024; i += 256) {
            int d = i & 31, k = i >> 5;
            float s = 0.f;
            for (int j = 0; j < 32; j++) s += V[k * 32 + j] * M[j * 32 + d];
            g_Wcv[(h * 32 + k) * 32 + d] = s * SC_C_V;
        }
    } else if (b == 48) {
        for (int i = tid; i < 4096; i += 256) {
            int bb = i >> 6, c = i & 63;
            float w = (c < 32) ? Wp_s[bb * 32 + c] : Wp_s[(64 + bb) * 32 + (c - 32)];
            g_Wts[bb * 1088 + 1024 + c] = w * SC_P_S;
        }
        for (int i = tid; i < 2048; i += 256) {
            int bb = i >> 6, c = i & 63;
            float w = (c < 32) ? Wp_v[bb * 32 + c] : Wp_v[(32 + bb) * 32 + (c - 32)];
            g_Wtv[bb * 576 + 512 + c] = w * SC_P_V;
        }
    } else {
        for (int i = tid; i < NN; i += 256) g_cnt[i] = 0;
    }
}

// ---------------- transpose x -> xT (+ histogram row) ------------------------------
__global__ void k_xT(const float* __restrict__ x, float* __restrict__ xT,
                     const int* __restrict__ ei) {
    int tx = threadIdx.x, ty = threadIdx.y;
    if (blockIdx.y == 5) {
        int e = blockIdx.x * 256 + ty * 32 + tx;
        atomicAdd(&g_cnt[ei[NE + e]], 1);
        return;
    }
    __shared__ float t[32][33];
    int n0 = blockIdx.x * 32, t0 = blockIdx.y * 32;
#pragma unroll
    for (int i = 0; i < 32; i += 8)
        t[ty + i][tx] = x[(size_t)(n0 + ty + i) * 160 + t0 + tx];
    __syncthreads();
#pragma unroll
    for (int i = 0; i < 32; i += 8)
        xT[(size_t)(t0 + ty + i) * 8192 + n0 + tx] = t[tx][ty + i];
}

// ---------------- merged node-projection GEMM (both K=64 and K=32x3 paths) ---------
template<int K>
__device__ __forceinline__ void gemmT_body(
        const float* __restrict__ AT, int baseRow, int rowStride,
        const float* __restrict__ W, int N,
        float* __restrict__ C, int cRow, size_t planeStride,
        int bx, int by, int z, float* As, float* Ws, int tid) {
    int n0 = bx * 64, m0 = by * 128;
#pragma unroll
    for (int r = 0; r < (K * 128) / 1024; r++) {
        int idx = tid + r * 256;
        int k = idx >> 5, mp = idx & 31;
        *(float4*)&As[k * 128 + mp * 4] =
            *(const float4*)&AT[(size_t)(baseRow + z + k * rowStride) * 8192 + m0 + mp * 4];
    }
#pragma unroll
    for (int r = 0; r < (K * 64) / 1024; r++) {
        int idx = tid + r * 256;
        int k = idx >> 4, j = idx & 15;
        *(float4*)&Ws[k * 64 + j * 4] = *(const float4*)&W[(size_t)k * N + n0 + j * 4];
    }
    __syncthreads();
    int ty = tid >> 4, tx = tid & 15;
    u64 acc[4][4] = {};
#pragma unroll 8
    for (int k = 0; k < K; k++) {
        ulonglong2 a01 = *(const ulonglong2*)&As[k * 128 + ty * 8];
        ulonglong2 a23 = *(const ulonglong2*)&As[k * 128 + ty * 8 + 4];
        float4 b4 = *(const float4*)&Ws[k * 64 + tx * 4];
        u64 bb0 = dupf(b4.x), bb1 = dupf(b4.y), bb2 = dupf(b4.z), bb3 = dupf(b4.w);
        u64 ap[4] = {a01.x, a01.y, a23.x, a23.y};
#pragma unroll
        for (int q = 0; q < 4; q++) {
            fma2(acc[q][0], ap[q], bb0);
            fma2(acc[q][1], ap[q], bb1);
            fma2(acc[q][2], ap[q], bb2);
            fma2(acc[q][3], ap[q], bb3);
        }
    }
    float* Cb = C + (size_t)z * planeStride;
#pragma unroll
    for (int q = 0; q < 4; q++) {
        float2 c0 = *(float2*)&acc[q][0];
        float2 c1 = *(float2*)&acc[q][1];
        float2 c2 = *(float2*)&acc[q][2];
        float2 c3 = *(float2*)&acc[q][3];
        int r0 = m0 + ty * 8 + 2 * q;
        *(float4*)&Cb[(size_t)r0 * cRow + n0 + tx * 4]       = make_float4(c0.x, c1.x, c2.x, c3.x);
        *(float4*)&Cb[(size_t)(r0 + 1) * cRow + n0 + tx * 4] = make_float4(c0.y, c1.y, c2.y, c3.y);
    }
}

__global__ void __launch_bounds__(256) k_gemmT_m(const float* __restrict__ AT) {
    __shared__ __align__(16) float As[64 * 128];
    __shared__ __align__(16) float Ws[64 * 64];
    int b = blockIdx.x, tid = threadIdx.x;
    if (b < 1088) {
        gemmT_body<64>(AT, 0, 1, g_Wts, 1088, g_S, 1088, 0,
                       b % 17, b / 17, 0, As, Ws, tid);
    } else {
        int i = b - 1088;
        int z = i / 576, r = i % 576;
        gemmT_body<32>(AT, 64, 3, g_Wtv, 576, g_V, 576, VPLANE,
                       r % 9, r / 9, z, As, Ws, tid);
    }
}

// ---------------- merged final projections, f32x2 (column-paired) -------------------
__global__ void __launch_bounds__(256) k_projm() {
    __shared__ __align__(16) float As[32 * 68];
    __shared__ __align__(16) float Ws[32 * 68];
    int tid = threadIdx.x;
    int b = blockIdx.x;
    const float* A; const float* W; float* C;
    int aRow, K, NC, cRow, cCol, m0;
    if (b < 128) {
        A = g_agg; aRow = 1280; K = 512; NC = 64;
        W = g_Wcs; C = g_m; cRow = 160; cCol = 1;
        m0 = b * 64;
    } else {
        int c = (b - 128) / 128, mt = (b - 128) % 128;
        A = g_agg + 512 + c * 256; aRow = 1280; K = 256; NC = 32;
        W = g_Wcv; C = g_m + 64 + c; cRow = 160; cCol = 3;
        m0 = mt * 64;
    }
    u64 acc[4][2] = {};     // rows i=0..3, col-pairs (tx*4+0,1) and (tx*4+2,3)
    int ty = tid >> 4, tx = tid & 15;

    for (int k0 = 0; k0 < K; k0 += 32) {
#pragma unroll
        for (int r = 0; r < 8; r++) {
            int l = tid + r * 256;
            int kk = l & 31, mm = l >> 5;
            As[kk * 68 + mm] = A[(size_t)(m0 + mm) * aRow + (k0 + kk)];
        }
#pragma unroll
        for (int r = 0; r < 8; r++) {
            int l = tid + r * 256;
            int kk = l >> 6, jj = l & 63;
            Ws[kk * 68 + jj] = (jj < NC) ? W[(size_t)(k0 + kk) * NC + jj] : 0.f;
        }
        __syncthreads();
#pragma unroll 8
        for (int k = 0; k < 32; k++) {
            float4 a4 = *(const float4*)&As[k * 68 + ty * 4];
            ulonglong2 bp = *(const ulonglong2*)&Ws[k * 68 + tx * 4];
            u64 aa0 = dupf(a4.x), aa1 = dupf(a4.y), aa2 = dupf(a4.z), aa3 = dupf(a4.w);
            fma2(acc[0][0], aa0, bp.x); fma2(acc[0][1], aa0, bp.y);
            fma2(acc[1][0], aa1, bp.x); fma2(acc[1][1], aa1, bp.y);
            fma2(acc[2][0], aa2, bp.x); fma2(acc[2][1], aa2, bp.y);
            fma2(acc[3][0], aa3, bp.x); fma2(acc[3][1], aa3, bp.y);
        }
        __syncthreads();
    }
#pragma unroll
    for (int i = 0; i < 4; i++) {
        int m = m0 + ty * 4 + i;
        float2 c01 = *(float2*)&acc[i][0];
        float2 c23 = *(float2*)&acc[i][1];
        int col = tx * 4;
        if (cCol == 1) {
            *(float4*)&C[(size_t)m * cRow + col] = make_float4(c01.x, c01.y, c23.x, c23.y);
        } else {
            if (col < NC) {
                C[(size_t)m * cRow + (col + 0) * 3] = c01.x;
                C[(size_t)m * cRow + (col + 1) * 3] = c01.y;
                C[(size_t)m * cRow + (col + 2) * 3] = c23.x;
                C[(size_t)m * cRow + (col + 3) * 3] = c23.y;
            }
        }
    }
}

// ---------------- CSR scan -----------------------------------------------------------
__global__ void __launch_bounds__(1024) k_scan() {
    __shared__ int wsum[32];
    int tid = threadIdx.x;
    int base = tid * 8;
    int loc[8]; int tot = 0;
#pragma unroll
    for (int i = 0; i < 8; i++) { loc[i] = tot; tot += g_cnt[base + i]; }
    int lane = tid & 31, w = tid >> 5;
    int incl = tot;
#pragma unroll
    for (int o = 1; o < 32; o <<= 1) {
        int y = __shfl_up_sync(0xffffffffu, incl, o);
        if (lane >= o) incl += y;
    }
    if (lane == 31) wsum[w] = incl;
    int excl = incl - tot;
    __syncthreads();
    if (w == 0) {
        int t = wsum[lane];
        int i2 = t;
#pragma unroll
        for (int o = 1; o < 32; o <<= 1) {
            int y = __shfl_up_sync(0xffffffffu, i2, o);
            if (lane >= o) i2 += y;
        }
        wsum[lane] = i2 - t;
    }
    __syncthreads();
    int off = wsum[w] + excl;
#pragma unroll
    for (int i = 0; i < 8; i++) {
        int o2 = off + loc[i];
        g_offs[base + i] = o2;
        g_cursor[base + i] = o2;
    }
    if (tid == 1023) g_offs[NN] = NE;
}

// ---------------- edgeprep + qkself + scatter merged ---------------------------------
__global__ void __launch_bounds__(256) k_edge_qk(const float* __restrict__ rbf,
                                                 const float* __restrict__ rsh,
                                                 const int* __restrict__ ei,
                                                 const float* __restrict__ Wrbf,
                                                 const float* __restrict__ x) {
    int b = blockIdx.x, tid = threadIdx.x;
    if (b < 1024) {
        __shared__ float sW[1024];
        for (int l = tid; l < 1024; l += 256) sW[l] = Wrbf[l];
        __syncthreads();
        int wid = tid >> 5, lane = tid & 31;
        int d = lane;
#pragma unroll
        for (int it = 0; it < 8; it++) {
            int e = b * 64 + it * 8 + wid;
            int src = ei[e], dst = ei[NE + e];
            float ps = g_S[(size_t)src * 1088 + 1024 + d] + g_S[(size_t)dst * 1088 + 1056 + d];
            float pv[3];
#pragma unroll
            for (int c = 0; c < 3; c++)
                pv[c] = g_V[c * VPLANE + (size_t)src * 576 + 512 + d]
                      + g_V[c * VPLANE + (size_t)dst * 576 + 544 + d];
            float rval = (lane < 16) ? rbf[e * 16 + lane] : 0.f;
            float scal_s = 0.f, scal_v = 0.f;
#pragma unroll
            for (int bq = 0; bq < 16; bq++) {
                float rb = __shfl_sync(0xffffffffu, rval, bq);
                scal_s += rb * sW[bq * 64 + d];
                scal_v += rb * sW[bq * 64 + 32 + d];
            }
            float rs = rsh[e * 128 + d];
            float sph_s = rs * scal_s * ps;
            float sv[3];
#pragma unroll
            for (int c = 0; c < 3; c++)
                sv[c] = rsh[e * 128 + 32 + d * 3 + c] * scal_v * pv[c];
            float* f = g_feat + (size_t)e * 160;
            f[d]      = sph_s * sph_s;
            f[32 + d] = (sv[0] * sv[0] + sv[1] * sv[1] + sv[2] * sv[2]) * INV_SQRT3;
#pragma unroll
            for (int c = 0; c < 3; c++)
                f[64 + c * 32 + d] = sph_s * sv[c];
        }
    } else if (b < 2048) {
        __shared__ float s_q[8][160];
        int wid = tid >> 5, lane = tid & 31;
        int n = (b - 1024) * 8 + wid;
        const float4* xs = (const float4*)(x + (size_t)n * 160);
        ((float4*)s_q[wid])[lane] = xs[lane];
        if (lane < 8) ((float4*)s_q[wid])[32 + lane] = xs[32 + lane];
        __syncwarp();
        const float* xr = s_q[wid];
        const float* Sb = g_S + (size_t)n * 1088 + 512;
#pragma unroll
        for (int h = 0; h < 8; h++) {
            float a = Sb[h * 64 + lane] * xr[lane]
                    + Sb[h * 64 + 32 + lane] * xr[32 + lane];
#pragma unroll
            for (int c = 0; c < 3; c++)
                a += g_V[c * VPLANE + (size_t)n * 576 + 256 + h * 32 + lane]
                     * xr[64 + lane * 3 + c];
#pragma unroll
            for (int o = 16; o; o >>= 1) a += __shfl_xor_sync(0xffffffffu, a, o);
            if (lane == 0) g_QKself[n * 8 + h] = a;
        }
    } else {
        int e = (b - 2048) * 256 + tid;
        int pos = atomicAdd(&g_cursor[ei[NE + e]], 1);
        g_elist[pos] = e;
    }
}

// ---------------- fused attention + aggregation: warp/node, dbl-buffer + prefetch -----
__global__ void __launch_bounds__(256) k_attn_agg2(const float* __restrict__ x,
                                                   const int* __restrict__ ei) {
    __shared__ __align__(16) float s_x[8][2][160];
    __shared__ float s_lg[8][512];
    const unsigned F = 0xffffffffu;
    int tid = threadIdx.x;
    int wid = tid >> 5, lane = tid & 31;
    int n = blockIdx.x * 8 + wid;
    int h = lane >> 2, p = lane & 3;

    int s0 = g_offs[n], deg = g_offs[n + 1] - s0;
    float* lg = (deg <= 64) ? &s_lg[wid][0] : (g_logit + (size_t)s0 * 8);

    int e0 = 0, e1 = 0, src0 = 0, src1 = 0;
    if (lane < deg) e0 = g_elist[s0 + lane];
    if (lane + 32 < deg) e1 = g_elist[s0 + 32 + lane];
    if (lane < deg) src0 = ei[e0];
    if (lane + 32 < deg) src1 = ei[e1];

    float mymax = -FLT_MAX;
    {
        float tkf[40];
#pragma unroll
        for (int tt = 0; tt < 40; tt++) {
            int t = p * 40 + tt;
            if (t < 64)
                tkf[tt] = g_S[(size_t)n * 1088 + h * 64 + t];
            else {
                int j = t - 64;
                tkf[tt] = g_V[(j % 3) * VPLANE + (size_t)n * 576 + h * 32 + (j / 3)];
            }
        }
        u64 tk2[20];
#pragma unroll
        for (int i = 0; i < 20; i++) tk2[i] = pk2(tkf[2 * i], tkf[2 * i + 1]);

        if (deg > 0) {
            int src = __shfl_sync(F, src0, 0);
            const float4* xs = (const float4*)(x + (size_t)src * 160);
            ((float4*)s_x[wid][0])[lane] = xs[lane];
            if (lane < 8) ((float4*)s_x[wid][0])[32 + lane] = xs[32 + lane];
        }
        __syncwarp();

        for (int i = 0; i < deg; i++) {
            int src;
            if (i < 64) src = __shfl_sync(F, (i < 32) ? src0 : src1, i & 31);
            else {
                int ss = 0;
                if (lane == 0) ss = ei[g_elist[s0 + i]];
                src = __shfl_sync(F, ss, 0);
            }
            float4 nf0, nf1;
            int havenext = (i + 1 < deg);
            if (havenext) {
                int nsrc;
                int j = i + 1;
                if (j < 64) nsrc = __shfl_sync(F, (j < 32) ? src0 : src1, j & 31);
                else {
                    int ss = 0;
                    if (lane == 0) ss = ei[g_elist[s0 + j]];
                    nsrc = __shfl_sync(F, ss, 0);
                }
                const float4* nxs = (const float4*)(x + (size_t)nsrc * 160);
                nf0 = nxs[lane];
                if (lane < 8) nf1 = nxs[32 + lane];
            }
            const u64* xr2 = (const u64*)(s_x[wid][i & 1] + p * 40);
            u64 ac0 = 0, ac1 = 0, ac2 = 0, ac3 = 0;
#pragma unroll
            for (int q = 0; q < 20; q += 4) {
                fma2(ac0, tk2[q + 0], xr2[q + 0]);
                fma2(ac1, tk2[q + 1], xr2[q + 1]);
                fma2(ac2, tk2[q + 2], xr2[q + 2]);
                fma2(ac3, tk2[q + 3], xr2[q + 3]);
            }
            float2 v0 = *(float2*)&ac0, v1 = *(float2*)&ac1;
            float2 v2 = *(float2*)&ac2, v3 = *(float2*)&ac3;
            float a = ((v0.x + v0.y) + (v1.x + v1.y)) + ((v2.x + v2.y) + (v3.x + v3.y));
            a += __shfl_xor_sync(F, a, 1);
            a += __shfl_xor_sync(F, a, 2);
            if (p == 0) {
                a += g_QKself[src * 8 + h];
                lg[i * 8 + h] = a;
                mymax = fmaxf(mymax, a);
            }
            if (havenext) {
                ((float4*)s_x[wid][(i + 1) & 1])[lane] = nf0;
                if (lane < 8) ((float4*)s_x[wid][(i + 1) & 1])[32 + lane] = nf1;
            }
            __syncwarp();
        }
    }

    if (p == 0 && deg > 0) {
        float den = 0.f;
        for (int i = 0; i < deg; i++) {
            float ex = expf(lg[i * 8 + h] - mymax);
            lg[i * 8 + h] = ex;
            den += ex;
        }
        float inv = 1.f / den;
        for (int i = 0; i < deg; i++) lg[i * 8 + h] *= inv;
    }
    __syncwarp();

    u64 accS[8] = {}, accV[8] = {};
    float accW[8] = {};

    float f0, f1, fv0, fv1, fv2;
    if (deg > 0) {
        int e = __shfl_sync(F, e0, 0);
        const float* fr = g_feat + (size_t)e * 160;
        f0 = fr[lane]; f1 = fr[32 + lane];
        fv0 = fr[64 + lane]; fv1 = fr[96 + lane]; fv2 = fr[128 + lane];
    }
    for (int i = 0; i < deg; i++) {
        float nf0v, nf1v, nv0, nv1, nv2;
        int havenext = (i + 1 < deg);
        if (havenext) {
            int j = i + 1, e;
            if (j < 64) e = __shfl_sync(F, (j < 32) ? e0 : e1, j & 31);
            else {
                int ee = 0;
                if (lane == 0) ee = g_elist[s0 + j];
                e = __shfl_sync(F, ee, 0);
            }
            const float* fr = g_feat + (size_t)e * 160;
            nf0v = fr[lane]; nf1v = fr[32 + lane];
            nv0 = fr[64 + lane]; nv1 = fr[96 + lane]; nv2 = fr[128 + lane];
        }
        u64 fS = pk2(f0, f1);
        u64 fV = pk2(fv0, fv1);
        const float* ar = lg + i * 8;
#pragma unroll
        for (int hh = 0; hh < 8; hh++) {
            float at = ar[hh];
            u64 at2 = dupf(at);
            fma2(accS[hh], fS, at2);
            fma2(accV[hh], fV, at2);
            accW[hh] += at * fv2;
        }
        if (havenext) { f0 = nf0v; f1 = nf1v; fv0 = nv0; fv1 = nv1; fv2 = nv2; }
    }
    float* ao = g_agg + (size_t)n * 1280;
#pragma unroll
    for (int hh = 0; hh < 8; hh++) {
        float2 s = *(float2*)&accS[hh];
        ao[(2 * hh) * 32 + lane]      = s.x;
        ao[(2 * hh + 1) * 32 + lane]  = s.y;
        float2 v = *(float2*)&accV[hh];
        ao[(16 + hh) * 32 + lane]     = v.x;
        ao[(24 + hh) * 32 + lane]     = v.y;
        ao[(32 + hh) * 32 + lane]     = accW[hh];
    }
}

// ---------------- NormGate + output --------------------------------------------------
__global__ void __launch_bounds__(256) k_normgate(const float* __restrict__ ln_g,
                                                  const float* __restrict__ ln_b,
                                                  const float* __restrict__ W1,
                                                  const float* __restrict__ b1,
                                                  const float* __restrict__ W2,
                                                  const float* __restrict__ b2,
                                                  float* __restrict__ out) {
    __shared__ float sW1[96 * 96];
    __shared__ float sX[8][96];
    __shared__ float sH[8][96];
    int tid = threadIdx.x;
    int w = tid >> 5, lane = tid & 31;
    for (int i = tid; i < 9216; i += 256) sW1[i] = W1[i];
    __syncthreads();

    for (int sub = 0; sub < 4; sub++) {
        int n = blockIdx.x * 32 + w * 4 + sub;
        const float* mrow = g_m + (size_t)n * 160;
        float ms0 = mrow[lane], ms1 = mrow[32 + lane];
        float v0 = mrow[64 + lane * 3 + 0];
        float v1 = mrow[64 + lane * 3 + 1];
        float v2 = mrow[64 + lane * 3 + 2];
        float n00 = fabsf(ms0), n01 = fabsf(ms1);
        float n02 = sqrtf(v0 * v0 + v1 * v1 + v2 * v2);
        float s = n00 + n01 + n02;
        float s2 = n00 * n00 + n01 * n01 + n02 * n02;
#pragma unroll
        for (int o = 16; o; o >>= 1) {
            s  += __shfl_xor_sync(0xffffffffu, s, o);
            s2 += __shfl_xor_sync(0xffffffffu, s2, o);
        }
        float mu = s * (1.f / 96.f);
        float var = s2 * (1.f / 96.f) - mu * mu;
        float rstd = rsqrtf(var + 1e-5f);
        sX[w][lane]      = (n00 - mu) * rstd * ln_g[lane]      + ln_b[lane];
        sX[w][lane + 32] = (n01 - mu) * rstd * ln_g[lane + 32] + ln_b[lane + 32];
        sX[w][lane + 64] = (n02 - mu) * rstd * ln_g[lane + 64] + ln_b[lane + 64];
        __syncwarp();
#pragma unroll
        for (int t = 0; t < 3; t++) {
            int jp = lane + t * 32;
            float hs = b1[jp];
            for (int j = 0; j < 96; j++) hs += sX[w][j] * sW1[j * 96 + jp];
            sH[w][jp] = hs / (1.f + expf(-hs));
        }
        __syncwarp();
        float n0arr[3] = {n00, n01, n02};
        float f[3];
#pragma unroll
        for (int t = 0; t < 3; t++) {
            int jp = lane + t * 32;
            float gs = b2[jp];
            for (int j = 0; j < 96; j++) gs += sH[w][j] * W2[j * 96 + jp];
            float gg = gs / (1.f + expf(-gs));
            f[t] = gg / (n0arr[t] + 1e-6f);
        }
        out[n * 160 + lane]      = ms0 * f[0];
        out[n * 160 + 32 + lane] = ms1 * f[1];
        out[n * 160 + 64 + lane * 3 + 0] = v0 * f[2];
        out[n * 160 + 64 + lane * 3 + 1] = v1 * f[2];
        out[n * 160 + 64 + lane * 3 + 2] = v2 * f[2];
        __syncwarp();
    }
}

// ---------------- launch ----------------------------------------------------------------
extern "C" void kernel_launch(void* const* d_in, const int* in_sizes, int n_in,
                              void* d_out, int out_size) {
    const float* pseduo_x = (const float*)d_in[0];
    const float* rbf   = (const float*)d_in[1];
    const float* rsh   = (const float*)d_in[2];
    const int*   ei    = (const int*)d_in[3];
    const float* Wq_s  = (const float*)d_in[4];
    const float* Wq_v  = (const float*)d_in[5];
    const float* Wk_s  = (const float*)d_in[6];
    const float* Wk_v  = (const float*)d_in[7];
    const float* Wp_s  = (const float*)d_in[8];
    const float* Wp_v  = (const float*)d_in[9];
    const float* Wrbf  = (const float*)d_in[10];
    const float* Wv_s  = (const float*)d_in[11];
    const float* Wv_v  = (const float*)d_in[12];
    const float* Wm_s  = (const float*)d_in[13];
    const float* Wm_v  = (const float*)d_in[14];
    const float* ln_g  = (const float*)d_in[15];
    const float* ln_b  = (const float*)d_in[16];
    const float* W1    = (const float*)d_in[17];
    const float* b1    = (const float*)d_in[18];
    const float* W2    = (const float*)d_in[19];
    const float* b2    = (const float*)d_in[20];
    float* out = (float*)d_out;

    void* p;
    cudaGetSymbolAddress(&p, g_xT);  float* XT  = (float*)p;

    k_pack2<<<50, 256>>>(Wq_s, Wq_v, Wk_s, Wk_v, Wp_s, Wp_v, Wv_s, Wv_v, Wm_s, Wm_v);
    k_xT<<<dim3(256, 6), dim3(32, 8)>>>(pseduo_x, XT, ei);

    k_gemmT_m<<<2816, 256>>>(XT);

    k_scan<<<1, 1024>>>();

    k_edge_qk<<<2304, 256>>>(rbf, rsh, ei, Wrbf, pseduo_x);

    k_attn_agg2<<<1024, 256>>>(pseduo_x, ei);

    k_projm<<<512, 256>>>();
    k_normgate<<<256, 256>>>(ln_g, ln_b, W1, b1, W2, b2, out);
}

// round 12
// speedup vs baseline: 1.7224x; 1.0040x over previous
#include <cuda_runtime.h>
#include <math.h>
#include <float.h>

#define NN 8192
#define NE 65536
#define VPLANE ((size_t)NN * 576)

#define INV_SQRT128 0.08838834764831843f
#define INV_SQRT512 0.04419417382415922f
#define INV_SQRT3   0.5773502691896258f
#define INV_SQRT160 0.07905694150420949f
#define INV_SQRT32  0.17677669529663687f

#define SC_S   (0.125f * INV_SQRT128 * INV_SQRT160)
#define SC_V   (INV_SQRT32 * 0.125f * INV_SQRT160)
#define SC_P_S (INV_SQRT128)
#define SC_P_V (0.125f)
#define SC_C_S (0.125f * INV_SQRT512)
#define SC_C_V (0.125f * 0.0625f)

typedef unsigned long long u64;

__device__ __forceinline__ void fma2(u64& d, u64 a, u64 b) {
    asm("fma.rn.f32x2 %0, %1, %2, %0;" : "+l"(d) : "l"(a), "l"(b));
}
__device__ __forceinline__ u64 dupf(float x) {
    u64 r; asm("mov.b64 %0, {%1, %1};" : "=l"(r) : "r"(__float_as_uint(x))); return r;
}
__device__ __forceinline__ u64 pk2(float lo, float hi) {
    u64 r; asm("mov.b64 %0, {%1, %2};" : "=l"(r) : "r"(__float_as_uint(lo)), "r"(__float_as_uint(hi)));
    return r;
}

// ---------------- scratch ------------------------------------------------------
__device__ float g_xT[160 * NN];
__device__ float g_S[NN * 1088];
__device__ float g_V[3 * NN * 576];
__device__ float g_QKself[NN * 8];
__device__ float g_feat[NE * 160];
__device__ float g_logit[NE * 8];
__device__ float g_agg[NN * 1280];
__device__ float g_m[NN * 160];
__device__ int   g_cnt[NN];
__device__ int   g_offs[NN + 1];
__device__ int   g_cursor[NN];
__device__ int   g_elist[NE];
__device__ float g_Wts[64 * 1088];
__device__ float g_Wtv[32 * 576];
__device__ float g_Wcs[512 * 64];
__device__ float g_Wcv[256 * 32];

// ---------------- merged prep: weight packing + transpose + histogram --------------
__global__ void __launch_bounds__(256) k_prep(
        const float* __restrict__ Wq_s, const float* __restrict__ Wq_v,
        const float* __restrict__ Wk_s, const float* __restrict__ Wk_v,
        const float* __restrict__ Wp_s, const float* __restrict__ Wp_v,
        const float* __restrict__ Wv_s, const float* __restrict__ Wv_v,
        const float* __restrict__ Wm_s, const float* __restrict__ Wm_v,
        const float* __restrict__ x, float* __restrict__ xT,
        const int* __restrict__ ei) {
    __shared__ __align__(16) float sm[8192];
    int b = blockIdx.x, tid = threadIdx.x;
    if (b < 16) {
        int h = b & 7, self = b >> 3;
        float* Q = sm; float* Kx = sm + 4096;
        for (int i = tid; i < 4096; i += 256) {
            int a = i >> 6, j = i & 63;
            Q[i]  = Wq_s[a * 512 + h * 64 + j];
            int kr = self ? a : (64 + a);
            Kx[i] = Wk_s[kr * 512 + h * 64 + j];
        }
        __syncthreads();
        for (int i = tid; i < 4096; i += 256) {
            int a = i & 63, bb = i >> 6;
            float s = 0.f;
            for (int j = 0; j < 64; j++) s += Q[a * 64 + j] * Kx[bb * 64 + j];
            g_Wts[bb * 1088 + self * 512 + h * 64 + a] = s * SC_S;
        }
    } else if (b < 32) {
        int h = (b - 16) & 7, self = (b - 16) >> 3;
        float* Q = sm; float* Kx = sm + 1024;
        for (int i = tid; i < 1024; i += 256) {
            int a = i >> 5, j = i & 31;
            Q[i]  = Wq_v[a * 256 + h * 32 + j];
            int kr = self ? a : (32 + a);
            Kx[i] = Wk_v[kr * 256 + h * 32 + j];
        }
        __syncthreads();
        for (int i = tid; i < 1024; i += 256) {
            int a = i & 31, bb = i >> 5;
            float s = 0.f;
            for (int j = 0; j < 32; j++) s += Q[a * 32 + j] * Kx[bb * 32 + j];
            g_Wtv[bb * 576 + self * 256 + h * 32 + a] = s * SC_V;
        }
    } else if (b < 40) {
        int h = b - 32;
        float* V = sm; float* M = sm + 4096;
        for (int i = tid; i < 4096; i += 256) {
            int k = i >> 6, j = i & 63;
            V[i] = Wv_s[k * 512 + h * 64 + j];
            M[i] = Wm_s[(h * 64 + k) * 64 + j];
        }
        __syncthreads();
        for (int i = tid; i < 4096; i += 256) {
            int d = i & 63, k = i >> 6;
            float s = 0.f;
            for (int j = 0; j < 64; j++) s += V[k * 64 + j] * M[j * 64 + d];
            g_Wcs[(h * 64 + k) * 64 + d] = s * SC_C_S;
        }
    } else if (b < 48) {
        int h = b - 40;
        float* V = sm; float* M = sm + 1024;
        for (int i = tid; i < 1024; i += 256) {
            int k = i >> 5, j = i & 31;
            V[i] = Wv_v[k * 256 + h * 32 + j] + Wv_v[(32 + k) * 256 + h * 32 + j];
            M[i] = Wm_v[(h * 32 + k) * 32 + j];
        }
        __syncthreads();
        for (int i = tid; i < 1024; i += 256) {
            int d = i & 31, k = i >> 5;
            float s = 0.f;
            for (int j = 0; j < 32; j++) s += V[k * 32 + j] * M[j * 32 + d];
            g_Wcv[(h * 32 + k) * 32 + d] = s * SC_C_V;
        }
    } else if (b == 48) {
        for (int i = tid; i < 4096; i += 256) {
            int bb = i >> 6, c = i & 63;
            float w = (c < 32) ? Wp_s[bb * 32 + c] : Wp_s[(64 + bb) * 32 + (c - 32)];
            g_Wts[bb * 1088 + 1024 + c] = w * SC_P_S;
        }
        for (int i = tid; i < 2048; i += 256) {
            int bb = i >> 6, c = i & 63;
            float w = (c < 32) ? Wp_v[bb * 32 + c] : Wp_v[(32 + bb) * 32 + (c - 32)];
            g_Wtv[bb * 576 + 512 + c] = w * SC_P_V;
        }
    } else if (b < 1329) {                 // transpose: 1280 blocks (256 x 5)
        float (*t)[33] = (float(*)[33])sm;
        int tx = tid & 31, ty = tid >> 5;
        int bi = b - 49;
        int n0 = (bi % 256) * 32, t0 = (bi / 256) * 32;
#pragma unroll
        for (int i = 0; i < 32; i += 8)
            t[ty + i][tx] = x[(size_t)(n0 + ty + i) * 160 + t0 + tx];
        __syncthreads();
#pragma unroll
        for (int i = 0; i < 32; i += 8)
            xT[(size_t)(t0 + ty + i) * 8192 + n0 + tx] = t[tx][ty + i];
    } else {                               // histogram: 256 blocks
        int e = (b - 1329) * 256 + tid;
        atomicAdd(&g_cnt[ei[NE + e]], 1);
    }
}

// ---------------- node-projection GEMM + embedded CSR scan --------------------------
template<int K>
__device__ __forceinline__ void gemmT_body(
        const float* __restrict__ AT, int baseRow, int rowStride,
        const float* __restrict__ W, int N,
        float* __restrict__ C, int cRow, size_t planeStride,
        int bx, int by, int z, float* As, float* Ws, int tid) {
    int n0 = bx * 64, m0 = by * 128;
#pragma unroll
    for (int r = 0; r < (K * 128) / 1024; r++) {
        int idx = tid + r * 256;
        int k = idx >> 5, mp = idx & 31;
        *(float4*)&As[k * 128 + mp * 4] =
            *(const float4*)&AT[(size_t)(baseRow + z + k * rowStride) * 8192 + m0 + mp * 4];
    }
#pragma unroll
    for (int r = 0; r < (K * 64) / 1024; r++) {
        int idx = tid + r * 256;
        int k = idx >> 4, j = idx & 15;
        *(float4*)&Ws[k * 64 + j * 4] = *(const float4*)&W[(size_t)k * N + n0 + j * 4];
    }
    __syncthreads();
    int ty = tid >> 4, tx = tid & 15;
    u64 acc[4][4] = {};
#pragma unroll 8
    for (int k = 0; k < K; k++) {
        ulonglong2 a01 = *(const ulonglong2*)&As[k * 128 + ty * 8];
        ulonglong2 a23 = *(const ulonglong2*)&As[k * 128 + ty * 8 + 4];
        float4 b4 = *(const float4*)&Ws[k * 64 + tx * 4];
        u64 bb0 = dupf(b4.x), bb1 = dupf(b4.y), bb2 = dupf(b4.z), bb3 = dupf(b4.w);
        u64 ap[4] = {a01.x, a01.y, a23.x, a23.y};
#pragma unroll
        for (int q = 0; q < 4; q++) {
            fma2(acc[q][0], ap[q], bb0);
            fma2(acc[q][1], ap[q], bb1);
            fma2(acc[q][2], ap[q], bb2);
            fma2(acc[q][3], ap[q], bb3);
        }
    }
    float* Cb = C + (size_t)z * planeStride;
#pragma unroll
    for (int q = 0; q < 4; q++) {
        float2 c0 = *(float2*)&acc[q][0];
        float2 c1 = *(float2*)&acc[q][1];
        float2 c2 = *(float2*)&acc[q][2];
        float2 c3 = *(float2*)&acc[q][3];
        int r0 = m0 + ty * 8 + 2 * q;
        *(float4*)&Cb[(size_t)r0 * cRow + n0 + tx * 4]       = make_float4(c0.x, c1.x, c2.x, c3.x);
        *(float4*)&Cb[(size_t)(r0 + 1) * cRow + n0 + tx * 4] = make_float4(c0.y, c1.y, c2.y, c3.y);
    }
}

__global__ void __launch_bounds__(256) k_gemmT_m(const float* __restrict__ AT) {
    __shared__ __align__(16) float As[64 * 128];
    __shared__ __align__(16) float Ws[64 * 64];
    int b = blockIdx.x, tid = threadIdx.x;
    if (b < 1088) {
        gemmT_body<64>(AT, 0, 1, g_Wts, 1088, g_S, 1088, 0,
                       b % 17, b / 17, 0, As, Ws, tid);
    } else if (b < 2816) {
        int i = b - 1088;
        int z = i / 576, r = i % 576;
        gemmT_body<32>(AT, 64, 3, g_Wtv, 576, g_V, 576, VPLANE,
                       r % 9, r / 9, z, As, Ws, tid);
    } else {
        // CSR exclusive scan over g_cnt (256 threads, counts staged in smem)
        int* s = (int*)As;
        int* wsum = (int*)Ws;
        for (int i = tid; i < NN; i += 256) s[i] = g_cnt[i];
        __syncthreads();
        int base = tid * 32;
        int tot = 0;
        for (int i = 0; i < 32; i++) tot += s[base + i];
        int lane = tid & 31, w = tid >> 5;
        int incl = tot;
#pragma unroll
        for (int o = 1; o < 32; o <<= 1) {
            int y = __shfl_up_sync(0xffffffffu, incl, o);
            if (lane >= o) incl += y;
        }
        if (lane == 31) wsum[w] = incl;
        __syncthreads();
        if (tid == 0) {
            int r = 0;
#pragma unroll
            for (int j = 0; j < 8; j++) { int t = wsum[j]; wsum[j] = r; r += t; }
        }
        __syncthreads();
        int run = wsum[w] + (incl - tot);
        for (int i = 0; i < 32; i++) {
            g_offs[base + i] = run;
            g_cursor[base + i] = run;
            run += s[base + i];
        }
        if (tid == 255) g_offs[NN] = NE;
    }
}

// ---------------- merged final projections, f32x2 (column-paired) -------------------
__global__ void __launch_bounds__(256) k_projm() {
    __shared__ __align__(16) float As[32 * 68];
    __shared__ __align__(16) float Ws[32 * 68];
    int tid = threadIdx.x;
    int b = blockIdx.x;
    const float* A; const float* W; float* C;
    int aRow, K, NC, cRow, cCol, m0;
    if (b < 128) {
        A = g_agg; aRow = 1280; K = 512; NC = 64;
        W = g_Wcs; C = g_m; cRow = 160; cCol = 1;
        m0 = b * 64;
    } else {
        int c = (b - 128) / 128, mt = (b - 128) % 128;
        A = g_agg + 512 + c * 256; aRow = 1280; K = 256; NC = 32;
        W = g_Wcv; C = g_m + 64 + c; cRow = 160; cCol = 3;
        m0 = mt * 64;
    }
    u64 acc[4][2] = {};
    int ty = tid >> 4, tx = tid & 15;

    for (int k0 = 0; k0 < K; k0 += 32) {
#pragma unroll
        for (int r = 0; r < 8; r++) {
            int l = tid + r * 256;
            int kk = l & 31, mm = l >> 5;
            As[kk * 68 + mm] = A[(size_t)(m0 + mm) * aRow + (k0 + kk)];
        }
#pragma unroll
        for (int r = 0; r < 8; r++) {
            int l = tid + r * 256;
            int kk = l >> 6, jj = l & 63;
            Ws[kk * 68 + jj] = (jj < NC) ? W[(size_t)(k0 + kk) * NC + jj] : 0.f;
        }
        __syncthreads();
#pragma unroll 8
        for (int k = 0; k < 32; k++) {
            float4 a4 = *(const float4*)&As[k * 68 + ty * 4];
            ulonglong2 bp = *(const ulonglong2*)&Ws[k * 68 + tx * 4];
            u64 aa0 = dupf(a4.x), aa1 = dupf(a4.y), aa2 = dupf(a4.z), aa3 = dupf(a4.w);
            fma2(acc[0][0], aa0, bp.x); fma2(acc[0][1], aa0, bp.y);
            fma2(acc[1][0], aa1, bp.x); fma2(acc[1][1], aa1, bp.y);
            fma2(acc[2][0], aa2, bp.x); fma2(acc[2][1], aa2, bp.y);
            fma2(acc[3][0], aa3, bp.x); fma2(acc[3][1], aa3, bp.y);
        }
        __syncthreads();
    }
#pragma unroll
    for (int i = 0; i < 4; i++) {
        int m = m0 + ty * 4 + i;
        float2 c01 = *(float2*)&acc[i][0];
        float2 c23 = *(float2*)&acc[i][1];
        int col = tx * 4;
        if (cCol == 1) {
            *(float4*)&C[(size_t)m * cRow + col] = make_float4(c01.x, c01.y, c23.x, c23.y);
        } else {
            if (col < NC) {
                C[(size_t)m * cRow + (col + 0) * 3] = c01.x;
                C[(size_t)m * cRow + (col + 1) * 3] = c01.y;
                C[(size_t)m * cRow + (col + 2) * 3] = c23.x;
                C[(size_t)m * cRow + (col + 3) * 3] = c23.y;
            }
        }
    }
}

// ---------------- edgeprep + qkself + scatter merged ---------------------------------
__global__ void __launch_bounds__(256) k_edge_qk(const float* __restrict__ rbf,
                                                 const float* __restrict__ rsh,
                                                 const int* __restrict__ ei,
                                                 const float* __restrict__ Wrbf,
                                                 const float* __restrict__ x) {
    int b = blockIdx.x, tid = threadIdx.x;
    if (b < 1024) {
        __shared__ float sW[1024];
        for (int l = tid; l < 1024; l += 256) sW[l] = Wrbf[l];
        __syncthreads();
        int wid = tid >> 5, lane = tid & 31;
        int d = lane;
#pragma unroll
        for (int it = 0; it < 8; it++) {
            int e = b * 64 + it * 8 + wid;
            int src = ei[e], dst = ei[NE + e];
            float ps = g_S[(size_t)src * 1088 + 1024 + d] + g_S[(size_t)dst * 1088 + 1056 + d];
            float pv[3];
#pragma unroll
            for (int c = 0; c < 3; c++)
                pv[c] = g_V[c * VPLANE + (size_t)src * 576 + 512 + d]
                      + g_V[c * VPLANE + (size_t)dst * 576 + 544 + d];
            float rval = (lane < 16) ? rbf[e * 16 + lane] : 0.f;
            float scal_s = 0.f, scal_v = 0.f;
#pragma unroll
            for (int bq = 0; bq < 16; bq++) {
                float rb = __shfl_sync(0xffffffffu, rval, bq);
                scal_s += rb * sW[bq * 64 + d];
                scal_v += rb * sW[bq * 64 + 32 + d];
            }
            float rs = rsh[e * 128 + d];
            float sph_s = rs * scal_s * ps;
            float sv[3];
#pragma unroll
            for (int c = 0; c < 3; c++)
                sv[c] = rsh[e * 128 + 32 + d * 3 + c] * scal_v * pv[c];
            float* f = g_feat + (size_t)e * 160;
            f[d]      = sph_s * sph_s;
            f[32 + d] = (sv[0] * sv[0] + sv[1] * sv[1] + sv[2] * sv[2]) * INV_SQRT3;
#pragma unroll
            for (int c = 0; c < 3; c++)
                f[64 + c * 32 + d] = sph_s * sv[c];
        }
    } else if (b < 2048) {
        __shared__ float s_q[8][160];
        int wid = tid >> 5, lane = tid & 31;
        int n = (b - 1024) * 8 + wid;
        const float4* xs = (const float4*)(x + (size_t)n * 160);
        ((float4*)s_q[wid])[lane] = xs[lane];
        if (lane < 8) ((float4*)s_q[wid])[32 + lane] = xs[32 + lane];
        __syncwarp();
        const float* xr = s_q[wid];
        const float* Sb = g_S + (size_t)n * 1088 + 512;
#pragma unroll
        for (int h = 0; h < 8; h++) {
            float a = Sb[h * 64 + lane] * xr[lane]
                    + Sb[h * 64 + 32 + lane] * xr[32 + lane];
#pragma unroll
            for (int c = 0; c < 3; c++)
                a += g_V[c * VPLANE + (size_t)n * 576 + 256 + h * 32 + lane]
                     * xr[64 + lane * 3 + c];
#pragma unroll
            for (int o = 16; o; o >>= 1) a += __shfl_xor_sync(0xffffffffu, a, o);
            if (lane == 0) g_QKself[n * 8 + h] = a;
        }
    } else {
        int e = (b - 2048) * 256 + tid;
        int pos = atomicAdd(&g_cursor[ei[NE + e]], 1);
        g_elist[pos] = e;
    }
}

// ---------------- fused attention + aggregation: warp/node, dbl-buffer + prefetch -----
__global__ void __launch_bounds__(256) k_attn_agg2(const float* __restrict__ x,
                                                   const int* __restrict__ ei) {
    __shared__ __align__(16) float s_x[8][2][160];
    __shared__ float s_lg[8][512];
    const unsigned F = 0xffffffffu;
    int tid = threadIdx.x;
    int wid = tid >> 5, lane = tid & 31;
    int n = blockIdx.x * 8 + wid;
    int h = lane >> 2, p = lane & 3;

    int s0 = g_offs[n], deg = g_offs[n + 1] - s0;
    float* lg = (deg <= 64) ? &s_lg[wid][0] : (g_logit + (size_t)s0 * 8);

    int e0 = 0, e1 = 0, src0 = 0, src1 = 0;
    if (lane < deg) e0 = g_elist[s0 + lane];
    if (lane + 32 < deg) e1 = g_elist[s0 + 32 + lane];
    if (lane < deg) src0 = ei[e0];
    if (lane + 32 < deg) src1 = ei[e1];

    float mymax = -FLT_MAX;
    {
        float tkf[40];
#pragma unroll
        for (int tt = 0; tt < 40; tt++) {
            int t = p * 40 + tt;
            if (t < 64)
                tkf[tt] = g_S[(size_t)n * 1088 + h * 64 + t];
            else {
                int j = t - 64;
                tkf[tt] = g_V[(j % 3) * VPLANE + (size_t)n * 576 + h * 32 + (j / 3)];
            }
        }
        u64 tk2[20];
#pragma unroll
        for (int i = 0; i < 20; i++) tk2[i] = pk2(tkf[2 * i], tkf[2 * i + 1]);

        if (deg > 0) {
            int src = __shfl_sync(F, src0, 0);
            const float4* xs = (const float4*)(x + (size_t)src * 160);
            ((float4*)s_x[wid][0])[lane] = xs[lane];
            if (lane < 8) ((float4*)s_x[wid][0])[32 + lane] = xs[32 + lane];
        }
        __syncwarp();

        for (int i = 0; i < deg; i++) {
            int src;
            if (i < 64) src = __shfl_sync(F, (i < 32) ? src0 : src1, i & 31);
            else {
                int ss = 0;
                if (lane == 0) ss = ei[g_elist[s0 + i]];
                src = __shfl_sync(F, ss, 0);
            }
            float4 nf0, nf1;
            int havenext = (i + 1 < deg);
            if (havenext) {
                int nsrc;
                int j = i + 1;
                if (j < 64) nsrc = __shfl_sync(F, (j < 32) ? src0 : src1, j & 31);
                else {
                    int ss = 0;
                    if (lane == 0) ss = ei[g_elist[s0 + j]];
                    nsrc = __shfl_sync(F, ss, 0);
                }
                const float4* nxs = (const float4*)(x + (size_t)nsrc * 160);
                nf0 = nxs[lane];
                if (lane < 8) nf1 = nxs[32 + lane];
            }
            const u64* xr2 = (const u64*)(s_x[wid][i & 1] + p * 40);
            u64 ac0 = 0, ac1 = 0, ac2 = 0, ac3 = 0;
#pragma unroll
            for (int q = 0; q < 20; q += 4) {
                fma2(ac0, tk2[q + 0], xr2[q + 0]);
                fma2(ac1, tk2[q + 1], xr2[q + 1]);
                fma2(ac2, tk2[q + 2], xr2[q + 2]);
                fma2(ac3, tk2[q + 3], xr2[q + 3]);
            }
            float2 v0 = *(float2*)&ac0, v1 = *(float2*)&ac1;
            float2 v2 = *(float2*)&ac2, v3 = *(float2*)&ac3;
            float a = ((v0.x + v0.y) + (v1.x + v1.y)) + ((v2.x + v2.y) + (v3.x + v3.y));
            a += __shfl_xor_sync(F, a, 1);
            a += __shfl_xor_sync(F, a, 2);
            if (p == 0) {
                a += g_QKself[src * 8 + h];
                lg[i * 8 + h] = a;
                mymax = fmaxf(mymax, a);
            }
            if (havenext) {
                ((float4*)s_x[wid][(i + 1) & 1])[lane] = nf0;
                if (lane < 8) ((float4*)s_x[wid][(i + 1) & 1])[32 + lane] = nf1;
            }
            __syncwarp();
        }
    }

    if (p == 0 && deg > 0) {
        float den = 0.f;
        for (int i = 0; i < deg; i++) {
            float ex = expf(lg[i * 8 + h] - mymax);
            lg[i * 8 + h] = ex;
            den += ex;
        }
        float inv = 1.f / den;
        for (int i = 0; i < deg; i++) lg[i * 8 + h] *= inv;
    }
    __syncwarp();

    u64 accS[8] = {}, accV[8] = {};
    float accW[8] = {};

    float f0, f1, fv0, fv1, fv2;
    if (deg > 0) {
        int e = __shfl_sync(F, e0, 0);
        const float* fr = g_feat + (size_t)e * 160;
        f0 = fr[lane]; f1 = fr[32 + lane];
        fv0 = fr[64 + lane]; fv1 = fr[96 + lane]; fv2 = fr[128 + lane];
    }
    for (int i = 0; i < deg; i++) {
        float nf0v, nf1v, nv0, nv1, nv2;
        int havenext = (i + 1 < deg);
        if (havenext) {
            int j = i + 1, e;
            if (j < 64) e = __shfl_sync(F, (j < 32) ? e0 : e1, j & 31);
            else {
                int ee = 0;
                if (lane == 0) ee = g_elist[s0 + j];
                e = __shfl_sync(F, ee, 0);
            }
            const float* fr = g_feat + (size_t)e * 160;
            nf0v = fr[lane]; nf1v = fr[32 + lane];
            nv0 = fr[64 + lane]; nv1 = fr[96 + lane]; nv2 = fr[128 + lane];
        }
        u64 fS = pk2(f0, f1);
        u64 fV = pk2(fv0, fv1);
        const float* ar = lg + i * 8;
#pragma unroll
        for (int hh = 0; hh < 8; hh++) {
            float at = ar[hh];
            u64 at2 = dupf(at);
            fma2(accS[hh], fS, at2);
            fma2(accV[hh], fV, at2);
            accW[hh] += at * fv2;
        }
        if (havenext) { f0 = nf0v; f1 = nf1v; fv0 = nv0; fv1 = nv1; fv2 = nv2; }
    }
    float* ao = g_agg + (size_t)n * 1280;
#pragma unroll
    for (int hh = 0; hh < 8; hh++) {
        float2 s = *(float2*)&accS[hh];
        ao[(2 * hh) * 32 + lane]      = s.x;
        ao[(2 * hh + 1) * 32 + lane]  = s.y;
        float2 v = *(float2*)&accV[hh];
        ao[(16 + hh) * 32 + lane]     = v.x;
        ao[(24 + hh) * 32 + lane]     = v.y;
        ao[(32 + hh) * 32 + lane]     = accW[hh];
    }
}

// ---------------- NormGate + output --------------------------------------------------
__global__ void __launch_bounds__(256) k_normgate(const float* __restrict__ ln_g,
                                                  const float* __restrict__ ln_b,
                                                  const float* __restrict__ W1,
                                                  const float* __restrict__ b1,
                                                  const float* __restrict__ W2,
                                                  const float* __restrict__ b2,
                                                  float* __restrict__ out) {
    __shared__ float sW1[96 * 96];
    __shared__ float sX[8][96];
    __shared__ float sH[8][96];
    int tid = threadIdx.x;
    int w = tid >> 5, lane = tid & 31;
    for (int i = tid; i < 9216; i += 256) sW1[i] = W1[i];
    __syncthreads();

    for (int sub = 0; sub < 4; sub++) {
        int n = blockIdx.x * 32 + w * 4 + sub;
        const float* mrow = g_m + (size_t)n * 160;
        float ms0 = mrow[lane], ms1 = mrow[32 + lane];
        float v0 = mrow[64 + lane * 3 + 0];
        float v1 = mrow[64 + lane * 3 + 1];
        float v2 = mrow[64 + lane * 3 + 2];
        float n00 = fabsf(ms0), n01 = fabsf(ms1);
        float n02 = sqrtf(v0 * v0 + v1 * v1 + v2 * v2);
        float s = n00 + n01 + n02;
        float s2 = n00 * n00 + n01 * n01 + n02 * n02;
#pragma unroll
        for (int o = 16; o; o >>= 1) {
            s  += __shfl_xor_sync(0xffffffffu, s, o);
            s2 += __shfl_xor_sync(0xffffffffu, s2, o);
        }
        float mu = s * (1.f / 96.f);
        float var = s2 * (1.f / 96.f) - mu * mu;
        float rstd = rsqrtf(var + 1e-5f);
        sX[w][lane]      = (n00 - mu) * rstd * ln_g[lane]      + ln_b[lane];
        sX[w][lane + 32] = (n01 - mu) * rstd * ln_g[lane + 32] + ln_b[lane + 32];
        sX[w][lane + 64] = (n02 - mu) * rstd * ln_g[lane + 64] + ln_b[lane + 64];
        __syncwarp();
#pragma unroll
        for (int t = 0; t < 3; t++) {
            int jp = lane + t * 32;
            float hs = b1[jp];
            for (int j = 0; j < 96; j++) hs += sX[w][j] * sW1[j * 96 + jp];
            sH[w][jp] = hs / (1.f + expf(-hs));
        }
        __syncwarp();
        float n0arr[3] = {n00, n01, n02};
        float f[3];
#pragma unroll
        for (int t = 0; t < 3; t++) {
            int jp = lane + t * 32;
            float gs = b2[jp];
            for (int j = 0; j < 96; j++) gs += sH[w][j] * W2[j * 96 + jp];
            float gg = gs / (1.f + expf(-gs));
            f[t] = gg / (n0arr[t] + 1e-6f);
        }
        out[n * 160 + lane]      = ms0 * f[0];
        out[n * 160 + 32 + lane] = ms1 * f[1];
        out[n * 160 + 64 + lane * 3 + 0] = v0 * f[2];
        out[n * 160 + 64 + lane * 3 + 1] = v1 * f[2];
        out[n * 160 + 64 + lane * 3 + 2] = v2 * f[2];
        __syncwarp();
    }
}

// ---------------- launch ----------------------------------------------------------------
extern "C" void kernel_launch(void* const* d_in, const int* in_sizes, int n_in,
                              void* d_out, int out_size) {
    const float* pseduo_x = (const float*)d_in[0];
    const float* rbf   = (const float*)d_in[1];
    const float* rsh   = (const float*)d_in[2];
    const int*   ei    = (const int*)d_in[3];
    const float* Wq_s  = (const float*)d_in[4];
    const float* Wq_v  = (const float*)d_in[5];
    const float* Wk_s  = (const float*)d_in[6];
    const float* Wk_v  = (const float*)d_in[7];
    const float* Wp_s  = (const float*)d_in[8];
    const float* Wp_v  = (const float*)d_in[9];
    const float* Wrbf  = (const float*)d_in[10];
    const float* Wv_s  = (const float*)d_in[11];
    const float* Wv_v  = (const float*)d_in[12];
    const float* Wm_s  = (const float*)d_in[13];
    const float* Wm_v  = (const float*)d_in[14];
    const float* ln_g  = (const float*)d_in[15];
    const float* ln_b  = (const float*)d_in[16];
    const float* W1    = (const float*)d_in[17];
    const float* b1    = (const float*)d_in[18];
    const float* W2    = (const float*)d_in[19];
    const float* b2    = (const float*)d_in[20];
    float* out = (float*)d_out;

    void* p;
    cudaGetSymbolAddress(&p, g_xT);  float* XT  = (float*)p;
    cudaGetSymbolAddress(&p, g_cnt); int*   CNT = (int*)p;

    cudaMemsetAsync(CNT, 0, NN * sizeof(int));
    k_prep<<<1585, 256>>>(Wq_s, Wq_v, Wk_s, Wk_v, Wp_s, Wp_v,
                          Wv_s, Wv_v, Wm_s, Wm_v, pseduo_x, XT, ei);

    k_gemmT_m<<<2817, 256>>>(XT);     // + embedded CSR scan (block 2816)

    k_edge_qk<<<2304, 256>>>(rbf, rsh, ei, Wrbf, pseduo_x);

    k_attn_agg2<<<1024, 256>>>(pseduo_x, ei);

    k_projm<<<512, 256>>>();
    k_normgate<<<256, 256>>>(ln_g, ln_b, W1, b1, W2, b2, out);
}